// round 2
// baseline (speedup 1.0000x reference)
#include <cuda_runtime.h>
#include <math.h>

#define BB 4
#define NN 1024
#define TT 4096
#define DIM 768
#define HEADS 12
#define HD 64
#define HID 3072
#define NE 8

// ---------------- scratch (static device globals; no allocs) ----------------
__device__ float g_h[(size_t)TT * DIM];          // LN output (reused for LN1 and LN2)
__device__ float g_qkv[(size_t)TT * 3 * DIM];    // qkv
__device__ float g_attn[(size_t)TT * DIM];       // attention out (pre-proj)
__device__ float g_x1[(size_t)TT * DIM];         // x after attention residual
__device__ float g_h1[(size_t)NE * TT * HID];    // MoE hidden (gelu), per (expert,slotpos)
__device__ float g_y[(size_t)NE * TT * DIM];     // MoE expert outputs per pair
__device__ int   g_cnt[NE];
__device__ int   g_ptok[NE * TT];                // token id per (expert, pos)
__device__ int   g_smap[TT * 2];                 // token -> e*TT+pos for its 2 slots
__device__ float g_sw[TT * 2];                   // combine weights

// ---------------- zero counts (must run every launch for graph replay) ------
__global__ void zero_cnt_kernel(int* c) {
    if (threadIdx.x < NE) c[threadIdx.x] = 0;
}

// ---------------- layernorm: one block per token -----------------------------
__global__ void ln_kernel(const float* __restrict__ x, const float* __restrict__ g,
                          const float* __restrict__ b, float* __restrict__ o) {
    __shared__ float xs[DIM];
    __shared__ float red[256];
    int t = blockIdx.x, tid = threadIdx.x;
    const float* xr = x + (size_t)t * DIM;
    float s = 0.f;
    for (int i = tid; i < DIM; i += 256) { float v = xr[i]; xs[i] = v; s += v; }
    red[tid] = s; __syncthreads();
    for (int st = 128; st > 0; st >>= 1) { if (tid < st) red[tid] += red[tid + st]; __syncthreads(); }
    float mu = red[0] * (1.f / DIM);
    __syncthreads();
    s = 0.f;
    for (int i = tid; i < DIM; i += 256) { float d = xs[i] - mu; s += d * d; }
    red[tid] = s; __syncthreads();
    for (int st = 128; st > 0; st >>= 1) { if (tid < st) red[tid] += red[tid + st]; __syncthreads(); }
    float inv = rsqrtf(red[0] * (1.f / DIM) + 1e-5f);
    float* orow = o + (size_t)t * DIM;
    for (int i = tid; i < DIM; i += 256)
        orow[i] = (xs[i] - mu) * inv * g[i] + b[i];
}

// ---------------- generic C = A @ B^T (+bias)(+gelu)(+resid), grouped -------
// A: [M,K] row-major (optionally gathered rows), B: [N,K] row-major.
// blockIdx.z selects group (expert); strides move A/B/C per group.
template <bool GATHER, bool GELU>
__global__ void __launch_bounds__(256)
gemm_nt(const float* __restrict__ A, const float* __restrict__ Bw,
        const float* __restrict__ bias, const float* __restrict__ resid,
        float* __restrict__ C, int M, int N, int K,
        const int* __restrict__ rows, const int* __restrict__ cnts,
        size_t sA, size_t sB, size_t sC) {
    int z = blockIdx.z;
    A += (size_t)z * sA; Bw += (size_t)z * sB; C += (size_t)z * sC;
    if (bias) bias += (size_t)z * N;
    if (rows) rows += (size_t)z * TT;
    int Mz = cnts ? cnts[z] : M;
    if (Mz > M) Mz = M;
    int m0 = blockIdx.y * 64;
    if (m0 >= Mz) return;
    int n0 = blockIdx.x * 64;

    __shared__ float As[16][68];
    __shared__ float Bs[16][68];

    int tid = threadIdx.x;
    int lr = tid >> 2, lc = tid & 3;
    int ar = m0 + lr;
    const float* ap = nullptr;
    if (ar < Mz) {
        int gr = GATHER ? rows[ar] : ar;
        ap = A + (size_t)gr * K + lc * 4;
    }
    const float* bp = Bw + (size_t)(n0 + lr) * K + lc * 4;

    int ty = tid >> 4, tx = tid & 15;
    float acc[4][4];
#pragma unroll
    for (int i = 0; i < 4; i++)
#pragma unroll
        for (int j = 0; j < 4; j++) acc[i][j] = 0.f;

    for (int k0 = 0; k0 < K; k0 += 16) {
        float4 av = ap ? *(const float4*)(ap + k0) : make_float4(0.f, 0.f, 0.f, 0.f);
        float4 bv = *(const float4*)(bp + k0);
        As[lc * 4 + 0][lr] = av.x; As[lc * 4 + 1][lr] = av.y;
        As[lc * 4 + 2][lr] = av.z; As[lc * 4 + 3][lr] = av.w;
        Bs[lc * 4 + 0][lr] = bv.x; Bs[lc * 4 + 1][lr] = bv.y;
        Bs[lc * 4 + 2][lr] = bv.z; Bs[lc * 4 + 3][lr] = bv.w;
        __syncthreads();
#pragma unroll
        for (int kk = 0; kk < 16; kk++) {
            float4 a = *(const float4*)&As[kk][ty * 4];
            float4 b = *(const float4*)&Bs[kk][tx * 4];
            acc[0][0] += a.x * b.x; acc[0][1] += a.x * b.y; acc[0][2] += a.x * b.z; acc[0][3] += a.x * b.w;
            acc[1][0] += a.y * b.x; acc[1][1] += a.y * b.y; acc[1][2] += a.y * b.z; acc[1][3] += a.y * b.w;
            acc[2][0] += a.z * b.x; acc[2][1] += a.z * b.y; acc[2][2] += a.z * b.z; acc[2][3] += a.z * b.w;
            acc[3][0] += a.w * b.x; acc[3][1] += a.w * b.y; acc[3][2] += a.w * b.z; acc[3][3] += a.w * b.w;
        }
        __syncthreads();
    }

#pragma unroll
    for (int i = 0; i < 4; i++) {
        int rr = m0 + ty * 4 + i;
        if (rr >= Mz) continue;
#pragma unroll
        for (int j = 0; j < 4; j++) {
            int col = n0 + tx * 4 + j;
            float v = acc[i][j];
            if (bias) v += bias[col];
            if (GELU) v = 0.5f * v * (1.f + erff(v * 0.70710678118654752f));
            if (resid) v += resid[(size_t)rr * N + col];
            C[(size_t)rr * N + col] = v;
        }
    }
}

// ---------------- attention: 64-query tiles, online softmax ------------------
// grid (N/64, B*H), 256 threads, dynamic smem 4*64*68*4 = 69632 B
__global__ void __launch_bounds__(256)
attn_kernel(const float* __restrict__ qkv, float* __restrict__ out) {
    extern __shared__ float sm[];
    float* Qt = sm;                 // [64 d][68]  (d-major, transposed)
    float* Kt = Qt + 64 * 68;       // [64 d][68]
    float* Vs = Kt + 64 * 68;       // [64 k][68]  (k-major)
    float* Ps = Vs + 64 * 68;       // [64 k][68]  (k-major: Ps[k][q])

    int bh = blockIdx.y;
    int b = bh / HEADS, h = bh % HEADS;
    int q0 = blockIdx.x * 64;
    int tid = threadIdx.x;
    int lr = tid >> 2, lc = tid & 3;
    int ty = tid >> 4, tx = tid & 15;
    const float scale = 0.125f;  // 64^-0.5

    // load Q tile transposed: Qt[d][q]
    {
        const float* qp = qkv + (size_t)(b * NN + q0 + lr) * (3 * DIM) + h * HD;
#pragma unroll
        for (int r = 0; r < 4; r++) {
            int d0 = lc * 4 + r * 16;
            float4 v = *(const float4*)(qp + d0);
            Qt[(d0 + 0) * 68 + lr] = v.x; Qt[(d0 + 1) * 68 + lr] = v.y;
            Qt[(d0 + 2) * 68 + lr] = v.z; Qt[(d0 + 3) * 68 + lr] = v.w;
        }
    }

    float o[4][4], mrow[4], lrow[4];
#pragma unroll
    for (int i = 0; i < 4; i++) {
        mrow[i] = -1e30f; lrow[i] = 0.f;
#pragma unroll
        for (int j = 0; j < 4; j++) o[i][j] = 0.f;
    }

    for (int kt = 0; kt < NN / 64; kt++) {
        __syncthreads();  // protect Kt/Vs/Ps from previous iteration reads
        int krow = kt * 64 + lr;
        const float* kp = qkv + (size_t)(b * NN + krow) * (3 * DIM) + DIM + h * HD;
        const float* vp = kp + DIM;
#pragma unroll
        for (int r = 0; r < 4; r++) {
            int d0 = lc * 4 + r * 16;
            float4 kv = *(const float4*)(kp + d0);
            Kt[(d0 + 0) * 68 + lr] = kv.x; Kt[(d0 + 1) * 68 + lr] = kv.y;
            Kt[(d0 + 2) * 68 + lr] = kv.z; Kt[(d0 + 3) * 68 + lr] = kv.w;
            float4 vv = *(const float4*)(vp + d0);
            *(float4*)&Vs[lr * 68 + d0] = vv;
        }
        __syncthreads();

        // S = scale * Q @ K^T  (rows = q (ty), cols = k (tx))
        float s[4][4];
#pragma unroll
        for (int i = 0; i < 4; i++)
#pragma unroll
            for (int j = 0; j < 4; j++) s[i][j] = 0.f;
#pragma unroll 8
        for (int d = 0; d < 64; d++) {
            float4 a = *(const float4*)&Qt[d * 68 + ty * 4];
            float4 bb = *(const float4*)&Kt[d * 68 + tx * 4];
            s[0][0] += a.x * bb.x; s[0][1] += a.x * bb.y; s[0][2] += a.x * bb.z; s[0][3] += a.x * bb.w;
            s[1][0] += a.y * bb.x; s[1][1] += a.y * bb.y; s[1][2] += a.y * bb.z; s[1][3] += a.y * bb.w;
            s[2][0] += a.z * bb.x; s[2][1] += a.z * bb.y; s[2][2] += a.z * bb.z; s[2][3] += a.z * bb.w;
            s[3][0] += a.w * bb.x; s[3][1] += a.w * bb.y; s[3][2] += a.w * bb.z; s[3][3] += a.w * bb.w;
        }

        // online softmax stats per q row (replicated across 16-lane tx group)
#pragma unroll
        for (int i = 0; i < 4; i++) {
            float rm = s[i][0] * scale;
            rm = fmaxf(rm, s[i][1] * scale);
            rm = fmaxf(rm, s[i][2] * scale);
            rm = fmaxf(rm, s[i][3] * scale);
#pragma unroll
            for (int off = 1; off < 16; off <<= 1)
                rm = fmaxf(rm, __shfl_xor_sync(0xffffffffu, rm, off));
            float mn = fmaxf(mrow[i], rm);
            float corr = __expf(mrow[i] - mn);
            mrow[i] = mn;
            float rs = 0.f;
#pragma unroll
            for (int j = 0; j < 4; j++) {
                float p = __expf(s[i][j] * scale - mn);
                s[i][j] = p;
                rs += p;
            }
#pragma unroll
            for (int off = 1; off < 16; off <<= 1)
                rs += __shfl_xor_sync(0xffffffffu, rs, off);
            lrow[i] = lrow[i] * corr + rs;
#pragma unroll
            for (int j = 0; j < 4; j++) o[i][j] *= corr;
        }

        // write P transposed: Ps[k][q]
#pragma unroll
        for (int i = 0; i < 4; i++)
#pragma unroll
            for (int j = 0; j < 4; j++)
                Ps[(tx * 4 + j) * 68 + ty * 4 + i] = s[i][j];
        __syncthreads();

        // O += P @ V  (rows = q (ty), cols = d (tx))
#pragma unroll 8
        for (int kk = 0; kk < 64; kk++) {
            float4 p = *(const float4*)&Ps[kk * 68 + ty * 4];
            float4 v = *(const float4*)&Vs[kk * 68 + tx * 4];
            o[0][0] += p.x * v.x; o[0][1] += p.x * v.y; o[0][2] += p.x * v.z; o[0][3] += p.x * v.w;
            o[1][0] += p.y * v.x; o[1][1] += p.y * v.y; o[1][2] += p.y * v.z; o[1][3] += p.y * v.w;
            o[2][0] += p.z * v.x; o[2][1] += p.z * v.y; o[2][2] += p.z * v.z; o[2][3] += p.z * v.w;
            o[3][0] += p.w * v.x; o[3][1] += p.w * v.y; o[3][2] += p.w * v.z; o[3][3] += p.w * v.w;
        }
    }

#pragma unroll
    for (int i = 0; i < 4; i++) {
        float inv = 1.f / lrow[i];
        int q = q0 + ty * 4 + i;
        float* orow = out + (size_t)(b * NN + q) * DIM + h * HD + tx * 4;
#pragma unroll
        for (int j = 0; j < 4; j++) orow[j] = o[i][j] * inv;
    }
}

// ---------------- gate: logits, top2, softmax, bucket by expert --------------
__global__ void gate_kernel(const float* __restrict__ h2, const float* __restrict__ gw,
                            const float* __restrict__ gb, int* __restrict__ cnt,
                            int* __restrict__ ptok, int* __restrict__ smap,
                            float* __restrict__ sw) {
    __shared__ float lg[NE];
    int t = blockIdx.x, tid = threadIdx.x;
    int w = tid >> 5, lane = tid & 31;
    const float* hr = h2 + (size_t)t * DIM;
    float s = 0.f;
    const float* gr = gw + (size_t)w * DIM;
    for (int k = lane; k < DIM; k += 32) s += hr[k] * gr[k];
#pragma unroll
    for (int off = 16; off > 0; off >>= 1) s += __shfl_down_sync(0xffffffffu, s, off);
    if (lane == 0) lg[w] = s + gb[w];
    __syncthreads();
    if (tid == 0) {
        int b0 = 0; float v0 = lg[0];
        for (int e = 1; e < NE; e++) if (lg[e] > v0) { v0 = lg[e]; b0 = e; }
        int b1 = -1; float v1 = -1e30f;
        for (int e = 0; e < NE; e++) {
            if (e == b0) continue;
            if (lg[e] > v1) { v1 = lg[e]; b1 = e; }
        }
        float e1 = __expf(v1 - v0);
        float s0 = 1.f / (1.f + e1);
        float s1 = 1.f - s0;
        int p0 = atomicAdd(&cnt[b0], 1);
        int p1 = atomicAdd(&cnt[b1], 1);
        ptok[b0 * TT + p0] = t;
        ptok[b1 * TT + p1] = t;
        smap[t * 2 + 0] = b0 * TT + p0; sw[t * 2 + 0] = s0;
        smap[t * 2 + 1] = b1 * TT + p1; sw[t * 2 + 1] = s1;
    }
}

// ---------------- combine: out = x1 + w0*y[slot0] + w1*y[slot1] --------------
__global__ void combine_kernel(const float* __restrict__ x1, const float* __restrict__ y,
                               const int* __restrict__ smap, const float* __restrict__ sw,
                               float* __restrict__ out) {
    int t = blockIdx.x, tid = threadIdx.x;
    int s0 = smap[t * 2 + 0], s1 = smap[t * 2 + 1];
    float w0 = sw[t * 2 + 0], w1 = sw[t * 2 + 1];
    const float* y0 = y + (size_t)s0 * DIM;
    const float* y1 = y + (size_t)s1 * DIM;
    const float* xr = x1 + (size_t)t * DIM;
    float* orow = out + (size_t)t * DIM;
    for (int c = tid; c < DIM; c += 256)
        orow[c] = xr[c] + w0 * y0[c] + w1 * y1[c];
}

// ---------------- host launcher ---------------------------------------------
extern "C" void kernel_launch(void* const* d_in, const int* in_sizes, int n_in,
                              void* d_out, int out_size) {
    const float* x      = (const float*)d_in[0];
    const float* ln1_g  = (const float*)d_in[1];
    const float* ln1_b  = (const float*)d_in[2];
    const float* qkv_w  = (const float*)d_in[3];
    const float* proj_w = (const float*)d_in[4];
    const float* proj_b = (const float*)d_in[5];
    const float* ln2_g  = (const float*)d_in[6];
    const float* ln2_b  = (const float*)d_in[7];
    const float* gate_w = (const float*)d_in[8];
    const float* gate_b = (const float*)d_in[9];
    const float* w1     = (const float*)d_in[10];
    const float* b1     = (const float*)d_in[11];
    const float* w2     = (const float*)d_in[12];
    const float* b2     = (const float*)d_in[13];
    float* out = (float*)d_out;

    float *h, *qkvb, *attn, *x1, *h1, *y, *sw;
    int *cnt, *ptok, *smap;
    cudaGetSymbolAddress((void**)&h, g_h);
    cudaGetSymbolAddress((void**)&qkvb, g_qkv);
    cudaGetSymbolAddress((void**)&attn, g_attn);
    cudaGetSymbolAddress((void**)&x1, g_x1);
    cudaGetSymbolAddress((void**)&h1, g_h1);
    cudaGetSymbolAddress((void**)&y, g_y);
    cudaGetSymbolAddress((void**)&cnt, g_cnt);
    cudaGetSymbolAddress((void**)&ptok, g_ptok);
    cudaGetSymbolAddress((void**)&smap, g_smap);
    cudaGetSymbolAddress((void**)&sw, g_sw);

    const int ATTN_SMEM = 4 * 64 * 68 * 4;  // 69632
    cudaFuncSetAttribute(attn_kernel, cudaFuncAttributeMaxDynamicSharedMemorySize, ATTN_SMEM);

    // 0. zero expert counters (every launch — graph replays)
    zero_cnt_kernel<<<1, 32>>>(cnt);

    // 1. LN1
    ln_kernel<<<TT, 256>>>(x, ln1_g, ln1_b, h);

    // 2. qkv = h @ qkv_w^T   [4096, 2304]
    gemm_nt<false, false><<<dim3(36, 64, 1), 256>>>(
        h, qkv_w, nullptr, nullptr, qkvb, TT, 3 * DIM, DIM, nullptr, nullptr, 0, 0, 0);

    // 3. attention
    attn_kernel<<<dim3(NN / 64, BB * HEADS), 256, ATTN_SMEM>>>(qkvb, attn);

    // 4. x1 = x + attn @ proj_w^T + proj_b
    gemm_nt<false, false><<<dim3(12, 64, 1), 256>>>(
        attn, proj_w, proj_b, x, x1, TT, DIM, DIM, nullptr, nullptr, 0, 0, 0);

    // 5. LN2
    ln_kernel<<<TT, 256>>>(x1, ln2_g, ln2_b, h);

    // 6. gate + bucketing
    gate_kernel<<<TT, 256>>>(h, gate_w, gate_b, cnt, ptok, smap, sw);

    // 7. MoE up-proj + GELU (grouped, gathered rows)
    gemm_nt<true, true><<<dim3(HID / 64, TT / 64, NE), 256>>>(
        h, w1, b1, nullptr, h1, TT, HID, DIM, ptok, cnt,
        0, (size_t)HID * DIM, (size_t)TT * HID);

    // 8. MoE down-proj (grouped)
    gemm_nt<false, false><<<dim3(DIM / 64, TT / 64, NE), 256>>>(
        h1, w2, b2, nullptr, y, TT, DIM, HID, nullptr, cnt,
        (size_t)TT * HID, (size_t)DIM * HID, (size_t)TT * DIM);

    // 9. combine + final residual
    combine_kernel<<<TT, 256>>>(x1, y, smap, sw, out);
}

// round 3
// speedup vs baseline: 2.2071x; 2.2071x over previous
#include <cuda_runtime.h>
#include <math.h>
#include <stdint.h>

#define BB 4
#define NN 1024
#define TT 4096
#define DIM 768
#define HEADS 12
#define HD 64
#define HID 3072
#define NE 8

#define NSTAGE 3
#define BKPAD 20   // 16 + 4 pad floats; 80B rows keep cp.async 16B-aligned, conflict-free frag reads

// ---------------- scratch (static device globals; no allocs) ----------------
__device__ float g_h[(size_t)TT * DIM];
__device__ float g_qkv[(size_t)TT * 3 * DIM];
__device__ float g_attn[(size_t)TT * DIM];
__device__ float g_x1[(size_t)TT * DIM];
__device__ float g_h1[(size_t)NE * TT * HID];
__device__ float g_y[(size_t)NE * TT * DIM];
__device__ int   g_cnt[NE];
__device__ int   g_ptok[NE * TT];
__device__ int   g_smap[TT * 2];
__device__ float g_sw[TT * 2];

__global__ void zero_cnt_kernel(int* c) {
    if (threadIdx.x < NE) c[threadIdx.x] = 0;
}

// ---------------- layernorm ---------------------------------------------------
__global__ void ln_kernel(const float* __restrict__ x, const float* __restrict__ g,
                          const float* __restrict__ b, float* __restrict__ o) {
    __shared__ float xs[DIM];
    __shared__ float red[256];
    int t = blockIdx.x, tid = threadIdx.x;
    const float* xr = x + (size_t)t * DIM;
    float s = 0.f;
    for (int i = tid; i < DIM; i += 256) { float v = xr[i]; xs[i] = v; s += v; }
    red[tid] = s; __syncthreads();
    for (int st = 128; st > 0; st >>= 1) { if (tid < st) red[tid] += red[tid + st]; __syncthreads(); }
    float mu = red[0] * (1.f / DIM);
    __syncthreads();
    s = 0.f;
    for (int i = tid; i < DIM; i += 256) { float d = xs[i] - mu; s += d * d; }
    red[tid] = s; __syncthreads();
    for (int st = 128; st > 0; st >>= 1) { if (tid < st) red[tid] += red[tid + st]; __syncthreads(); }
    float inv = rsqrtf(red[0] * (1.f / DIM) + 1e-5f);
    float* orow = o + (size_t)t * DIM;
    for (int i = tid; i < DIM; i += 256)
        orow[i] = (xs[i] - mu) * inv * g[i] + b[i];
}

// ---------------- tf32 tensor-core GEMM helpers ------------------------------
__device__ __forceinline__ uint32_t f2tf(float f) {
    uint32_t u;
    asm("cvt.rna.tf32.f32 %0, %1;" : "=r"(u) : "f"(f));
    return u;
}

__device__ __forceinline__ void mma_tf32(float* c, const uint32_t* a, const uint32_t* b) {
    asm volatile(
        "mma.sync.aligned.m16n8k8.row.col.f32.tf32.tf32.f32 "
        "{%0,%1,%2,%3}, {%4,%5,%6,%7}, {%8,%9}, {%0,%1,%2,%3};"
        : "+f"(c[0]), "+f"(c[1]), "+f"(c[2]), "+f"(c[3])
        : "r"(a[0]), "r"(a[1]), "r"(a[2]), "r"(a[3]), "r"(b[0]), "r"(b[1]));
}

__device__ __forceinline__ void cp16(uint32_t dst, const float* src, int sz) {
    asm volatile("cp.async.cg.shared.global [%0], [%1], 16, %2;"
                 :: "r"(dst), "l"(src), "r"(sz));
}

// ---------------- C = A @ B^T (+bias)(+gelu)(+resid), grouped, tf32 MMA ------
// BM=128, BN=128, BK=16, 256 threads (8 warps, each 32x64 via m16n8k8).
template <bool GATHER, bool GELU>
__global__ void __launch_bounds__(256)
gemm_tc(const float* __restrict__ A, const float* __restrict__ Bw,
        const float* __restrict__ bias, const float* __restrict__ resid,
        float* __restrict__ C, int M, int N, int K,
        const int* __restrict__ rows, const int* __restrict__ cnts,
        size_t sA, size_t sB, size_t sC) {
    extern __shared__ float sm[];
    float* SA = sm;                               // [NSTAGE][128*BKPAD]
    float* SB = sm + NSTAGE * 128 * BKPAD;

    int z = blockIdx.z;
    A += (size_t)z * sA; Bw += (size_t)z * sB; C += (size_t)z * sC;
    if (bias) bias += (size_t)z * N;
    if (rows) rows += (size_t)z * TT;
    int Mz = cnts ? cnts[z] : M;
    if (Mz > M) Mz = M;
    int m0 = blockIdx.y * 128;
    if (m0 >= Mz) return;
    int n0 = blockIdx.x * 128;

    int tid = threadIdx.x;
    int r0 = tid >> 2, kq = tid & 3;

    // loader: each thread owns rows r0 and r0+64 of A tile and B tile, 16B chunk kq
    const float *ga0, *ga1;
    int za0 = 16, za1 = 16;
    if (GATHER) {
        int i0 = m0 + r0, i1 = i0 + 64;
        int g0 = 0, g1 = 0;
        if (i0 < Mz) g0 = rows[i0]; else za0 = 0;
        if (i1 < Mz) g1 = rows[i1]; else za1 = 0;
        ga0 = A + (size_t)g0 * K + kq * 4;
        ga1 = A + (size_t)g1 * K + kq * 4;
    } else {
        ga0 = A + (size_t)(m0 + r0) * K + kq * 4;
        ga1 = ga0 + (size_t)64 * K;
    }
    const float* gb0 = Bw + (size_t)(n0 + r0) * K + kq * 4;
    const float* gb1 = gb0 + (size_t)64 * K;

    uint32_t sa_base = (uint32_t)__cvta_generic_to_shared(SA) + (r0 * BKPAD + kq * 4) * 4;
    uint32_t sb_base = (uint32_t)__cvta_generic_to_shared(SB) + (r0 * BKPAD + kq * 4) * 4;
    const uint32_t BUFB = 128 * BKPAD * 4;
    const uint32_t HALF = 64 * BKPAD * 4;

    int NIT = K >> 4;

    auto load_tile = [&](int it) {
        uint32_t off = (uint32_t)(it % NSTAGE) * BUFB;
        cp16(sa_base + off,        ga0 + it * 16, za0);
        cp16(sa_base + off + HALF, ga1 + it * 16, za1);
        cp16(sb_base + off,        gb0 + it * 16, 16);
        cp16(sb_base + off + HALF, gb1 + it * 16, 16);
        asm volatile("cp.async.commit_group;" ::: "memory");
    };

    int warp = tid >> 5, lane = tid & 31;
    int gid = lane >> 2, tg = lane & 3;
    int wm = (warp >> 1) * 32, wn = (warp & 1) * 64;

    float acc[2][8][4];
#pragma unroll
    for (int i = 0; i < 2; i++)
#pragma unroll
        for (int j = 0; j < 8; j++)
#pragma unroll
            for (int k = 0; k < 4; k++) acc[i][j][k] = 0.f;

    load_tile(0);
    if (NIT > 1) load_tile(1);

    for (int it = 0; it < NIT; ++it) {
        if (it + 1 < NIT) asm volatile("cp.async.wait_group 1;" ::: "memory");
        else              asm volatile("cp.async.wait_group 0;" ::: "memory");
        __syncthreads();
        if (it + 2 < NIT) load_tile(it + 2);

        const float* As = SA + (size_t)(it % NSTAGE) * 128 * BKPAD;
        const float* Bs = SB + (size_t)(it % NSTAGE) * 128 * BKPAD;

#pragma unroll
        for (int ks = 0; ks < 2; ks++) {
            int kk = ks * 8 + tg;
            uint32_t af[2][4], bf[8][2];
#pragma unroll
            for (int mi = 0; mi < 2; mi++) {
                int mr = wm + mi * 16 + gid;
                af[mi][0] = f2tf(As[mr * BKPAD + kk]);
                af[mi][1] = f2tf(As[(mr + 8) * BKPAD + kk]);
                af[mi][2] = f2tf(As[mr * BKPAD + kk + 4]);
                af[mi][3] = f2tf(As[(mr + 8) * BKPAD + kk + 4]);
            }
#pragma unroll
            for (int ni = 0; ni < 8; ni++) {
                int nr = wn + ni * 8 + gid;
                bf[ni][0] = f2tf(Bs[nr * BKPAD + kk]);
                bf[ni][1] = f2tf(Bs[nr * BKPAD + kk + 4]);
            }
#pragma unroll
            for (int mi = 0; mi < 2; mi++)
#pragma unroll
                for (int ni = 0; ni < 8; ni++)
                    mma_tf32(acc[mi][ni], af[mi], bf[ni]);
        }
    }

    // epilogue: c0,c1 -> (row gid, cols tg*2, tg*2+1); c2,c3 -> row gid+8
#pragma unroll
    for (int mi = 0; mi < 2; mi++) {
#pragma unroll
        for (int hh = 0; hh < 2; hh++) {
            int rr = m0 + wm + mi * 16 + gid + hh * 8;
            if (rr >= Mz) continue;
            float* crow = C + (size_t)rr * N;
            const float* rrow = resid ? resid + (size_t)rr * N : nullptr;
#pragma unroll
            for (int ni = 0; ni < 8; ni++) {
                int col = n0 + wn + ni * 8 + tg * 2;
                float v0 = acc[mi][ni][hh * 2 + 0];
                float v1 = acc[mi][ni][hh * 2 + 1];
                if (bias) { v0 += bias[col]; v1 += bias[col + 1]; }
                if (GELU) {
                    v0 = 0.5f * v0 * (1.f + erff(v0 * 0.70710678118654752f));
                    v1 = 0.5f * v1 * (1.f + erff(v1 * 0.70710678118654752f));
                }
                if (rrow) { v0 += rrow[col]; v1 += rrow[col + 1]; }
                crow[col] = v0; crow[col + 1] = v1;
            }
        }
    }
}

// ---------------- attention: 64-query tiles, online softmax ------------------
__global__ void __launch_bounds__(256)
attn_kernel(const float* __restrict__ qkv, float* __restrict__ out) {
    extern __shared__ float sm[];
    float* Qt = sm;
    float* Kt = Qt + 64 * 68;
    float* Vs = Kt + 64 * 68;
    float* Ps = Vs + 64 * 68;

    int bh = blockIdx.y;
    int b = bh / HEADS, h = bh % HEADS;
    int q0 = blockIdx.x * 64;
    int tid = threadIdx.x;
    int lr = tid >> 2, lc = tid & 3;
    int ty = tid >> 4, tx = tid & 15;
    const float scale = 0.125f;

    {
        const float* qp = qkv + (size_t)(b * NN + q0 + lr) * (3 * DIM) + h * HD;
#pragma unroll
        for (int r = 0; r < 4; r++) {
            int d0 = lc * 4 + r * 16;
            float4 v = *(const float4*)(qp + d0);
            Qt[(d0 + 0) * 68 + lr] = v.x; Qt[(d0 + 1) * 68 + lr] = v.y;
            Qt[(d0 + 2) * 68 + lr] = v.z; Qt[(d0 + 3) * 68 + lr] = v.w;
        }
    }

    float o[4][4], mrow[4], lrow[4];
#pragma unroll
    for (int i = 0; i < 4; i++) {
        mrow[i] = -1e30f; lrow[i] = 0.f;
#pragma unroll
        for (int j = 0; j < 4; j++) o[i][j] = 0.f;
    }

    for (int kt = 0; kt < NN / 64; kt++) {
        __syncthreads();
        int krow = kt * 64 + lr;
        const float* kp = qkv + (size_t)(b * NN + krow) * (3 * DIM) + DIM + h * HD;
        const float* vp = kp + DIM;
#pragma unroll
        for (int r = 0; r < 4; r++) {
            int d0 = lc * 4 + r * 16;
            float4 kv = *(const float4*)(kp + d0);
            Kt[(d0 + 0) * 68 + lr] = kv.x; Kt[(d0 + 1) * 68 + lr] = kv.y;
            Kt[(d0 + 2) * 68 + lr] = kv.z; Kt[(d0 + 3) * 68 + lr] = kv.w;
            float4 vv = *(const float4*)(vp + d0);
            *(float4*)&Vs[lr * 68 + d0] = vv;
        }
        __syncthreads();

        float s[4][4];
#pragma unroll
        for (int i = 0; i < 4; i++)
#pragma unroll
            for (int j = 0; j < 4; j++) s[i][j] = 0.f;
#pragma unroll 8
        for (int d = 0; d < 64; d++) {
            float4 a = *(const float4*)&Qt[d * 68 + ty * 4];
            float4 bb = *(const float4*)&Kt[d * 68 + tx * 4];
            s[0][0] += a.x * bb.x; s[0][1] += a.x * bb.y; s[0][2] += a.x * bb.z; s[0][3] += a.x * bb.w;
            s[1][0] += a.y * bb.x; s[1][1] += a.y * bb.y; s[1][2] += a.y * bb.z; s[1][3] += a.y * bb.w;
            s[2][0] += a.z * bb.x; s[2][1] += a.z * bb.y; s[2][2] += a.z * bb.z; s[2][3] += a.z * bb.w;
            s[3][0] += a.w * bb.x; s[3][1] += a.w * bb.y; s[3][2] += a.w * bb.z; s[3][3] += a.w * bb.w;
        }

#pragma unroll
        for (int i = 0; i < 4; i++) {
            float rm = s[i][0] * scale;
            rm = fmaxf(rm, s[i][1] * scale);
            rm = fmaxf(rm, s[i][2] * scale);
            rm = fmaxf(rm, s[i][3] * scale);
#pragma unroll
            for (int off = 1; off < 16; off <<= 1)
                rm = fmaxf(rm, __shfl_xor_sync(0xffffffffu, rm, off));
            float mn = fmaxf(mrow[i], rm);
            float corr = __expf(mrow[i] - mn);
            mrow[i] = mn;
            float rs = 0.f;
#pragma unroll
            for (int j = 0; j < 4; j++) {
                float p = __expf(s[i][j] * scale - mn);
                s[i][j] = p;
                rs += p;
            }
#pragma unroll
            for (int off = 1; off < 16; off <<= 1)
                rs += __shfl_xor_sync(0xffffffffu, rs, off);
            lrow[i] = lrow[i] * corr + rs;
#pragma unroll
            for (int j = 0; j < 4; j++) o[i][j] *= corr;
        }

#pragma unroll
        for (int i = 0; i < 4; i++)
#pragma unroll
            for (int j = 0; j < 4; j++)
                Ps[(tx * 4 + j) * 68 + ty * 4 + i] = s[i][j];
        __syncthreads();

#pragma unroll 8
        for (int kk = 0; kk < 64; kk++) {
            float4 p = *(const float4*)&Ps[kk * 68 + ty * 4];
            float4 v = *(const float4*)&Vs[kk * 68 + tx * 4];
            o[0][0] += p.x * v.x; o[0][1] += p.x * v.y; o[0][2] += p.x * v.z; o[0][3] += p.x * v.w;
            o[1][0] += p.y * v.x; o[1][1] += p.y * v.y; o[1][2] += p.y * v.z; o[1][3] += p.y * v.w;
            o[2][0] += p.z * v.x; o[2][1] += p.z * v.y; o[2][2] += p.z * v.z; o[2][3] += p.z * v.w;
            o[3][0] += p.w * v.x; o[3][1] += p.w * v.y; o[3][2] += p.w * v.z; o[3][3] += p.w * v.w;
        }
    }

#pragma unroll
    for (int i = 0; i < 4; i++) {
        float inv = 1.f / lrow[i];
        int q = q0 + ty * 4 + i;
        float* orow = out + (size_t)(b * NN + q) * DIM + h * HD + tx * 4;
#pragma unroll
        for (int j = 0; j < 4; j++) orow[j] = o[i][j] * inv;
    }
}

// ---------------- gate ---------------------------------------------------------
__global__ void gate_kernel(const float* __restrict__ h2, const float* __restrict__ gw,
                            const float* __restrict__ gb, int* __restrict__ cnt,
                            int* __restrict__ ptok, int* __restrict__ smap,
                            float* __restrict__ sw) {
    __shared__ float lg[NE];
    int t = blockIdx.x, tid = threadIdx.x;
    int w = tid >> 5, lane = tid & 31;
    const float* hr = h2 + (size_t)t * DIM;
    float s = 0.f;
    const float* gr = gw + (size_t)w * DIM;
    for (int k = lane; k < DIM; k += 32) s += hr[k] * gr[k];
#pragma unroll
    for (int off = 16; off > 0; off >>= 1) s += __shfl_down_sync(0xffffffffu, s, off);
    if (lane == 0) lg[w] = s + gb[w];
    __syncthreads();
    if (tid == 0) {
        int b0 = 0; float v0 = lg[0];
        for (int e = 1; e < NE; e++) if (lg[e] > v0) { v0 = lg[e]; b0 = e; }
        int b1 = -1; float v1 = -1e30f;
        for (int e = 0; e < NE; e++) {
            if (e == b0) continue;
            if (lg[e] > v1) { v1 = lg[e]; b1 = e; }
        }
        float e1 = __expf(v1 - v0);
        float s0 = 1.f / (1.f + e1);
        float s1 = 1.f - s0;
        int p0 = atomicAdd(&cnt[b0], 1);
        int p1 = atomicAdd(&cnt[b1], 1);
        ptok[b0 * TT + p0] = t;
        ptok[b1 * TT + p1] = t;
        smap[t * 2 + 0] = b0 * TT + p0; sw[t * 2 + 0] = s0;
        smap[t * 2 + 1] = b1 * TT + p1; sw[t * 2 + 1] = s1;
    }
}

// ---------------- combine ------------------------------------------------------
__global__ void combine_kernel(const float* __restrict__ x1, const float* __restrict__ y,
                               const int* __restrict__ smap, const float* __restrict__ sw,
                               float* __restrict__ out) {
    int t = blockIdx.x, tid = threadIdx.x;
    int s0 = smap[t * 2 + 0], s1 = smap[t * 2 + 1];
    float w0 = sw[t * 2 + 0], w1 = sw[t * 2 + 1];
    const float* y0 = y + (size_t)s0 * DIM;
    const float* y1 = y + (size_t)s1 * DIM;
    const float* xr = x1 + (size_t)t * DIM;
    float* orow = out + (size_t)t * DIM;
    for (int c = tid; c < DIM; c += 256)
        orow[c] = xr[c] + w0 * y0[c] + w1 * y1[c];
}

// ---------------- host launcher ------------------------------------------------
extern "C" void kernel_launch(void* const* d_in, const int* in_sizes, int n_in,
                              void* d_out, int out_size) {
    const float* x      = (const float*)d_in[0];
    const float* ln1_g  = (const float*)d_in[1];
    const float* ln1_b  = (const float*)d_in[2];
    const float* qkv_w  = (const float*)d_in[3];
    const float* proj_w = (const float*)d_in[4];
    const float* proj_b = (const float*)d_in[5];
    const float* ln2_g  = (const float*)d_in[6];
    const float* ln2_b  = (const float*)d_in[7];
    const float* gate_w = (const float*)d_in[8];
    const float* gate_b = (const float*)d_in[9];
    const float* w1     = (const float*)d_in[10];
    const float* b1     = (const float*)d_in[11];
    const float* w2     = (const float*)d_in[12];
    const float* b2     = (const float*)d_in[13];
    float* out = (float*)d_out;

    float *h, *qkvb, *attn, *x1, *h1, *y, *sw;
    int *cnt, *ptok, *smap;
    cudaGetSymbolAddress((void**)&h, g_h);
    cudaGetSymbolAddress((void**)&qkvb, g_qkv);
    cudaGetSymbolAddress((void**)&attn, g_attn);
    cudaGetSymbolAddress((void**)&x1, g_x1);
    cudaGetSymbolAddress((void**)&h1, g_h1);
    cudaGetSymbolAddress((void**)&y, g_y);
    cudaGetSymbolAddress((void**)&cnt, g_cnt);
    cudaGetSymbolAddress((void**)&ptok, g_ptok);
    cudaGetSymbolAddress((void**)&smap, g_smap);
    cudaGetSymbolAddress((void**)&sw, g_sw);

    const int ATTN_SMEM = 4 * 64 * 68 * 4;                  // 69632
    const int GEMM_SMEM = NSTAGE * 128 * BKPAD * 4 * 2;     // 61440
    cudaFuncSetAttribute(attn_kernel, cudaFuncAttributeMaxDynamicSharedMemorySize, ATTN_SMEM);
    cudaFuncSetAttribute(gemm_tc<false, false>, cudaFuncAttributeMaxDynamicSharedMemorySize, GEMM_SMEM);
    cudaFuncSetAttribute(gemm_tc<true, true>,   cudaFuncAttributeMaxDynamicSharedMemorySize, GEMM_SMEM);

    // 0. zero expert counters
    zero_cnt_kernel<<<1, 32>>>(cnt);

    // 1. LN1
    ln_kernel<<<TT, 256>>>(x, ln1_g, ln1_b, h);

    // 2. qkv = h @ qkv_w^T  [4096, 2304]
    gemm_tc<false, false><<<dim3(18, 32, 1), 256, GEMM_SMEM>>>(
        h, qkv_w, nullptr, nullptr, qkvb, TT, 3 * DIM, DIM, nullptr, nullptr, 0, 0, 0);

    // 3. attention
    attn_kernel<<<dim3(NN / 64, BB * HEADS), 256, ATTN_SMEM>>>(qkvb, attn);

    // 4. x1 = x + attn @ proj_w^T + proj_b
    gemm_tc<false, false><<<dim3(6, 32, 1), 256, GEMM_SMEM>>>(
        attn, proj_w, proj_b, x, x1, TT, DIM, DIM, nullptr, nullptr, 0, 0, 0);

    // 5. LN2
    ln_kernel<<<TT, 256>>>(x1, ln2_g, ln2_b, h);

    // 6. gate + bucketing
    gate_kernel<<<TT, 256>>>(h, gate_w, gate_b, cnt, ptok, smap, sw);

    // 7. MoE up-proj + GELU (grouped, gathered rows)
    gemm_tc<true, true><<<dim3(HID / 128, TT / 128, NE), 256, GEMM_SMEM>>>(
        h, w1, b1, nullptr, h1, TT, HID, DIM, ptok, cnt,
        0, (size_t)HID * DIM, (size_t)TT * HID);

    // 8. MoE down-proj (grouped)
    gemm_tc<false, false><<<dim3(DIM / 128, TT / 128, NE), 256, GEMM_SMEM>>>(
        h1, w2, b2, nullptr, y, TT, DIM, HID, nullptr, cnt,
        (size_t)TT * HID, (size_t)DIM * HID, (size_t)TT * DIM);

    // 9. combine + final residual
    combine_kernel<<<TT, 256>>>(x1, y, smap, sw, out);
}

// round 4
// speedup vs baseline: 2.5829x; 1.1703x over previous
#include <cuda_runtime.h>
#include <math.h>
#include <stdint.h>

#define BB 4
#define NN 1024
#define TT 4096
#define DIM 768
#define HEADS 12
#define HD 64
#define HID 3072
#define NE 8

#define NSTAGE 3
#define BKPAD 20

// attention tiling
#define BQ 128
#define PADK 68
#define PADV 72
#define PADP 68

// ---------------- scratch (static device globals; no allocs) ----------------
__device__ float g_h[(size_t)TT * DIM];
__device__ float g_qkv[(size_t)TT * 3 * DIM];
__device__ float g_attn[(size_t)TT * DIM];
__device__ float g_x1[(size_t)TT * DIM];
__device__ float g_h1[(size_t)NE * TT * HID];
__device__ float g_y[(size_t)NE * TT * DIM];
__device__ int   g_cnt[NE];
__device__ int   g_ptok[NE * TT];
__device__ int   g_smap[TT * 2];
__device__ float g_sw[TT * 2];

__global__ void zero_cnt_kernel(int* c) {
    if (threadIdx.x < NE) c[threadIdx.x] = 0;
}

// ---------------- layernorm ---------------------------------------------------
__global__ void ln_kernel(const float* __restrict__ x, const float* __restrict__ g,
                          const float* __restrict__ b, float* __restrict__ o) {
    __shared__ float xs[DIM];
    __shared__ float red[256];
    int t = blockIdx.x, tid = threadIdx.x;
    const float* xr = x + (size_t)t * DIM;
    float s = 0.f;
    for (int i = tid; i < DIM; i += 256) { float v = xr[i]; xs[i] = v; s += v; }
    red[tid] = s; __syncthreads();
    for (int st = 128; st > 0; st >>= 1) { if (tid < st) red[tid] += red[tid + st]; __syncthreads(); }
    float mu = red[0] * (1.f / DIM);
    __syncthreads();
    s = 0.f;
    for (int i = tid; i < DIM; i += 256) { float d = xs[i] - mu; s += d * d; }
    red[tid] = s; __syncthreads();
    for (int st = 128; st > 0; st >>= 1) { if (tid < st) red[tid] += red[tid + st]; __syncthreads(); }
    float inv = rsqrtf(red[0] * (1.f / DIM) + 1e-5f);
    float* orow = o + (size_t)t * DIM;
    for (int i = tid; i < DIM; i += 256)
        orow[i] = (xs[i] - mu) * inv * g[i] + b[i];
}

// ---------------- tf32 tensor-core helpers ------------------------------------
__device__ __forceinline__ uint32_t f2tf(float f) {
    uint32_t u;
    asm("cvt.rna.tf32.f32 %0, %1;" : "=r"(u) : "f"(f));
    return u;
}

__device__ __forceinline__ void mma_tf32(float* c, const uint32_t* a, const uint32_t* b) {
    asm volatile(
        "mma.sync.aligned.m16n8k8.row.col.f32.tf32.tf32.f32 "
        "{%0,%1,%2,%3}, {%4,%5,%6,%7}, {%8,%9}, {%0,%1,%2,%3};"
        : "+f"(c[0]), "+f"(c[1]), "+f"(c[2]), "+f"(c[3])
        : "r"(a[0]), "r"(a[1]), "r"(a[2]), "r"(a[3]), "r"(b[0]), "r"(b[1]));
}

__device__ __forceinline__ void cp16(uint32_t dst, const float* src, int sz) {
    asm volatile("cp.async.cg.shared.global [%0], [%1], 16, %2;"
                 :: "r"(dst), "l"(src), "r"(sz));
}

// ---------------- C = A @ B^T (+bias)(+gelu)(+resid), grouped, tf32 MMA ------
template <bool GATHER, bool GELU>
__global__ void __launch_bounds__(256)
gemm_tc(const float* __restrict__ A, const float* __restrict__ Bw,
        const float* __restrict__ bias, const float* __restrict__ resid,
        float* __restrict__ C, int M, int N, int K,
        const int* __restrict__ rows, const int* __restrict__ cnts,
        size_t sA, size_t sB, size_t sC) {
    extern __shared__ float sm[];
    float* SA = sm;
    float* SB = sm + NSTAGE * 128 * BKPAD;

    int z = blockIdx.z;
    A += (size_t)z * sA; Bw += (size_t)z * sB; C += (size_t)z * sC;
    if (bias) bias += (size_t)z * N;
    if (rows) rows += (size_t)z * TT;
    int Mz = cnts ? cnts[z] : M;
    if (Mz > M) Mz = M;
    int m0 = blockIdx.y * 128;
    if (m0 >= Mz) return;
    int n0 = blockIdx.x * 128;

    int tid = threadIdx.x;
    int r0 = tid >> 2, kq = tid & 3;

    const float *ga0, *ga1;
    int za0 = 16, za1 = 16;
    if (GATHER) {
        int i0 = m0 + r0, i1 = i0 + 64;
        int g0 = 0, g1 = 0;
        if (i0 < Mz) g0 = rows[i0]; else za0 = 0;
        if (i1 < Mz) g1 = rows[i1]; else za1 = 0;
        ga0 = A + (size_t)g0 * K + kq * 4;
        ga1 = A + (size_t)g1 * K + kq * 4;
    } else {
        ga0 = A + (size_t)(m0 + r0) * K + kq * 4;
        ga1 = ga0 + (size_t)64 * K;
    }
    const float* gb0 = Bw + (size_t)(n0 + r0) * K + kq * 4;
    const float* gb1 = gb0 + (size_t)64 * K;

    uint32_t sa_base = (uint32_t)__cvta_generic_to_shared(SA) + (r0 * BKPAD + kq * 4) * 4;
    uint32_t sb_base = (uint32_t)__cvta_generic_to_shared(SB) + (r0 * BKPAD + kq * 4) * 4;
    const uint32_t BUFB = 128 * BKPAD * 4;
    const uint32_t HALF = 64 * BKPAD * 4;

    int NIT = K >> 4;

    auto load_tile = [&](int it) {
        uint32_t off = (uint32_t)(it % NSTAGE) * BUFB;
        cp16(sa_base + off,        ga0 + it * 16, za0);
        cp16(sa_base + off + HALF, ga1 + it * 16, za1);
        cp16(sb_base + off,        gb0 + it * 16, 16);
        cp16(sb_base + off + HALF, gb1 + it * 16, 16);
        asm volatile("cp.async.commit_group;" ::: "memory");
    };

    int warp = tid >> 5, lane = tid & 31;
    int gid = lane >> 2, tg = lane & 3;
    int wm = (warp >> 1) * 32, wn = (warp & 1) * 64;

    float acc[2][8][4];
#pragma unroll
    for (int i = 0; i < 2; i++)
#pragma unroll
        for (int j = 0; j < 8; j++)
#pragma unroll
            for (int k = 0; k < 4; k++) acc[i][j][k] = 0.f;

    load_tile(0);
    if (NIT > 1) load_tile(1);

    for (int it = 0; it < NIT; ++it) {
        if (it + 1 < NIT) asm volatile("cp.async.wait_group 1;" ::: "memory");
        else              asm volatile("cp.async.wait_group 0;" ::: "memory");
        __syncthreads();
        if (it + 2 < NIT) load_tile(it + 2);

        const float* As = SA + (size_t)(it % NSTAGE) * 128 * BKPAD;
        const float* Bs = SB + (size_t)(it % NSTAGE) * 128 * BKPAD;

#pragma unroll
        for (int ks = 0; ks < 2; ks++) {
            int kk = ks * 8 + tg;
            uint32_t af[2][4], bf[8][2];
#pragma unroll
            for (int mi = 0; mi < 2; mi++) {
                int mr = wm + mi * 16 + gid;
                af[mi][0] = f2tf(As[mr * BKPAD + kk]);
                af[mi][1] = f2tf(As[(mr + 8) * BKPAD + kk]);
                af[mi][2] = f2tf(As[mr * BKPAD + kk + 4]);
                af[mi][3] = f2tf(As[(mr + 8) * BKPAD + kk + 4]);
            }
#pragma unroll
            for (int ni = 0; ni < 8; ni++) {
                int nr = wn + ni * 8 + gid;
                bf[ni][0] = f2tf(Bs[nr * BKPAD + kk]);
                bf[ni][1] = f2tf(Bs[nr * BKPAD + kk + 4]);
            }
#pragma unroll
            for (int mi = 0; mi < 2; mi++)
#pragma unroll
                for (int ni = 0; ni < 8; ni++)
                    mma_tf32(acc[mi][ni], af[mi], bf[ni]);
        }
    }

#pragma unroll
    for (int mi = 0; mi < 2; mi++) {
#pragma unroll
        for (int hh = 0; hh < 2; hh++) {
            int rr = m0 + wm + mi * 16 + gid + hh * 8;
            if (rr >= Mz) continue;
            float* crow = C + (size_t)rr * N;
            const float* rrow = resid ? resid + (size_t)rr * N : nullptr;
#pragma unroll
            for (int ni = 0; ni < 8; ni++) {
                int col = n0 + wn + ni * 8 + tg * 2;
                float v0 = acc[mi][ni][hh * 2 + 0];
                float v1 = acc[mi][ni][hh * 2 + 1];
                if (bias) { v0 += bias[col]; v1 += bias[col + 1]; }
                if (GELU) {
                    v0 = 0.5f * v0 * (1.f + erff(v0 * 0.70710678118654752f));
                    v1 = 0.5f * v1 * (1.f + erff(v1 * 0.70710678118654752f));
                }
                if (rrow) { v0 += rrow[col]; v1 += rrow[col + 1]; }
                crow[col] = v0; crow[col + 1] = v1;
            }
        }
    }
}

// ---------------- tensor-core flash attention --------------------------------
// 128-query x 64-key tiles. 8 warps; warp w owns q-rows [16w, 16w+16) for both
// S = (Q/8) K^T and O += P V. Softmax: 2 threads per row.
__global__ void __launch_bounds__(256)
attn_tc(const float* __restrict__ qkv, float* __restrict__ out) {
    extern __shared__ float sm[];
    float* SK    = sm;                      // [64][PADK]
    float* SV    = SK + 64 * PADK;          // [64][PADV]
    float* SP    = SV + 64 * PADV;          // [128][PADP]  (Q stage, then S/P)
    float* scorr = SP + 128 * PADP;         // [128]
    float* slsum = scorr + 128;             // [128]

    int bh = blockIdx.y;
    int b = bh / HEADS, h = bh % HEADS;
    int q0 = blockIdx.x * BQ;
    int tid = threadIdx.x;
    int warp = tid >> 5, lane = tid & 31;
    int gid = lane >> 2, tg = lane & 3;
    int wm = warp * 16;

    // ---- stage Q (scaled by 1/8) into SP ----
    {
        int row = tid >> 1, cb = (tid & 1) * 32;
        const float* qp = qkv + (size_t)(b * NN + q0 + row) * (3 * DIM) + h * HD + cb;
        float* dst = SP + row * PADP + cb;
#pragma unroll
        for (int j = 0; j < 8; j++) {
            float4 v = *(const float4*)(qp + j * 4);
            v.x *= 0.125f; v.y *= 0.125f; v.z *= 0.125f; v.w *= 0.125f;
            *(float4*)(dst + j * 4) = v;
        }
    }
    __syncthreads();

    // ---- Q fragments (tf32, converted once) ----
    uint32_t qf[8][4];
#pragma unroll
    for (int ks = 0; ks < 8; ks++) {
        int kk = ks * 8 + tg;
        qf[ks][0] = f2tf(SP[(wm + gid) * PADP + kk]);
        qf[ks][1] = f2tf(SP[(wm + gid + 8) * PADP + kk]);
        qf[ks][2] = f2tf(SP[(wm + gid) * PADP + kk + 4]);
        qf[ks][3] = f2tf(SP[(wm + gid + 8) * PADP + kk + 4]);
    }

    float of[8][4];
#pragma unroll
    for (int i = 0; i < 8; i++)
#pragma unroll
        for (int j = 0; j < 4; j++) of[i][j] = 0.f;

    int srow = tid >> 1, scb = (tid & 1) * 32;
    float mrun = -1e30f, lrun = 0.f;

    for (int kt = 0; kt < NN / 64; kt++) {
        __syncthreads();   // SP/SK/SV reuse guard
        // ---- load K,V tiles ----
        {
            int row = tid >> 2, cb = (tid & 3) * 16;
            const float* kp = qkv + (size_t)(b * NN + kt * 64 + row) * (3 * DIM) + DIM + h * HD + cb;
            const float* vp = kp + DIM;
            float* kd = SK + row * PADK + cb;
            float* vd = SV + row * PADV + cb;
#pragma unroll
            for (int j = 0; j < 4; j++) {
                *(float4*)(kd + j * 4) = *(const float4*)(kp + j * 4);
                *(float4*)(vd + j * 4) = *(const float4*)(vp + j * 4);
            }
        }
        __syncthreads();

        // ---- S = Qs @ K^T  (warp: 16 x 64) ----
        float sf[8][4];
#pragma unroll
        for (int i = 0; i < 8; i++)
#pragma unroll
            for (int j = 0; j < 4; j++) sf[i][j] = 0.f;
#pragma unroll
        for (int ks = 0; ks < 8; ks++) {
            int kk = ks * 8 + tg;
            uint32_t bfr[8][2];
#pragma unroll
            for (int ni = 0; ni < 8; ni++) {
                const float* kr = SK + (ni * 8 + gid) * PADK;
                bfr[ni][0] = f2tf(kr[kk]);
                bfr[ni][1] = f2tf(kr[kk + 4]);
            }
#pragma unroll
            for (int ni = 0; ni < 8; ni++)
                mma_tf32(sf[ni], qf[ks], bfr[ni]);
        }
        // write S to SP
#pragma unroll
        for (int ni = 0; ni < 8; ni++) {
            float* p0 = SP + (wm + gid) * PADP + ni * 8 + 2 * tg;
            float* p1 = SP + (wm + gid + 8) * PADP + ni * 8 + 2 * tg;
            p0[0] = sf[ni][0]; p0[1] = sf[ni][1];
            p1[0] = sf[ni][2]; p1[1] = sf[ni][3];
        }
        __syncthreads();

        // ---- online softmax (2 threads per row, 32 cols each) ----
        {
            float* rowp = SP + srow * PADP + scb;
            float rm = -1e30f;
#pragma unroll
            for (int j = 0; j < 32; j++) rm = fmaxf(rm, rowp[j]);
            rm = fmaxf(rm, __shfl_xor_sync(0xffffffffu, rm, 1));
            float mn = fmaxf(mrun, rm);
            float corr = __expf(mrun - mn);
            mrun = mn;
            float rs = 0.f;
#pragma unroll
            for (int j = 0; j < 32; j++) {
                float p = __expf(rowp[j] - mn);
                rowp[j] = p;
                rs += p;
            }
            rs += __shfl_xor_sync(0xffffffffu, rs, 1);
            lrun = lrun * corr + rs;
            if ((tid & 1) == 0) scorr[srow] = corr;
        }
        __syncthreads();

        // ---- rescale O, then O += P @ V ----
        float c0 = scorr[wm + gid], c1 = scorr[wm + gid + 8];
#pragma unroll
        for (int ni = 0; ni < 8; ni++) {
            of[ni][0] *= c0; of[ni][1] *= c0;
            of[ni][2] *= c1; of[ni][3] *= c1;
        }
#pragma unroll
        for (int ks = 0; ks < 8; ks++) {
            int kk = ks * 8 + tg;
            uint32_t af[4], bfr[8][2];
            af[0] = f2tf(SP[(wm + gid) * PADP + kk]);
            af[1] = f2tf(SP[(wm + gid + 8) * PADP + kk]);
            af[2] = f2tf(SP[(wm + gid) * PADP + kk + 4]);
            af[3] = f2tf(SP[(wm + gid + 8) * PADP + kk + 4]);
#pragma unroll
            for (int ni = 0; ni < 8; ni++) {
                bfr[ni][0] = f2tf(SV[(ks * 8 + tg) * PADV + ni * 8 + gid]);
                bfr[ni][1] = f2tf(SV[(ks * 8 + tg + 4) * PADV + ni * 8 + gid]);
            }
#pragma unroll
            for (int ni = 0; ni < 8; ni++)
                mma_tf32(of[ni], af, bfr[ni]);
        }
    }

    // ---- finalize: divide by l and write out ----
    if ((tid & 1) == 0) slsum[srow] = lrun;
    __syncthreads();
    float i0 = 1.f / slsum[wm + gid];
    float i1 = 1.f / slsum[wm + gid + 8];
    float* o0 = out + (size_t)(b * NN + q0 + wm + gid) * DIM + h * HD;
    float* o1 = out + (size_t)(b * NN + q0 + wm + gid + 8) * DIM + h * HD;
#pragma unroll
    for (int ni = 0; ni < 8; ni++) {
        int col = ni * 8 + 2 * tg;
        o0[col] = of[ni][0] * i0; o0[col + 1] = of[ni][1] * i0;
        o1[col] = of[ni][2] * i1; o1[col + 1] = of[ni][3] * i1;
    }
}

// ---------------- gate ---------------------------------------------------------
__global__ void gate_kernel(const float* __restrict__ h2, const float* __restrict__ gw,
                            const float* __restrict__ gb, int* __restrict__ cnt,
                            int* __restrict__ ptok, int* __restrict__ smap,
                            float* __restrict__ sw) {
    __shared__ float lg[NE];
    int t = blockIdx.x, tid = threadIdx.x;
    int w = tid >> 5, lane = tid & 31;
    const float* hr = h2 + (size_t)t * DIM;
    float s = 0.f;
    const float* gr = gw + (size_t)w * DIM;
    for (int k = lane; k < DIM; k += 32) s += hr[k] * gr[k];
#pragma unroll
    for (int off = 16; off > 0; off >>= 1) s += __shfl_down_sync(0xffffffffu, s, off);
    if (lane == 0) lg[w] = s + gb[w];
    __syncthreads();
    if (tid == 0) {
        int b0 = 0; float v0 = lg[0];
        for (int e = 1; e < NE; e++) if (lg[e] > v0) { v0 = lg[e]; b0 = e; }
        int b1 = -1; float v1 = -1e30f;
        for (int e = 0; e < NE; e++) {
            if (e == b0) continue;
            if (lg[e] > v1) { v1 = lg[e]; b1 = e; }
        }
        float e1 = __expf(v1 - v0);
        float s0 = 1.f / (1.f + e1);
        float s1 = 1.f - s0;
        int p0 = atomicAdd(&cnt[b0], 1);
        int p1 = atomicAdd(&cnt[b1], 1);
        ptok[b0 * TT + p0] = t;
        ptok[b1 * TT + p1] = t;
        smap[t * 2 + 0] = b0 * TT + p0; sw[t * 2 + 0] = s0;
        smap[t * 2 + 1] = b1 * TT + p1; sw[t * 2 + 1] = s1;
    }
}

// ---------------- combine ------------------------------------------------------
__global__ void combine_kernel(const float* __restrict__ x1, const float* __restrict__ y,
                               const int* __restrict__ smap, const float* __restrict__ sw,
                               float* __restrict__ out) {
    int t = blockIdx.x, tid = threadIdx.x;
    int s0 = smap[t * 2 + 0], s1 = smap[t * 2 + 1];
    float w0 = sw[t * 2 + 0], w1 = sw[t * 2 + 1];
    const float* y0 = y + (size_t)s0 * DIM;
    const float* y1 = y + (size_t)s1 * DIM;
    const float* xr = x1 + (size_t)t * DIM;
    float* orow = out + (size_t)t * DIM;
    for (int c = tid; c < DIM; c += 256)
        orow[c] = xr[c] + w0 * y0[c] + w1 * y1[c];
}

// ---------------- host launcher ------------------------------------------------
extern "C" void kernel_launch(void* const* d_in, const int* in_sizes, int n_in,
                              void* d_out, int out_size) {
    const float* x      = (const float*)d_in[0];
    const float* ln1_g  = (const float*)d_in[1];
    const float* ln1_b  = (const float*)d_in[2];
    const float* qkv_w  = (const float*)d_in[3];
    const float* proj_w = (const float*)d_in[4];
    const float* proj_b = (const float*)d_in[5];
    const float* ln2_g  = (const float*)d_in[6];
    const float* ln2_b  = (const float*)d_in[7];
    const float* gate_w = (const float*)d_in[8];
    const float* gate_b = (const float*)d_in[9];
    const float* w1     = (const float*)d_in[10];
    const float* b1     = (const float*)d_in[11];
    const float* w2     = (const float*)d_in[12];
    const float* b2     = (const float*)d_in[13];
    float* out = (float*)d_out;

    float *h, *qkvb, *attn, *x1, *h1, *y, *sw;
    int *cnt, *ptok, *smap;
    cudaGetSymbolAddress((void**)&h, g_h);
    cudaGetSymbolAddress((void**)&qkvb, g_qkv);
    cudaGetSymbolAddress((void**)&attn, g_attn);
    cudaGetSymbolAddress((void**)&x1, g_x1);
    cudaGetSymbolAddress((void**)&h1, g_h1);
    cudaGetSymbolAddress((void**)&y, g_y);
    cudaGetSymbolAddress((void**)&cnt, g_cnt);
    cudaGetSymbolAddress((void**)&ptok, g_ptok);
    cudaGetSymbolAddress((void**)&smap, g_smap);
    cudaGetSymbolAddress((void**)&sw, g_sw);

    const int ATTN_SMEM = (64 * PADK + 64 * PADV + 128 * PADP + 256) * 4;  // 71680
    const int GEMM_SMEM = NSTAGE * 128 * BKPAD * 4 * 2;                    // 61440
    cudaFuncSetAttribute(attn_tc, cudaFuncAttributeMaxDynamicSharedMemorySize, ATTN_SMEM);
    cudaFuncSetAttribute(gemm_tc<false, false>, cudaFuncAttributeMaxDynamicSharedMemorySize, GEMM_SMEM);
    cudaFuncSetAttribute(gemm_tc<true, true>,   cudaFuncAttributeMaxDynamicSharedMemorySize, GEMM_SMEM);

    // 0. zero expert counters
    zero_cnt_kernel<<<1, 32>>>(cnt);

    // 1. LN1
    ln_kernel<<<TT, 256>>>(x, ln1_g, ln1_b, h);

    // 2. qkv = h @ qkv_w^T
    gemm_tc<false, false><<<dim3(18, 32, 1), 256, GEMM_SMEM>>>(
        h, qkv_w, nullptr, nullptr, qkvb, TT, 3 * DIM, DIM, nullptr, nullptr, 0, 0, 0);

    // 3. attention (tensor cores)
    attn_tc<<<dim3(NN / BQ, BB * HEADS), 256, ATTN_SMEM>>>(qkvb, attn);

    // 4. x1 = x + attn @ proj_w^T + proj_b
    gemm_tc<false, false><<<dim3(6, 32, 1), 256, GEMM_SMEM>>>(
        attn, proj_w, proj_b, x, x1, TT, DIM, DIM, nullptr, nullptr, 0, 0, 0);

    // 5. LN2
    ln_kernel<<<TT, 256>>>(x1, ln2_g, ln2_b, h);

    // 6. gate + bucketing
    gate_kernel<<<TT, 256>>>(h, gate_w, gate_b, cnt, ptok, smap, sw);

    // 7. MoE up-proj + GELU (grouped, gathered rows)
    gemm_tc<true, true><<<dim3(HID / 128, TT / 128, NE), 256, GEMM_SMEM>>>(
        h, w1, b1, nullptr, h1, TT, HID, DIM, ptok, cnt,
        0, (size_t)HID * DIM, (size_t)TT * HID);

    // 8. MoE down-proj (grouped)
    gemm_tc<false, false><<<dim3(DIM / 128, TT / 128, NE), 256, GEMM_SMEM>>>(
        h1, w2, b2, nullptr, y, TT, DIM, HID, nullptr, cnt,
        (size_t)TT * HID, (size_t)DIM * HID, (size_t)TT * DIM);

    // 9. combine + final residual
    combine_kernel<<<TT, 256>>>(x1, y, smap, sw, out);
}

// round 5
// speedup vs baseline: 2.8040x; 1.0856x over previous
#include <cuda_runtime.h>
#include <math.h>
#include <stdint.h>

#define BB 4
#define NN 1024
#define TT 4096
#define DIM 768
#define HEADS 12
#define HD 64
#define HID 3072
#define NE 8

#define NSTAGE 3
#define BKPAD 20

// attention tiling
#define BQ 128
#define PADK 68
#define PADV 72
#define PADP 68

// weight scratch offsets (floats)
#define W_QKV_OFF 0
#define W_QKV_N   (3 * DIM * DIM)                 // 1769472
#define W_PROJ_OFF (W_QKV_OFF + W_QKV_N)
#define W_PROJ_N  (DIM * DIM)                     // 589824
#define W_W1_OFF  (W_PROJ_OFF + W_PROJ_N)
#define W_W1_N    (NE * HID * DIM)                // 18874368
#define W_W2_OFF  (W_W1_OFF + W_W1_N)
#define W_W2_N    (NE * DIM * HID)                // 18874368

// ---------------- scratch (static device globals; no allocs) ----------------
__device__ float g_h[(size_t)TT * DIM];
__device__ float g_qkv[(size_t)TT * 3 * DIM];
__device__ float g_attn[(size_t)TT * DIM];
__device__ float g_x1[(size_t)TT * DIM];
__device__ float g_h1[(size_t)NE * TT * HID];
__device__ float g_y[(size_t)NE * TT * DIM];
__device__ float g_wtf[(size_t)W_W2_OFF + W_W2_N];   // tf32-rounded weights
__device__ int   g_cnt[NE];
__device__ int   g_ptok[NE * TT];
__device__ int   g_smap[TT * 2];
__device__ float g_sw[TT * 2];

__global__ void zero_cnt_kernel(int* c) {
    if (threadIdx.x < NE) c[threadIdx.x] = 0;
}

// ---------------- tf32 helpers -------------------------------------------------
__device__ __forceinline__ uint32_t f2tf(float f) {
    uint32_t u;
    asm("cvt.rna.tf32.f32 %0, %1;" : "=r"(u) : "f"(f));
    return u;
}
__device__ __forceinline__ float tf32r(float f) {
    uint32_t u;
    asm("cvt.rna.tf32.f32 %0, %1;" : "=r"(u) : "f"(f));
    return __uint_as_float(u);
}

__device__ __forceinline__ void mma_tf32(float* c, const uint32_t* a, const uint32_t* b) {
    asm volatile(
        "mma.sync.aligned.m16n8k8.row.col.f32.tf32.tf32.f32 "
        "{%0,%1,%2,%3}, {%4,%5,%6,%7}, {%8,%9}, {%0,%1,%2,%3};"
        : "+f"(c[0]), "+f"(c[1]), "+f"(c[2]), "+f"(c[3])
        : "r"(a[0]), "r"(a[1]), "r"(a[2]), "r"(a[3]), "r"(b[0]), "r"(b[1]));
}

__device__ __forceinline__ void cp16(uint32_t dst, const float* src, int sz) {
    asm volatile("cp.async.cg.shared.global [%0], [%1], 16, %2;"
                 :: "r"(dst), "l"(src), "r"(sz));
}

// ---------------- tf32 round-copy of weights ----------------------------------
__global__ void round_copy(const float4* __restrict__ src, float4* __restrict__ dst, int n4) {
    int i = blockIdx.x * blockDim.x + threadIdx.x;
    int stride = gridDim.x * blockDim.x;
    for (; i < n4; i += stride) {
        float4 v = src[i];
        v.x = tf32r(v.x); v.y = tf32r(v.y); v.z = tf32r(v.z); v.w = tf32r(v.w);
        dst[i] = v;
    }
}

// ---------------- layernorm (tf32-rounded output) ------------------------------
__global__ void ln_kernel(const float* __restrict__ x, const float* __restrict__ g,
                          const float* __restrict__ b, float* __restrict__ o) {
    __shared__ float xs[DIM];
    __shared__ float red[256];
    int t = blockIdx.x, tid = threadIdx.x;
    const float* xr = x + (size_t)t * DIM;
    float s = 0.f;
    for (int i = tid; i < DIM; i += 256) { float v = xr[i]; xs[i] = v; s += v; }
    red[tid] = s; __syncthreads();
    for (int st = 128; st > 0; st >>= 1) { if (tid < st) red[tid] += red[tid + st]; __syncthreads(); }
    float mu = red[0] * (1.f / DIM);
    __syncthreads();
    s = 0.f;
    for (int i = tid; i < DIM; i += 256) { float d = xs[i] - mu; s += d * d; }
    red[tid] = s; __syncthreads();
    for (int st = 128; st > 0; st >>= 1) { if (tid < st) red[tid] += red[tid + st]; __syncthreads(); }
    float inv = rsqrtf(red[0] * (1.f / DIM) + 1e-5f);
    float* orow = o + (size_t)t * DIM;
    for (int i = tid; i < DIM; i += 256)
        orow[i] = tf32r((xs[i] - mu) * inv * g[i] + b[i]);
}

// ---------------- C = A @ B^T (+bias)(+gelu)(+resid)(+round), grouped ---------
// Inputs A and Bw must already be tf32-rounded (reinterpret, no cvt).
template <bool GATHER, bool GELU, bool ROUND>
__global__ void __launch_bounds__(256)
gemm_tc(const float* __restrict__ A, const float* __restrict__ Bw,
        const float* __restrict__ bias, const float* __restrict__ resid,
        float* __restrict__ C, int M, int N, int K,
        const int* __restrict__ rows, const int* __restrict__ cnts,
        size_t sA, size_t sB, size_t sC) {
    extern __shared__ float sm[];
    float* SA = sm;
    float* SB = sm + NSTAGE * 128 * BKPAD;

    int z = blockIdx.z;
    A += (size_t)z * sA; Bw += (size_t)z * sB; C += (size_t)z * sC;
    if (bias) bias += (size_t)z * N;
    if (rows) rows += (size_t)z * TT;
    int Mz = cnts ? cnts[z] : M;
    if (Mz > M) Mz = M;
    int m0 = blockIdx.y * 128;
    if (m0 >= Mz) return;
    int n0 = blockIdx.x * 128;

    int tid = threadIdx.x;
    int r0 = tid >> 2, kq = tid & 3;

    const float *ga0, *ga1;
    int za0 = 16, za1 = 16;
    if (GATHER) {
        int i0 = m0 + r0, i1 = i0 + 64;
        int g0 = 0, g1 = 0;
        if (i0 < Mz) g0 = rows[i0]; else za0 = 0;
        if (i1 < Mz) g1 = rows[i1]; else za1 = 0;
        ga0 = A + (size_t)g0 * K + kq * 4;
        ga1 = A + (size_t)g1 * K + kq * 4;
    } else {
        ga0 = A + (size_t)(m0 + r0) * K + kq * 4;
        ga1 = ga0 + (size_t)64 * K;
    }
    const float* gb0 = Bw + (size_t)(n0 + r0) * K + kq * 4;
    const float* gb1 = gb0 + (size_t)64 * K;

    uint32_t sa_base = (uint32_t)__cvta_generic_to_shared(SA) + (r0 * BKPAD + kq * 4) * 4;
    uint32_t sb_base = (uint32_t)__cvta_generic_to_shared(SB) + (r0 * BKPAD + kq * 4) * 4;
    const uint32_t BUFB = 128 * BKPAD * 4;
    const uint32_t HALF = 64 * BKPAD * 4;

    int NIT = K >> 4;

    auto load_tile = [&](int it) {
        uint32_t off = (uint32_t)(it % NSTAGE) * BUFB;
        cp16(sa_base + off,        ga0 + it * 16, za0);
        cp16(sa_base + off + HALF, ga1 + it * 16, za1);
        cp16(sb_base + off,        gb0 + it * 16, 16);
        cp16(sb_base + off + HALF, gb1 + it * 16, 16);
        asm volatile("cp.async.commit_group;" ::: "memory");
    };

    int warp = tid >> 5, lane = tid & 31;
    int gid = lane >> 2, tg = lane & 3;
    int wm = (warp >> 1) * 32, wn = (warp & 1) * 64;

    float acc[2][8][4];
#pragma unroll
    for (int i = 0; i < 2; i++)
#pragma unroll
        for (int j = 0; j < 8; j++)
#pragma unroll
            for (int k = 0; k < 4; k++) acc[i][j][k] = 0.f;

    load_tile(0);
    if (NIT > 1) load_tile(1);

    for (int it = 0; it < NIT; ++it) {
        if (it + 1 < NIT) asm volatile("cp.async.wait_group 1;" ::: "memory");
        else              asm volatile("cp.async.wait_group 0;" ::: "memory");
        __syncthreads();
        if (it + 2 < NIT) load_tile(it + 2);

        const float* As = SA + (size_t)(it % NSTAGE) * 128 * BKPAD;
        const float* Bs = SB + (size_t)(it % NSTAGE) * 128 * BKPAD;

#pragma unroll
        for (int ks = 0; ks < 2; ks++) {
            int kk = ks * 8 + tg;
            uint32_t af[2][4], bf[8][2];
#pragma unroll
            for (int mi = 0; mi < 2; mi++) {
                int mr = wm + mi * 16 + gid;
                af[mi][0] = __float_as_uint(As[mr * BKPAD + kk]);
                af[mi][1] = __float_as_uint(As[(mr + 8) * BKPAD + kk]);
                af[mi][2] = __float_as_uint(As[mr * BKPAD + kk + 4]);
                af[mi][3] = __float_as_uint(As[(mr + 8) * BKPAD + kk + 4]);
            }
#pragma unroll
            for (int ni = 0; ni < 8; ni++) {
                int nr = wn + ni * 8 + gid;
                bf[ni][0] = __float_as_uint(Bs[nr * BKPAD + kk]);
                bf[ni][1] = __float_as_uint(Bs[nr * BKPAD + kk + 4]);
            }
#pragma unroll
            for (int mi = 0; mi < 2; mi++)
#pragma unroll
                for (int ni = 0; ni < 8; ni++)
                    mma_tf32(acc[mi][ni], af[mi], bf[ni]);
        }
    }

#pragma unroll
    for (int mi = 0; mi < 2; mi++) {
#pragma unroll
        for (int hh = 0; hh < 2; hh++) {
            int rr = m0 + wm + mi * 16 + gid + hh * 8;
            if (rr >= Mz) continue;
            float* crow = C + (size_t)rr * N;
            const float* rrow = resid ? resid + (size_t)rr * N : nullptr;
#pragma unroll
            for (int ni = 0; ni < 8; ni++) {
                int col = n0 + wn + ni * 8 + tg * 2;
                float v0 = acc[mi][ni][hh * 2 + 0];
                float v1 = acc[mi][ni][hh * 2 + 1];
                if (bias) { v0 += bias[col]; v1 += bias[col + 1]; }
                if (GELU) {
                    v0 = 0.5f * v0 * (1.f + erff(v0 * 0.70710678118654752f));
                    v1 = 0.5f * v1 * (1.f + erff(v1 * 0.70710678118654752f));
                }
                if (rrow) { v0 += rrow[col]; v1 += rrow[col + 1]; }
                if (ROUND) { v0 = tf32r(v0); v1 = tf32r(v1); }
                crow[col] = v0; crow[col + 1] = v1;
            }
        }
    }
}

// ---------------- tensor-core flash attention --------------------------------
// qkv input is pre-rounded tf32; only P fragments need cvt.
__global__ void __launch_bounds__(256)
attn_tc(const float* __restrict__ qkv, float* __restrict__ out) {
    extern __shared__ float sm[];
    float* SK    = sm;                      // [64][PADK]
    float* SV    = SK + 64 * PADK;          // [64][PADV]
    float* SP    = SV + 64 * PADV;          // [128][PADP]
    float* scorr = SP + 128 * PADP;         // [128]
    float* slsum = scorr + 128;             // [128]

    int bh = blockIdx.y;
    int b = bh / HEADS, h = bh % HEADS;
    int q0 = blockIdx.x * BQ;
    int tid = threadIdx.x;
    int warp = tid >> 5, lane = tid & 31;
    int gid = lane >> 2, tg = lane & 3;
    int wm = warp * 16;

    // stage Q (scaled by 1/8 — exact in tf32) into SP
    {
        int row = tid >> 1, cb = (tid & 1) * 32;
        const float* qp = qkv + (size_t)(b * NN + q0 + row) * (3 * DIM) + h * HD + cb;
        float* dst = SP + row * PADP + cb;
#pragma unroll
        for (int j = 0; j < 8; j++) {
            float4 v = *(const float4*)(qp + j * 4);
            v.x *= 0.125f; v.y *= 0.125f; v.z *= 0.125f; v.w *= 0.125f;
            *(float4*)(dst + j * 4) = v;
        }
    }
    __syncthreads();

    uint32_t qf[8][4];
#pragma unroll
    for (int ks = 0; ks < 8; ks++) {
        int kk = ks * 8 + tg;
        qf[ks][0] = __float_as_uint(SP[(wm + gid) * PADP + kk]);
        qf[ks][1] = __float_as_uint(SP[(wm + gid + 8) * PADP + kk]);
        qf[ks][2] = __float_as_uint(SP[(wm + gid) * PADP + kk + 4]);
        qf[ks][3] = __float_as_uint(SP[(wm + gid + 8) * PADP + kk + 4]);
    }

    float of[8][4];
#pragma unroll
    for (int i = 0; i < 8; i++)
#pragma unroll
        for (int j = 0; j < 4; j++) of[i][j] = 0.f;

    int srow = tid >> 1, scb = (tid & 1) * 32;
    float mrun = -1e30f, lrun = 0.f;

    for (int kt = 0; kt < NN / 64; kt++) {
        __syncthreads();
        {
            int row = tid >> 2, cb = (tid & 3) * 16;
            const float* kp = qkv + (size_t)(b * NN + kt * 64 + row) * (3 * DIM) + DIM + h * HD + cb;
            const float* vp = kp + DIM;
            float* kd = SK + row * PADK + cb;
            float* vd = SV + row * PADV + cb;
#pragma unroll
            for (int j = 0; j < 4; j++) {
                *(float4*)(kd + j * 4) = *(const float4*)(kp + j * 4);
                *(float4*)(vd + j * 4) = *(const float4*)(vp + j * 4);
            }
        }
        __syncthreads();

        float sf[8][4];
#pragma unroll
        for (int i = 0; i < 8; i++)
#pragma unroll
            for (int j = 0; j < 4; j++) sf[i][j] = 0.f;
#pragma unroll
        for (int ks = 0; ks < 8; ks++) {
            int kk = ks * 8 + tg;
            uint32_t bfr[8][2];
#pragma unroll
            for (int ni = 0; ni < 8; ni++) {
                const float* kr = SK + (ni * 8 + gid) * PADK;
                bfr[ni][0] = __float_as_uint(kr[kk]);
                bfr[ni][1] = __float_as_uint(kr[kk + 4]);
            }
#pragma unroll
            for (int ni = 0; ni < 8; ni++)
                mma_tf32(sf[ni], qf[ks], bfr[ni]);
        }
#pragma unroll
        for (int ni = 0; ni < 8; ni++) {
            float* p0 = SP + (wm + gid) * PADP + ni * 8 + 2 * tg;
            float* p1 = SP + (wm + gid + 8) * PADP + ni * 8 + 2 * tg;
            p0[0] = sf[ni][0]; p0[1] = sf[ni][1];
            p1[0] = sf[ni][2]; p1[1] = sf[ni][3];
        }
        __syncthreads();

        {
            float* rowp = SP + srow * PADP + scb;
            float rm = -1e30f;
#pragma unroll
            for (int j = 0; j < 32; j++) rm = fmaxf(rm, rowp[j]);
            rm = fmaxf(rm, __shfl_xor_sync(0xffffffffu, rm, 1));
            float mn = fmaxf(mrun, rm);
            float corr = __expf(mrun - mn);
            mrun = mn;
            float rs = 0.f;
#pragma unroll
            for (int j = 0; j < 32; j++) {
                float p = __expf(rowp[j] - mn);
                rowp[j] = p;
                rs += p;
            }
            rs += __shfl_xor_sync(0xffffffffu, rs, 1);
            lrun = lrun * corr + rs;
            if ((tid & 1) == 0) scorr[srow] = corr;
        }
        __syncthreads();

        float c0 = scorr[wm + gid], c1 = scorr[wm + gid + 8];
#pragma unroll
        for (int ni = 0; ni < 8; ni++) {
            of[ni][0] *= c0; of[ni][1] *= c0;
            of[ni][2] *= c1; of[ni][3] *= c1;
        }
#pragma unroll
        for (int ks = 0; ks < 8; ks++) {
            int kk = ks * 8 + tg;
            uint32_t af[4], bfr[8][2];
            af[0] = f2tf(SP[(wm + gid) * PADP + kk]);
            af[1] = f2tf(SP[(wm + gid + 8) * PADP + kk]);
            af[2] = f2tf(SP[(wm + gid) * PADP + kk + 4]);
            af[3] = f2tf(SP[(wm + gid + 8) * PADP + kk + 4]);
#pragma unroll
            for (int ni = 0; ni < 8; ni++) {
                bfr[ni][0] = __float_as_uint(SV[(ks * 8 + tg) * PADV + ni * 8 + gid]);
                bfr[ni][1] = __float_as_uint(SV[(ks * 8 + tg + 4) * PADV + ni * 8 + gid]);
            }
#pragma unroll
            for (int ni = 0; ni < 8; ni++)
                mma_tf32(of[ni], af, bfr[ni]);
        }
    }

    if ((tid & 1) == 0) slsum[srow] = lrun;
    __syncthreads();
    float i0 = 1.f / slsum[wm + gid];
    float i1 = 1.f / slsum[wm + gid + 8];
    float* o0 = out + (size_t)(b * NN + q0 + wm + gid) * DIM + h * HD;
    float* o1 = out + (size_t)(b * NN + q0 + wm + gid + 8) * DIM + h * HD;
#pragma unroll
    for (int ni = 0; ni < 8; ni++) {
        int col = ni * 8 + 2 * tg;
        o0[col] = tf32r(of[ni][0] * i0); o0[col + 1] = tf32r(of[ni][1] * i0);
        o1[col] = tf32r(of[ni][2] * i1); o1[col + 1] = tf32r(of[ni][3] * i1);
    }
}

// ---------------- gate ----------------------------------------------------------
__global__ void gate_kernel(const float* __restrict__ h2, const float* __restrict__ gw,
                            const float* __restrict__ gb, int* __restrict__ cnt,
                            int* __restrict__ ptok, int* __restrict__ smap,
                            float* __restrict__ sw) {
    __shared__ float lg[NE];
    int t = blockIdx.x, tid = threadIdx.x;
    int w = tid >> 5, lane = tid & 31;
    const float* hr = h2 + (size_t)t * DIM;
    float s = 0.f;
    const float* gr = gw + (size_t)w * DIM;
    for (int k = lane; k < DIM; k += 32) s += hr[k] * gr[k];
#pragma unroll
    for (int off = 16; off > 0; off >>= 1) s += __shfl_down_sync(0xffffffffu, s, off);
    if (lane == 0) lg[w] = s + gb[w];
    __syncthreads();
    if (tid == 0) {
        int b0 = 0; float v0 = lg[0];
        for (int e = 1; e < NE; e++) if (lg[e] > v0) { v0 = lg[e]; b0 = e; }
        int b1 = -1; float v1 = -1e30f;
        for (int e = 0; e < NE; e++) {
            if (e == b0) continue;
            if (lg[e] > v1) { v1 = lg[e]; b1 = e; }
        }
        float e1 = __expf(v1 - v0);
        float s0 = 1.f / (1.f + e1);
        float s1 = 1.f - s0;
        int p0 = atomicAdd(&cnt[b0], 1);
        int p1 = atomicAdd(&cnt[b1], 1);
        ptok[b0 * TT + p0] = t;
        ptok[b1 * TT + p1] = t;
        smap[t * 2 + 0] = b0 * TT + p0; sw[t * 2 + 0] = s0;
        smap[t * 2 + 1] = b1 * TT + p1; sw[t * 2 + 1] = s1;
    }
}

// ---------------- combine -------------------------------------------------------
__global__ void combine_kernel(const float* __restrict__ x1, const float* __restrict__ y,
                               const int* __restrict__ smap, const float* __restrict__ sw,
                               float* __restrict__ out) {
    int t = blockIdx.x, tid = threadIdx.x;
    int s0 = smap[t * 2 + 0], s1 = smap[t * 2 + 1];
    float w0 = sw[t * 2 + 0], w1 = sw[t * 2 + 1];
    const float* y0 = y + (size_t)s0 * DIM;
    const float* y1 = y + (size_t)s1 * DIM;
    const float* xr = x1 + (size_t)t * DIM;
    float* orow = out + (size_t)t * DIM;
    for (int c = tid; c < DIM; c += 256)
        orow[c] = xr[c] + w0 * y0[c] + w1 * y1[c];
}

// ---------------- host launcher -------------------------------------------------
extern "C" void kernel_launch(void* const* d_in, const int* in_sizes, int n_in,
                              void* d_out, int out_size) {
    const float* x      = (const float*)d_in[0];
    const float* ln1_g  = (const float*)d_in[1];
    const float* ln1_b  = (const float*)d_in[2];
    const float* qkv_w  = (const float*)d_in[3];
    const float* proj_w = (const float*)d_in[4];
    const float* proj_b = (const float*)d_in[5];
    const float* ln2_g  = (const float*)d_in[6];
    const float* ln2_b  = (const float*)d_in[7];
    const float* gate_w = (const float*)d_in[8];
    const float* gate_b = (const float*)d_in[9];
    const float* w1     = (const float*)d_in[10];
    const float* b1     = (const float*)d_in[11];
    const float* w2     = (const float*)d_in[12];
    const float* b2     = (const float*)d_in[13];
    float* out = (float*)d_out;

    float *h, *qkvb, *attn, *x1, *h1, *y, *sw, *wtf;
    int *cnt, *ptok, *smap;
    cudaGetSymbolAddress((void**)&h, g_h);
    cudaGetSymbolAddress((void**)&qkvb, g_qkv);
    cudaGetSymbolAddress((void**)&attn, g_attn);
    cudaGetSymbolAddress((void**)&x1, g_x1);
    cudaGetSymbolAddress((void**)&h1, g_h1);
    cudaGetSymbolAddress((void**)&y, g_y);
    cudaGetSymbolAddress((void**)&wtf, g_wtf);
    cudaGetSymbolAddress((void**)&cnt, g_cnt);
    cudaGetSymbolAddress((void**)&ptok, g_ptok);
    cudaGetSymbolAddress((void**)&smap, g_smap);
    cudaGetSymbolAddress((void**)&sw, g_sw);

    float* qkv_wt  = wtf + W_QKV_OFF;
    float* proj_wt = wtf + W_PROJ_OFF;
    float* w1t     = wtf + W_W1_OFF;
    float* w2t     = wtf + W_W2_OFF;

    const int ATTN_SMEM = (64 * PADK + 64 * PADV + 128 * PADP + 256) * 4;  // 71680
    const int GEMM_SMEM = NSTAGE * 128 * BKPAD * 4 * 2;                    // 61440
    cudaFuncSetAttribute(attn_tc, cudaFuncAttributeMaxDynamicSharedMemorySize, ATTN_SMEM);
    cudaFuncSetAttribute(gemm_tc<false, false, true>,  cudaFuncAttributeMaxDynamicSharedMemorySize, GEMM_SMEM);
    cudaFuncSetAttribute(gemm_tc<false, false, false>, cudaFuncAttributeMaxDynamicSharedMemorySize, GEMM_SMEM);
    cudaFuncSetAttribute(gemm_tc<true, true, true>,    cudaFuncAttributeMaxDynamicSharedMemorySize, GEMM_SMEM);

    // 0. zero counters + tf32-round all weights into scratch
    zero_cnt_kernel<<<1, 32>>>(cnt);
    round_copy<<<1024, 256>>>((const float4*)qkv_w,  (float4*)qkv_wt,  W_QKV_N / 4);
    round_copy<<<512, 256>>>((const float4*)proj_w, (float4*)proj_wt, W_PROJ_N / 4);
    round_copy<<<4096, 256>>>((const float4*)w1,     (float4*)w1t,     W_W1_N / 4);
    round_copy<<<4096, 256>>>((const float4*)w2,     (float4*)w2t,     W_W2_N / 4);

    // 1. LN1 (rounded output)
    ln_kernel<<<TT, 256>>>(x, ln1_g, ln1_b, h);

    // 2. qkv = h @ qkv_w^T (rounded output)
    gemm_tc<false, false, true><<<dim3(18, 32, 1), 256, GEMM_SMEM>>>(
        h, qkv_wt, nullptr, nullptr, qkvb, TT, 3 * DIM, DIM, nullptr, nullptr, 0, 0, 0);

    // 3. attention (rounded output)
    attn_tc<<<dim3(NN / BQ, BB * HEADS), 256, ATTN_SMEM>>>(qkvb, attn);

    // 4. x1 = x + attn @ proj_w^T + proj_b  (full fp32 out)
    gemm_tc<false, false, false><<<dim3(6, 32, 1), 256, GEMM_SMEM>>>(
        attn, proj_wt, proj_b, x, x1, TT, DIM, DIM, nullptr, nullptr, 0, 0, 0);

    // 5. LN2 (rounded output)
    ln_kernel<<<TT, 256>>>(x1, ln2_g, ln2_b, h);

    // 6. gate + bucketing
    gate_kernel<<<TT, 256>>>(h, gate_w, gate_b, cnt, ptok, smap, sw);

    // 7. MoE up-proj + GELU (rounded output)
    gemm_tc<true, true, true><<<dim3(HID / 128, TT / 128, NE), 256, GEMM_SMEM>>>(
        h, w1t, b1, nullptr, h1, TT, HID, DIM, ptok, cnt,
        0, (size_t)HID * DIM, (size_t)TT * HID);

    // 8. MoE down-proj (full fp32 out)
    gemm_tc<false, false, false><<<dim3(DIM / 128, TT / 128, NE), 256, GEMM_SMEM>>>(
        h1, w2t, b2, nullptr, y, TT, DIM, HID, nullptr, cnt,
        (size_t)TT * HID, (size_t)DIM * HID, (size_t)TT * DIM);

    // 9. combine + final residual
    combine_kernel<<<TT, 256>>>(x1, y, smap, sw, out);
}

// round 6
// speedup vs baseline: 4.3548x; 1.5531x over previous
#include <cuda_runtime.h>
#include <cuda_fp16.h>
#include <math.h>
#include <stdint.h>

#define BB 4
#define NN 1024
#define TT 4096
#define DIM 768
#define HEADS 12
#define HD 64
#define HID 3072
#define NE 8

#define NSTAGE 3
#define HKPAD 40   // halves per smem row: 32 data + 8 pad (80B rows, conflict-free)

// attention tiling (tf32 path, unchanged)
#define BQ 128
#define PADK 68
#define PADV 72
#define PADP 68

// half weight scratch offsets (in halves)
#define W_QKV_OFF 0
#define W_QKV_N   (3 * DIM * DIM)
#define W_PROJ_OFF (W_QKV_OFF + W_QKV_N)
#define W_PROJ_N  (DIM * DIM)
#define W_W1_OFF  (W_PROJ_OFF + W_PROJ_N)
#define W_W1_N    (NE * HID * DIM)
#define W_W2_OFF  (W_W1_OFF + W_W1_N)
#define W_W2_N    (NE * DIM * HID)

// ---------------- scratch (static device globals; no allocs) ----------------
__device__ __half g_h[(size_t)TT * DIM];
__device__ float  g_qkv[(size_t)TT * 3 * DIM];
__device__ __half g_attn[(size_t)TT * DIM];
__device__ float  g_x1[(size_t)TT * DIM];
__device__ __half g_h1[(size_t)NE * TT * HID];
__device__ float  g_y[(size_t)NE * TT * DIM];
__device__ __half g_wh[(size_t)W_W2_OFF + W_W2_N];
__device__ int    g_cnt[NE];
__device__ int    g_ptok[NE * TT];
__device__ int    g_smap[TT * 2];
__device__ float  g_sw[TT * 2];

__global__ void zero_cnt_kernel(int* c) {
    if (threadIdx.x < NE) c[threadIdx.x] = 0;
}

// ---------------- helpers ------------------------------------------------------
__device__ __forceinline__ uint32_t f2tf(float f) {
    uint32_t u;
    asm("cvt.rna.tf32.f32 %0, %1;" : "=r"(u) : "f"(f));
    return u;
}
__device__ __forceinline__ float tf32r(float f) {
    uint32_t u;
    asm("cvt.rna.tf32.f32 %0, %1;" : "=r"(u) : "f"(f));
    return __uint_as_float(u);
}

__device__ __forceinline__ void mma_tf32(float* c, const uint32_t* a, const uint32_t* b) {
    asm volatile(
        "mma.sync.aligned.m16n8k8.row.col.f32.tf32.tf32.f32 "
        "{%0,%1,%2,%3}, {%4,%5,%6,%7}, {%8,%9}, {%0,%1,%2,%3};"
        : "+f"(c[0]), "+f"(c[1]), "+f"(c[2]), "+f"(c[3])
        : "r"(a[0]), "r"(a[1]), "r"(a[2]), "r"(a[3]), "r"(b[0]), "r"(b[1]));
}

__device__ __forceinline__ void mma_f16(float* c, const uint32_t* a, const uint32_t* b) {
    asm volatile(
        "mma.sync.aligned.m16n8k16.row.col.f32.f16.f16.f32 "
        "{%0,%1,%2,%3}, {%4,%5,%6,%7}, {%8,%9}, {%0,%1,%2,%3};"
        : "+f"(c[0]), "+f"(c[1]), "+f"(c[2]), "+f"(c[3])
        : "r"(a[0]), "r"(a[1]), "r"(a[2]), "r"(a[3]), "r"(b[0]), "r"(b[1]));
}

__device__ __forceinline__ void cp16(uint32_t dst, const void* src, int sz) {
    asm volatile("cp.async.cg.shared.global [%0], [%1], 16, %2;"
                 :: "r"(dst), "l"(src), "r"(sz));
}

// ---------------- f32 -> f16 weight conversion ---------------------------------
__global__ void tohalf_kernel(const float4* __restrict__ src, __half2* __restrict__ dst, int n4) {
    int i = blockIdx.x * blockDim.x + threadIdx.x;
    int stride = gridDim.x * blockDim.x;
    for (; i < n4; i += stride) {
        float4 v = src[i];
        dst[2 * i + 0] = __floats2half2_rn(v.x, v.y);
        dst[2 * i + 1] = __floats2half2_rn(v.z, v.w);
    }
}

// ---------------- layernorm (fp16 output) --------------------------------------
__global__ void ln_kernel(const float* __restrict__ x, const float* __restrict__ g,
                          const float* __restrict__ b, __half* __restrict__ o) {
    __shared__ float xs[DIM];
    __shared__ float red[256];
    int t = blockIdx.x, tid = threadIdx.x;
    const float* xr = x + (size_t)t * DIM;
    float s = 0.f;
    for (int i = tid; i < DIM; i += 256) { float v = xr[i]; xs[i] = v; s += v; }
    red[tid] = s; __syncthreads();
    for (int st = 128; st > 0; st >>= 1) { if (tid < st) red[tid] += red[tid + st]; __syncthreads(); }
    float mu = red[0] * (1.f / DIM);
    __syncthreads();
    s = 0.f;
    for (int i = tid; i < DIM; i += 256) { float d = xs[i] - mu; s += d * d; }
    red[tid] = s; __syncthreads();
    for (int st = 128; st > 0; st >>= 1) { if (tid < st) red[tid] += red[tid + st]; __syncthreads(); }
    float inv = rsqrtf(red[0] * (1.f / DIM) + 1e-5f);
    __half* orow = o + (size_t)t * DIM;
    for (int i = tid; i < DIM; i += 256)
        orow[i] = __float2half_rn((xs[i] - mu) * inv * g[i] + b[i]);
}

// ---------------- fp16 tensor-core GEMM: C = A @ B^T ---------------------------
// A: half [M,K] (optionally gathered); B: half [N,K]; accum fp32.
// OUTMODE: 0 = float, 1 = float tf32-rounded, 2 = half
template <bool GATHER, bool GELU, int OUTMODE>
__global__ void __launch_bounds__(256)
gemm_hc(const __half* __restrict__ A, const __half* __restrict__ Bw,
        const float* __restrict__ bias, const float* __restrict__ resid,
        void* __restrict__ Cout, int M, int N, int K,
        const int* __restrict__ rows, const int* __restrict__ cnts,
        size_t sA, size_t sB, size_t sC) {
    extern __shared__ __half smh[];
    __half* SA = smh;                            // [NSTAGE][128*HKPAD]
    __half* SB = smh + (size_t)NSTAGE * 128 * HKPAD;

    int z = blockIdx.z;
    A += (size_t)z * sA; Bw += (size_t)z * sB;
    if (bias) bias += (size_t)z * N;
    if (rows) rows += (size_t)z * TT;
    int Mz = cnts ? cnts[z] : M;
    if (Mz > M) Mz = M;
    int m0 = blockIdx.y * 128;
    if (m0 >= Mz) return;
    int n0 = blockIdx.x * 128;

    int tid = threadIdx.x;
    int r0 = tid >> 2, kq = tid & 3;   // row within 64-row half, 16B chunk (8 halves)

    const __half *ga0, *ga1;
    int za0 = 16, za1 = 16;
    if (GATHER) {
        int i0 = m0 + r0, i1 = i0 + 64;
        int g0 = 0, g1 = 0;
        if (i0 < Mz) g0 = rows[i0]; else za0 = 0;
        if (i1 < Mz) g1 = rows[i1]; else za1 = 0;
        ga0 = A + (size_t)g0 * K + kq * 8;
        ga1 = A + (size_t)g1 * K + kq * 8;
    } else {
        ga0 = A + (size_t)(m0 + r0) * K + kq * 8;
        ga1 = ga0 + (size_t)64 * K;
    }
    const __half* gb0 = Bw + (size_t)(n0 + r0) * K + kq * 8;
    const __half* gb1 = gb0 + (size_t)64 * K;

    uint32_t sa_base = (uint32_t)__cvta_generic_to_shared(SA) + (r0 * HKPAD + kq * 8) * 2;
    uint32_t sb_base = (uint32_t)__cvta_generic_to_shared(SB) + (r0 * HKPAD + kq * 8) * 2;
    const uint32_t BUFB = 128 * HKPAD * 2;
    const uint32_t HALF = 64 * HKPAD * 2;

    int NIT = K >> 5;   // BK = 32

    auto load_tile = [&](int it) {
        uint32_t off = (uint32_t)(it % NSTAGE) * BUFB;
        cp16(sa_base + off,        ga0 + it * 32, za0);
        cp16(sa_base + off + HALF, ga1 + it * 32, za1);
        cp16(sb_base + off,        gb0 + it * 32, 16);
        cp16(sb_base + off + HALF, gb1 + it * 32, 16);
        asm volatile("cp.async.commit_group;" ::: "memory");
    };

    int warp = tid >> 5, lane = tid & 31;
    int gid = lane >> 2, tg = lane & 3;
    int wm = (warp >> 1) * 32, wn = (warp & 1) * 64;

    float acc[2][8][4];
#pragma unroll
    for (int i = 0; i < 2; i++)
#pragma unroll
        for (int j = 0; j < 8; j++)
#pragma unroll
            for (int k = 0; k < 4; k++) acc[i][j][k] = 0.f;

    load_tile(0);
    if (NIT > 1) load_tile(1);

    for (int it = 0; it < NIT; ++it) {
        if (it + 1 < NIT) asm volatile("cp.async.wait_group 1;" ::: "memory");
        else              asm volatile("cp.async.wait_group 0;" ::: "memory");
        __syncthreads();
        if (it + 2 < NIT) load_tile(it + 2);

        // 32-bit views of current stage (HKPAD/2 = 20 uint32 per row)
        const uint32_t* As32 = (const uint32_t*)(SA + (size_t)(it % NSTAGE) * 128 * HKPAD);
        const uint32_t* Bs32 = (const uint32_t*)(SB + (size_t)(it % NSTAGE) * 128 * HKPAD);

#pragma unroll
        for (int ks = 0; ks < 2; ks++) {      // two k16 slices of BK=32
            int kb = ks * 8 + tg;             // uint32 index of k-pair base
            uint32_t af[2][4], bf[8][2];
#pragma unroll
            for (int mi = 0; mi < 2; mi++) {
                int mr = wm + mi * 16 + gid;
                af[mi][0] = As32[mr * 20 + kb];
                af[mi][1] = As32[(mr + 8) * 20 + kb];
                af[mi][2] = As32[mr * 20 + kb + 4];
                af[mi][3] = As32[(mr + 8) * 20 + kb + 4];
            }
#pragma unroll
            for (int ni = 0; ni < 8; ni++) {
                int nr = wn + ni * 8 + gid;
                bf[ni][0] = Bs32[nr * 20 + kb];
                bf[ni][1] = Bs32[nr * 20 + kb + 4];
            }
#pragma unroll
            for (int mi = 0; mi < 2; mi++)
#pragma unroll
                for (int ni = 0; ni < 8; ni++)
                    mma_f16(acc[mi][ni], af[mi], bf[ni]);
        }
    }

    // ---- epilogue ----
#pragma unroll
    for (int mi = 0; mi < 2; mi++) {
#pragma unroll
        for (int hh = 0; hh < 2; hh++) {
            int rr = m0 + wm + mi * 16 + gid + hh * 8;
            if (rr >= Mz) continue;
            const float* rrow = resid ? resid + (size_t)rr * N : nullptr;
#pragma unroll
            for (int ni = 0; ni < 8; ni++) {
                int col = n0 + wn + ni * 8 + tg * 2;
                float v0 = acc[mi][ni][hh * 2 + 0];
                float v1 = acc[mi][ni][hh * 2 + 1];
                if (bias) { v0 += bias[col]; v1 += bias[col + 1]; }
                if (GELU) {
                    v0 = 0.5f * v0 * (1.f + erff(v0 * 0.70710678118654752f));
                    v1 = 0.5f * v1 * (1.f + erff(v1 * 0.70710678118654752f));
                }
                if (rrow) { v0 += rrow[col]; v1 += rrow[col + 1]; }
                if (OUTMODE == 2) {
                    __half2* crow = (__half2*)((__half*)Cout + (size_t)z * sC + (size_t)rr * N + col);
                    *crow = __floats2half2_rn(v0, v1);
                } else {
                    float* crow = (float*)Cout + (size_t)z * sC + (size_t)rr * N + col;
                    if (OUTMODE == 1) { v0 = tf32r(v0); v1 = tf32r(v1); }
                    crow[0] = v0; crow[1] = v1;
                }
            }
        }
    }
}

// ---------------- tensor-core flash attention (tf32, fp32 qkv in, fp16 out) ----
__global__ void __launch_bounds__(256)
attn_tc(const float* __restrict__ qkv, __half* __restrict__ out) {
    extern __shared__ float sm[];
    float* SK    = sm;                      // [64][PADK]
    float* SV    = SK + 64 * PADK;          // [64][PADV]
    float* SP    = SV + 64 * PADV;          // [128][PADP]
    float* scorr = SP + 128 * PADP;         // [128]
    float* slsum = scorr + 128;             // [128]

    int bh = blockIdx.y;
    int b = bh / HEADS, h = bh % HEADS;
    int q0 = blockIdx.x * BQ;
    int tid = threadIdx.x;
    int warp = tid >> 5, lane = tid & 31;
    int gid = lane >> 2, tg = lane & 3;
    int wm = warp * 16;

    {
        int row = tid >> 1, cb = (tid & 1) * 32;
        const float* qp = qkv + (size_t)(b * NN + q0 + row) * (3 * DIM) + h * HD + cb;
        float* dst = SP + row * PADP + cb;
#pragma unroll
        for (int j = 0; j < 8; j++) {
            float4 v = *(const float4*)(qp + j * 4);
            v.x *= 0.125f; v.y *= 0.125f; v.z *= 0.125f; v.w *= 0.125f;
            *(float4*)(dst + j * 4) = v;
        }
    }
    __syncthreads();

    uint32_t qf[8][4];
#pragma unroll
    for (int ks = 0; ks < 8; ks++) {
        int kk = ks * 8 + tg;
        qf[ks][0] = __float_as_uint(SP[(wm + gid) * PADP + kk]);
        qf[ks][1] = __float_as_uint(SP[(wm + gid + 8) * PADP + kk]);
        qf[ks][2] = __float_as_uint(SP[(wm + gid) * PADP + kk + 4]);
        qf[ks][3] = __float_as_uint(SP[(wm + gid + 8) * PADP + kk + 4]);
    }

    float of[8][4];
#pragma unroll
    for (int i = 0; i < 8; i++)
#pragma unroll
        for (int j = 0; j < 4; j++) of[i][j] = 0.f;

    int srow = tid >> 1, scb = (tid & 1) * 32;
    float mrun = -1e30f, lrun = 0.f;

    for (int kt = 0; kt < NN / 64; kt++) {
        __syncthreads();
        {
            int row = tid >> 2, cb = (tid & 3) * 16;
            const float* kp = qkv + (size_t)(b * NN + kt * 64 + row) * (3 * DIM) + DIM + h * HD + cb;
            const float* vp = kp + DIM;
            float* kd = SK + row * PADK + cb;
            float* vd = SV + row * PADV + cb;
#pragma unroll
            for (int j = 0; j < 4; j++) {
                *(float4*)(kd + j * 4) = *(const float4*)(kp + j * 4);
                *(float4*)(vd + j * 4) = *(const float4*)(vp + j * 4);
            }
        }
        __syncthreads();

        float sf[8][4];
#pragma unroll
        for (int i = 0; i < 8; i++)
#pragma unroll
            for (int j = 0; j < 4; j++) sf[i][j] = 0.f;
#pragma unroll
        for (int ks = 0; ks < 8; ks++) {
            int kk = ks * 8 + tg;
            uint32_t bfr[8][2];
#pragma unroll
            for (int ni = 0; ni < 8; ni++) {
                const float* kr = SK + (ni * 8 + gid) * PADK;
                bfr[ni][0] = __float_as_uint(kr[kk]);
                bfr[ni][1] = __float_as_uint(kr[kk + 4]);
            }
#pragma unroll
            for (int ni = 0; ni < 8; ni++)
                mma_tf32(sf[ni], qf[ks], bfr[ni]);
        }
#pragma unroll
        for (int ni = 0; ni < 8; ni++) {
            float* p0 = SP + (wm + gid) * PADP + ni * 8 + 2 * tg;
            float* p1 = SP + (wm + gid + 8) * PADP + ni * 8 + 2 * tg;
            p0[0] = sf[ni][0]; p0[1] = sf[ni][1];
            p1[0] = sf[ni][2]; p1[1] = sf[ni][3];
        }
        __syncthreads();

        {
            float* rowp = SP + srow * PADP + scb;
            float rm = -1e30f;
#pragma unroll
            for (int j = 0; j < 32; j++) rm = fmaxf(rm, rowp[j]);
            rm = fmaxf(rm, __shfl_xor_sync(0xffffffffu, rm, 1));
            float mn = fmaxf(mrun, rm);
            float corr = __expf(mrun - mn);
            mrun = mn;
            float rs = 0.f;
#pragma unroll
            for (int j = 0; j < 32; j++) {
                float p = __expf(rowp[j] - mn);
                rowp[j] = p;
                rs += p;
            }
            rs += __shfl_xor_sync(0xffffffffu, rs, 1);
            lrun = lrun * corr + rs;
            if ((tid & 1) == 0) scorr[srow] = corr;
        }
        __syncthreads();

        float c0 = scorr[wm + gid], c1 = scorr[wm + gid + 8];
#pragma unroll
        for (int ni = 0; ni < 8; ni++) {
            of[ni][0] *= c0; of[ni][1] *= c0;
            of[ni][2] *= c1; of[ni][3] *= c1;
        }
#pragma unroll
        for (int ks = 0; ks < 8; ks++) {
            int kk = ks * 8 + tg;
            uint32_t af[4], bfr[8][2];
            af[0] = f2tf(SP[(wm + gid) * PADP + kk]);
            af[1] = f2tf(SP[(wm + gid + 8) * PADP + kk]);
            af[2] = f2tf(SP[(wm + gid) * PADP + kk + 4]);
            af[3] = f2tf(SP[(wm + gid + 8) * PADP + kk + 4]);
#pragma unroll
            for (int ni = 0; ni < 8; ni++) {
                bfr[ni][0] = __float_as_uint(SV[(ks * 8 + tg) * PADV + ni * 8 + gid]);
                bfr[ni][1] = __float_as_uint(SV[(ks * 8 + tg + 4) * PADV + ni * 8 + gid]);
            }
#pragma unroll
            for (int ni = 0; ni < 8; ni++)
                mma_tf32(of[ni], af, bfr[ni]);
        }
    }

    if ((tid & 1) == 0) slsum[srow] = lrun;
    __syncthreads();
    float i0 = 1.f / slsum[wm + gid];
    float i1 = 1.f / slsum[wm + gid + 8];
    __half* o0 = out + (size_t)(b * NN + q0 + wm + gid) * DIM + h * HD;
    __half* o1 = out + (size_t)(b * NN + q0 + wm + gid + 8) * DIM + h * HD;
#pragma unroll
    for (int ni = 0; ni < 8; ni++) {
        int col = ni * 8 + 2 * tg;
        *(__half2*)(o0 + col) = __floats2half2_rn(of[ni][0] * i0, of[ni][1] * i0);
        *(__half2*)(o1 + col) = __floats2half2_rn(of[ni][2] * i1, of[ni][3] * i1);
    }
}

// ---------------- fused LN2 + gate (fp32 accurate logits) ----------------------
__global__ void gate_ln_kernel(const float* __restrict__ x1, const float* __restrict__ g,
                               const float* __restrict__ bparm, const float* __restrict__ gw,
                               const float* __restrict__ gb, int* __restrict__ cnt,
                               int* __restrict__ ptok, int* __restrict__ smap,
                               float* __restrict__ sw) {
    __shared__ float xs[DIM];
    __shared__ float red[256];
    __shared__ float lg[NE];
    int t = blockIdx.x, tid = threadIdx.x;
    const float* xr = x1 + (size_t)t * DIM;
    float s = 0.f;
    for (int i = tid; i < DIM; i += 256) { float v = xr[i]; xs[i] = v; s += v; }
    red[tid] = s; __syncthreads();
    for (int st = 128; st > 0; st >>= 1) { if (tid < st) red[tid] += red[tid + st]; __syncthreads(); }
    float mu = red[0] * (1.f / DIM);
    __syncthreads();
    s = 0.f;
    for (int i = tid; i < DIM; i += 256) { float d = xs[i] - mu; s += d * d; }
    red[tid] = s; __syncthreads();
    for (int st = 128; st > 0; st >>= 1) { if (tid < st) red[tid] += red[tid + st]; __syncthreads(); }
    float inv = rsqrtf(red[0] * (1.f / DIM) + 1e-5f);
    __syncthreads();

    int w = tid >> 5, lane = tid & 31;
    float acc = 0.f;
    const float* gr = gw + (size_t)w * DIM;
    for (int k = lane; k < DIM; k += 32) {
        float hv = (xs[k] - mu) * inv * g[k] + bparm[k];
        acc += hv * gr[k];
    }
#pragma unroll
    for (int off = 16; off > 0; off >>= 1) acc += __shfl_down_sync(0xffffffffu, acc, off);
    if (lane == 0) lg[w] = acc + gb[w];
    __syncthreads();
    if (tid == 0) {
        int b0 = 0; float v0 = lg[0];
        for (int e = 1; e < NE; e++) if (lg[e] > v0) { v0 = lg[e]; b0 = e; }
        int b1 = -1; float v1 = -1e30f;
        for (int e = 0; e < NE; e++) {
            if (e == b0) continue;
            if (lg[e] > v1) { v1 = lg[e]; b1 = e; }
        }
        float e1 = __expf(v1 - v0);
        float s0 = 1.f / (1.f + e1);
        float s1 = 1.f - s0;
        int p0 = atomicAdd(&cnt[b0], 1);
        int p1 = atomicAdd(&cnt[b1], 1);
        ptok[b0 * TT + p0] = t;
        ptok[b1 * TT + p1] = t;
        smap[t * 2 + 0] = b0 * TT + p0; sw[t * 2 + 0] = s0;
        smap[t * 2 + 1] = b1 * TT + p1; sw[t * 2 + 1] = s1;
    }
}

// ---------------- combine -------------------------------------------------------
__global__ void combine_kernel(const float* __restrict__ x1, const float* __restrict__ y,
                               const int* __restrict__ smap, const float* __restrict__ sw,
                               float* __restrict__ out) {
    int t = blockIdx.x, tid = threadIdx.x;
    int s0 = smap[t * 2 + 0], s1 = smap[t * 2 + 1];
    float w0 = sw[t * 2 + 0], w1 = sw[t * 2 + 1];
    const float* y0 = y + (size_t)s0 * DIM;
    const float* y1 = y + (size_t)s1 * DIM;
    const float* xr = x1 + (size_t)t * DIM;
    float* orow = out + (size_t)t * DIM;
    for (int c = tid; c < DIM; c += 256)
        orow[c] = xr[c] + w0 * y0[c] + w1 * y1[c];
}

// ---------------- host launcher -------------------------------------------------
extern "C" void kernel_launch(void* const* d_in, const int* in_sizes, int n_in,
                              void* d_out, int out_size) {
    const float* x      = (const float*)d_in[0];
    const float* ln1_g  = (const float*)d_in[1];
    const float* ln1_b  = (const float*)d_in[2];
    const float* qkv_w  = (const float*)d_in[3];
    const float* proj_w = (const float*)d_in[4];
    const float* proj_b = (const float*)d_in[5];
    const float* ln2_g  = (const float*)d_in[6];
    const float* ln2_b  = (const float*)d_in[7];
    const float* gate_w = (const float*)d_in[8];
    const float* gate_b = (const float*)d_in[9];
    const float* w1     = (const float*)d_in[10];
    const float* b1     = (const float*)d_in[11];
    const float* w2     = (const float*)d_in[12];
    const float* b2     = (const float*)d_in[13];
    float* out = (float*)d_out;

    __half *h, *attn, *h1, *wh;
    float *qkvb, *x1, *y, *sw;
    int *cnt, *ptok, *smap;
    cudaGetSymbolAddress((void**)&h, g_h);
    cudaGetSymbolAddress((void**)&qkvb, g_qkv);
    cudaGetSymbolAddress((void**)&attn, g_attn);
    cudaGetSymbolAddress((void**)&x1, g_x1);
    cudaGetSymbolAddress((void**)&h1, g_h1);
    cudaGetSymbolAddress((void**)&y, g_y);
    cudaGetSymbolAddress((void**)&wh, g_wh);
    cudaGetSymbolAddress((void**)&cnt, g_cnt);
    cudaGetSymbolAddress((void**)&ptok, g_ptok);
    cudaGetSymbolAddress((void**)&smap, g_smap);
    cudaGetSymbolAddress((void**)&sw, g_sw);

    __half* qkv_wh = wh + W_QKV_OFF;
    __half* proj_wh = wh + W_PROJ_OFF;
    __half* w1h = wh + W_W1_OFF;
    __half* w2h = wh + W_W2_OFF;

    const int ATTN_SMEM = (64 * PADK + 64 * PADV + 128 * PADP + 256) * 4;   // 71680
    const int GEMM_SMEM = NSTAGE * 128 * HKPAD * 2 * 2;                     // 61440
    cudaFuncSetAttribute(attn_tc, cudaFuncAttributeMaxDynamicSharedMemorySize, ATTN_SMEM);
    cudaFuncSetAttribute(gemm_hc<false, false, 1>, cudaFuncAttributeMaxDynamicSharedMemorySize, GEMM_SMEM);
    cudaFuncSetAttribute(gemm_hc<false, false, 0>, cudaFuncAttributeMaxDynamicSharedMemorySize, GEMM_SMEM);
    cudaFuncSetAttribute(gemm_hc<true, true, 2>,   cudaFuncAttributeMaxDynamicSharedMemorySize, GEMM_SMEM);

    // 0. zero counters + fp16 weight conversion
    zero_cnt_kernel<<<1, 32>>>(cnt);
    tohalf_kernel<<<1024, 256>>>((const float4*)qkv_w,  (__half2*)qkv_wh,  W_QKV_N / 4);
    tohalf_kernel<<<512, 256>>>((const float4*)proj_w, (__half2*)proj_wh, W_PROJ_N / 4);
    tohalf_kernel<<<4096, 256>>>((const float4*)w1,     (__half2*)w1h,     W_W1_N / 4);
    tohalf_kernel<<<4096, 256>>>((const float4*)w2,     (__half2*)w2h,     W_W2_N / 4);

    // 1. LN1 -> h (fp16)
    ln_kernel<<<TT, 256>>>(x, ln1_g, ln1_b, h);

    // 2. qkv = h @ qkv_w^T  (fp32 out, tf32-rounded for attention)
    gemm_hc<false, false, 1><<<dim3(18, 32, 1), 256, GEMM_SMEM>>>(
        h, qkv_wh, nullptr, nullptr, qkvb, TT, 3 * DIM, DIM, nullptr, nullptr, 0, 0, 0);

    // 3. attention (tf32 internals, fp16 out)
    attn_tc<<<dim3(NN / BQ, BB * HEADS), 256, ATTN_SMEM>>>(qkvb, attn);

    // 4. x1 = x + attn @ proj_w^T + proj_b  (fp32 out)
    gemm_hc<false, false, 0><<<dim3(6, 32, 1), 256, GEMM_SMEM>>>(
        attn, proj_wh, proj_b, x, x1, TT, DIM, DIM, nullptr, nullptr, 0, 0, 0);

    // 5. LN2 -> h (fp16, GEMM input only)
    ln_kernel<<<TT, 256>>>(x1, ln2_g, ln2_b, h);

    // 6. fused LN2+gate from fp32 x1 (accurate top-2 selection)
    gate_ln_kernel<<<TT, 256>>>(x1, ln2_g, ln2_b, gate_w, gate_b, cnt, ptok, smap, sw);

    // 7. MoE up-proj + GELU (gathered, fp16 out)
    gemm_hc<true, true, 2><<<dim3(HID / 128, TT / 128, NE), 256, GEMM_SMEM>>>(
        h, w1h, b1, nullptr, h1, TT, HID, DIM, ptok, cnt,
        0, (size_t)HID * DIM, (size_t)TT * HID);

    // 8. MoE down-proj (fp32 out)
    gemm_hc<false, false, 0><<<dim3(6, 32, NE), 256, GEMM_SMEM>>>(
        h1, w2h, b2, nullptr, y, TT, DIM, HID, nullptr, cnt,
        (size_t)TT * HID, (size_t)DIM * HID, (size_t)TT * DIM);

    // 9. combine + final residual
    combine_kernel<<<TT, 256>>>(x1, y, smap, sw, out);
}

// round 8
// speedup vs baseline: 4.8473x; 1.1131x over previous
#include <cuda_runtime.h>
#include <cuda_fp16.h>
#include <math.h>
#include <stdint.h>

#define BB 4
#define NN 1024
#define TT 4096
#define DIM 768
#define HEADS 12
#define HD 64
#define HID 3072
#define NE 8

#define NSTAGE 3
#define HKPAD 40   // gemm smem pitch in halves (32 data + 8 pad)

// attention: pitch 72 halves (36 u32) for 64-half rows -> conflict-free frags
#define APITCH 72
#define AP32 36

// half weight scratch offsets (in halves)
#define W_QKV_OFF 0
#define W_QKV_N   (3 * DIM * DIM)
#define W_PROJ_OFF (W_QKV_OFF + W_QKV_N)
#define W_PROJ_N  (DIM * DIM)
#define W_W1_OFF  (W_PROJ_OFF + W_PROJ_N)
#define W_W1_N    (NE * HID * DIM)
#define W_W2_OFF  (W_W1_OFF + W_W1_N)
#define W_W2_N    (NE * DIM * HID)

// ---------------- scratch (static device globals; no allocs) ----------------
__device__ __half g_h[(size_t)TT * DIM];
__device__ __half g_qkv[(size_t)TT * 3 * DIM];
__device__ __half g_attn[(size_t)TT * DIM];
__device__ float  g_x1[(size_t)TT * DIM];
__device__ __half g_h1[(size_t)NE * TT * HID];
__device__ float  g_y[(size_t)NE * TT * DIM];
__device__ __half g_wh[(size_t)W_W2_OFF + W_W2_N];
__device__ int    g_cnt[NE];
__device__ int    g_ptok[NE * TT];
__device__ int    g_smap[TT * 2];
__device__ float  g_sw[TT * 2];

__global__ void zero_cnt_kernel(int* c) {
    if (threadIdx.x < NE) c[threadIdx.x] = 0;
}

// ---------------- helpers ------------------------------------------------------
__device__ __forceinline__ uint32_t h2u(__half2 v) {
    union { __half2 h; uint32_t u; } cvt;
    cvt.h = v;
    return cvt.u;
}

__device__ __forceinline__ uint32_t pack2(float a, float b) {
    return h2u(__floats2half2_rn(a, b));
}

__device__ __forceinline__ void mma_f16(float* c, const uint32_t* a, const uint32_t* b) {
    asm volatile(
        "mma.sync.aligned.m16n8k16.row.col.f32.f16.f16.f32 "
        "{%0,%1,%2,%3}, {%4,%5,%6,%7}, {%8,%9}, {%0,%1,%2,%3};"
        : "+f"(c[0]), "+f"(c[1]), "+f"(c[2]), "+f"(c[3])
        : "r"(a[0]), "r"(a[1]), "r"(a[2]), "r"(a[3]), "r"(b[0]), "r"(b[1]));
}

__device__ __forceinline__ void cp16(uint32_t dst, const void* src, int sz) {
    asm volatile("cp.async.cg.shared.global [%0], [%1], 16, %2;"
                 :: "r"(dst), "l"(src), "r"(sz));
}

// ---------------- f32 -> f16 weight conversion ---------------------------------
__global__ void tohalf_kernel(const float4* __restrict__ src, __half2* __restrict__ dst, int n4) {
    int i = blockIdx.x * blockDim.x + threadIdx.x;
    int stride = gridDim.x * blockDim.x;
    for (; i < n4; i += stride) {
        float4 v = src[i];
        dst[2 * i + 0] = __floats2half2_rn(v.x, v.y);
        dst[2 * i + 1] = __floats2half2_rn(v.z, v.w);
    }
}

// ---------------- layernorm (fp16 output) --------------------------------------
__global__ void ln_kernel(const float* __restrict__ x, const float* __restrict__ g,
                          const float* __restrict__ b, __half* __restrict__ o) {
    __shared__ float xs[DIM];
    __shared__ float red[256];
    int t = blockIdx.x, tid = threadIdx.x;
    const float* xr = x + (size_t)t * DIM;
    float s = 0.f;
    for (int i = tid; i < DIM; i += 256) { float v = xr[i]; xs[i] = v; s += v; }
    red[tid] = s; __syncthreads();
    for (int st = 128; st > 0; st >>= 1) { if (tid < st) red[tid] += red[tid + st]; __syncthreads(); }
    float mu = red[0] * (1.f / DIM);
    __syncthreads();
    s = 0.f;
    for (int i = tid; i < DIM; i += 256) { float d = xs[i] - mu; s += d * d; }
    red[tid] = s; __syncthreads();
    for (int st = 128; st > 0; st >>= 1) { if (tid < st) red[tid] += red[tid + st]; __syncthreads(); }
    float inv = rsqrtf(red[0] * (1.f / DIM) + 1e-5f);
    __half* orow = o + (size_t)t * DIM;
    for (int i = tid; i < DIM; i += 256)
        orow[i] = __float2half_rn((xs[i] - mu) * inv * g[i] + b[i]);
}

// ---------------- fp16 tensor-core GEMM: C = A @ B^T ---------------------------
// OUTMODE: 0 = float, 2 = half
template <bool GATHER, bool GELU, int OUTMODE>
__global__ void __launch_bounds__(256)
gemm_hc(const __half* __restrict__ A, const __half* __restrict__ Bw,
        const float* __restrict__ bias, const float* __restrict__ resid,
        void* __restrict__ Cout, int M, int N, int K,
        const int* __restrict__ rows, const int* __restrict__ cnts,
        size_t sA, size_t sB, size_t sC) {
    extern __shared__ __half smh[];
    __half* SA = smh;
    __half* SB = smh + (size_t)NSTAGE * 128 * HKPAD;

    int z = blockIdx.z;
    A += (size_t)z * sA; Bw += (size_t)z * sB;
    if (bias) bias += (size_t)z * N;
    if (rows) rows += (size_t)z * TT;
    int Mz = cnts ? cnts[z] : M;
    if (Mz > M) Mz = M;
    int m0 = blockIdx.y * 128;
    if (m0 >= Mz) return;
    int n0 = blockIdx.x * 128;

    int tid = threadIdx.x;
    int r0 = tid >> 2, kq = tid & 3;

    const __half *ga0, *ga1;
    int za0 = 16, za1 = 16;
    if (GATHER) {
        int i0 = m0 + r0, i1 = i0 + 64;
        int g0 = 0, g1 = 0;
        if (i0 < Mz) g0 = rows[i0]; else za0 = 0;
        if (i1 < Mz) g1 = rows[i1]; else za1 = 0;
        ga0 = A + (size_t)g0 * K + kq * 8;
        ga1 = A + (size_t)g1 * K + kq * 8;
    } else {
        ga0 = A + (size_t)(m0 + r0) * K + kq * 8;
        ga1 = ga0 + (size_t)64 * K;
    }
    const __half* gb0 = Bw + (size_t)(n0 + r0) * K + kq * 8;
    const __half* gb1 = gb0 + (size_t)64 * K;

    uint32_t sa_base = (uint32_t)__cvta_generic_to_shared(SA) + (r0 * HKPAD + kq * 8) * 2;
    uint32_t sb_base = (uint32_t)__cvta_generic_to_shared(SB) + (r0 * HKPAD + kq * 8) * 2;
    const uint32_t BUFB = 128 * HKPAD * 2;
    const uint32_t HALF = 64 * HKPAD * 2;

    int NIT = K >> 5;

    auto load_tile = [&](int it) {
        uint32_t off = (uint32_t)(it % NSTAGE) * BUFB;
        cp16(sa_base + off,        ga0 + it * 32, za0);
        cp16(sa_base + off + HALF, ga1 + it * 32, za1);
        cp16(sb_base + off,        gb0 + it * 32, 16);
        cp16(sb_base + off + HALF, gb1 + it * 32, 16);
        asm volatile("cp.async.commit_group;" ::: "memory");
    };

    int warp = tid >> 5, lane = tid & 31;
    int gid = lane >> 2, tg = lane & 3;
    int wm = (warp >> 1) * 32, wn = (warp & 1) * 64;

    float acc[2][8][4];
#pragma unroll
    for (int i = 0; i < 2; i++)
#pragma unroll
        for (int j = 0; j < 8; j++)
#pragma unroll
            for (int k = 0; k < 4; k++) acc[i][j][k] = 0.f;

    load_tile(0);
    if (NIT > 1) load_tile(1);

    for (int it = 0; it < NIT; ++it) {
        if (it + 1 < NIT) asm volatile("cp.async.wait_group 1;" ::: "memory");
        else              asm volatile("cp.async.wait_group 0;" ::: "memory");
        __syncthreads();
        if (it + 2 < NIT) load_tile(it + 2);

        const uint32_t* As32 = (const uint32_t*)(SA + (size_t)(it % NSTAGE) * 128 * HKPAD);
        const uint32_t* Bs32 = (const uint32_t*)(SB + (size_t)(it % NSTAGE) * 128 * HKPAD);

#pragma unroll
        for (int ks = 0; ks < 2; ks++) {
            int kb = ks * 8 + tg;
            uint32_t af[2][4], bf[8][2];
#pragma unroll
            for (int mi = 0; mi < 2; mi++) {
                int mr = wm + mi * 16 + gid;
                af[mi][0] = As32[mr * 20 + kb];
                af[mi][1] = As32[(mr + 8) * 20 + kb];
                af[mi][2] = As32[mr * 20 + kb + 4];
                af[mi][3] = As32[(mr + 8) * 20 + kb + 4];
            }
#pragma unroll
            for (int ni = 0; ni < 8; ni++) {
                int nr = wn + ni * 8 + gid;
                bf[ni][0] = Bs32[nr * 20 + kb];
                bf[ni][1] = Bs32[nr * 20 + kb + 4];
            }
#pragma unroll
            for (int mi = 0; mi < 2; mi++)
#pragma unroll
                for (int ni = 0; ni < 8; ni++)
                    mma_f16(acc[mi][ni], af[mi], bf[ni]);
        }
    }

#pragma unroll
    for (int mi = 0; mi < 2; mi++) {
#pragma unroll
        for (int hh = 0; hh < 2; hh++) {
            int rr = m0 + wm + mi * 16 + gid + hh * 8;
            if (rr >= Mz) continue;
            const float* rrow = resid ? resid + (size_t)rr * N : nullptr;
#pragma unroll
            for (int ni = 0; ni < 8; ni++) {
                int col = n0 + wn + ni * 8 + tg * 2;
                float v0 = acc[mi][ni][hh * 2 + 0];
                float v1 = acc[mi][ni][hh * 2 + 1];
                if (bias) { v0 += bias[col]; v1 += bias[col + 1]; }
                if (GELU) {
                    v0 = 0.5f * v0 * (1.f + erff(v0 * 0.70710678118654752f));
                    v1 = 0.5f * v1 * (1.f + erff(v1 * 0.70710678118654752f));
                }
                if (rrow) { v0 += rrow[col]; v1 += rrow[col + 1]; }
                if (OUTMODE == 2) {
                    __half2* crow = (__half2*)((__half*)Cout + (size_t)z * sC + (size_t)rr * N + col);
                    *crow = __floats2half2_rn(v0, v1);
                } else {
                    float* crow = (float*)Cout + (size_t)z * sC + (size_t)rr * N + col;
                    crow[0] = v0; crow[1] = v1;
                }
            }
        }
    }
}

// ---------------- fp16 flash attention, register-resident softmax --------------
// 128 q-rows/block, 8 warps, warp w owns rows [16w,16w+16). 64-key tiles.
__global__ void __launch_bounds__(256)
attn_h(const __half* __restrict__ qkv, __half* __restrict__ out) {
    __shared__ __half SQ[128 * APITCH];
    __shared__ __half SK[64 * APITCH];
    __shared__ __half SVt[64 * APITCH];   // transposed: [dim][key]

    int bh = blockIdx.y;
    int b = bh / HEADS, h = bh % HEADS;
    int q0 = blockIdx.x * 128;
    int tid = threadIdx.x;
    int warp = tid >> 5, lane = tid & 31;
    int gid = lane >> 2, tg = lane & 3;
    int wm = warp * 16;

    // ---- stage Q (x 0.125, exact in fp16) ----
    {
        int row = tid >> 1, cb = (tid & 1) * 32;
        const __half* qp = qkv + (size_t)(b * NN + q0 + row) * (3 * DIM) + h * HD + cb;
        __half* dst = SQ + row * APITCH + cb;
        const __half2 sc = __floats2half2_rn(0.125f, 0.125f);
#pragma unroll
        for (int j = 0; j < 4; j++) {
            __half2 v0 = *(const __half2*)(qp + j * 8 + 0);
            __half2 v1 = *(const __half2*)(qp + j * 8 + 2);
            __half2 v2 = *(const __half2*)(qp + j * 8 + 4);
            __half2 v3 = *(const __half2*)(qp + j * 8 + 6);
            *(__half2*)(dst + j * 8 + 0) = __hmul2(v0, sc);
            *(__half2*)(dst + j * 8 + 2) = __hmul2(v1, sc);
            *(__half2*)(dst + j * 8 + 4) = __hmul2(v2, sc);
            *(__half2*)(dst + j * 8 + 6) = __hmul2(v3, sc);
        }
    }
    __syncthreads();

    // ---- Q fragments (4 k16 slices over HD=64) ----
    uint32_t qf[4][4];
    const uint32_t* SQ32 = (const uint32_t*)SQ;
#pragma unroll
    for (int s = 0; s < 4; s++) {
        qf[s][0] = SQ32[(wm + gid) * AP32 + 8 * s + tg];
        qf[s][1] = SQ32[(wm + gid + 8) * AP32 + 8 * s + tg];
        qf[s][2] = SQ32[(wm + gid) * AP32 + 8 * s + 4 + tg];
        qf[s][3] = SQ32[(wm + gid + 8) * AP32 + 8 * s + 4 + tg];
    }

    float of[8][4];
#pragma unroll
    for (int i = 0; i < 8; i++)
#pragma unroll
        for (int j = 0; j < 4; j++) of[i][j] = 0.f;
    float m0r = -1e30f, m1r = -1e30f, l0r = 0.f, l1r = 0.f;

    const uint32_t* SK32 = (const uint32_t*)SK;
    const uint32_t* SV32 = (const uint32_t*)SVt;

    for (int kt = 0; kt < NN / 64; kt++) {
        __syncthreads();   // previous-tile readers done
        // ---- load K (row-major) and V (transposed) ----
        {
            int row = tid >> 2, cb = (tid & 3) * 16;
            const __half* kp = qkv + (size_t)(b * NN + kt * 64 + row) * (3 * DIM) + DIM + h * HD + cb;
            const __half* vp = kp + DIM;
            *(uint4*)(SK + row * APITCH + cb)     = *(const uint4*)(kp);
            *(uint4*)(SK + row * APITCH + cb + 8) = *(const uint4*)(kp + 8);
#pragma unroll
            for (int j = 0; j < 16; j++)
                SVt[(cb + j) * APITCH + row] = vp[j];
        }
        __syncthreads();

        // ---- S = Qs @ K^T ----
        float sf[8][4];
#pragma unroll
        for (int i = 0; i < 8; i++)
#pragma unroll
            for (int j = 0; j < 4; j++) sf[i][j] = 0.f;
#pragma unroll
        for (int s = 0; s < 4; s++) {
            int kb = 8 * s + tg;
            uint32_t bf[8][2];
#pragma unroll
            for (int ni = 0; ni < 8; ni++) {
                bf[ni][0] = SK32[(ni * 8 + gid) * AP32 + kb];
                bf[ni][1] = SK32[(ni * 8 + gid) * AP32 + kb + 4];
            }
#pragma unroll
            for (int ni = 0; ni < 8; ni++)
                mma_f16(sf[ni], qf[s], bf[ni]);
        }

        // ---- register-resident online softmax ----
        // row gid: sf[ni][0..1]; row gid+8: sf[ni][2..3]
        float tm0 = -1e30f, tm1 = -1e30f;
#pragma unroll
        for (int ni = 0; ni < 8; ni++) {
            tm0 = fmaxf(tm0, fmaxf(sf[ni][0], sf[ni][1]));
            tm1 = fmaxf(tm1, fmaxf(sf[ni][2], sf[ni][3]));
        }
        tm0 = fmaxf(tm0, __shfl_xor_sync(0xffffffffu, tm0, 1));
        tm0 = fmaxf(tm0, __shfl_xor_sync(0xffffffffu, tm0, 2));
        tm1 = fmaxf(tm1, __shfl_xor_sync(0xffffffffu, tm1, 1));
        tm1 = fmaxf(tm1, __shfl_xor_sync(0xffffffffu, tm1, 2));
        float mn0 = fmaxf(m0r, tm0), mn1 = fmaxf(m1r, tm1);
        float c0 = __expf(m0r - mn0), c1 = __expf(m1r - mn1);
        m0r = mn0; m1r = mn1;
        float rs0 = 0.f, rs1 = 0.f;
#pragma unroll
        for (int ni = 0; ni < 8; ni++) {
            sf[ni][0] = __expf(sf[ni][0] - mn0);
            sf[ni][1] = __expf(sf[ni][1] - mn0);
            sf[ni][2] = __expf(sf[ni][2] - mn1);
            sf[ni][3] = __expf(sf[ni][3] - mn1);
            rs0 += sf[ni][0] + sf[ni][1];
            rs1 += sf[ni][2] + sf[ni][3];
        }
        rs0 += __shfl_xor_sync(0xffffffffu, rs0, 1);
        rs0 += __shfl_xor_sync(0xffffffffu, rs0, 2);
        rs1 += __shfl_xor_sync(0xffffffffu, rs1, 1);
        rs1 += __shfl_xor_sync(0xffffffffu, rs1, 2);
        l0r = l0r * c0 + rs0;
        l1r = l1r * c1 + rs1;
#pragma unroll
        for (int ni = 0; ni < 8; ni++) {
            of[ni][0] *= c0; of[ni][1] *= c0;
            of[ni][2] *= c1; of[ni][3] *= c1;
        }

        // ---- O += P @ V : P frags = repacked S accumulators ----
#pragma unroll
        for (int s = 0; s < 4; s++) {
            uint32_t pf[4];
            pf[0] = pack2(sf[2 * s][0], sf[2 * s][1]);
            pf[1] = pack2(sf[2 * s][2], sf[2 * s][3]);
            pf[2] = pack2(sf[2 * s + 1][0], sf[2 * s + 1][1]);
            pf[3] = pack2(sf[2 * s + 1][2], sf[2 * s + 1][3]);
            int kb = 8 * s + tg;
            uint32_t bf[8][2];
#pragma unroll
            for (int ni = 0; ni < 8; ni++) {
                bf[ni][0] = SV32[(ni * 8 + gid) * AP32 + kb];
                bf[ni][1] = SV32[(ni * 8 + gid) * AP32 + kb + 4];
            }
#pragma unroll
            for (int ni = 0; ni < 8; ni++)
                mma_f16(of[ni], pf, bf[ni]);
        }
    }

    // ---- finalize ----
    float i0 = 1.f / l0r, i1 = 1.f / l1r;
    __half* o0 = out + (size_t)(b * NN + q0 + wm + gid) * DIM + h * HD;
    __half* o1 = out + (size_t)(b * NN + q0 + wm + gid + 8) * DIM + h * HD;
#pragma unroll
    for (int ni = 0; ni < 8; ni++) {
        int col = ni * 8 + 2 * tg;
        *(__half2*)(o0 + col) = __floats2half2_rn(of[ni][0] * i0, of[ni][1] * i0);
        *(__half2*)(o1 + col) = __floats2half2_rn(of[ni][2] * i1, of[ni][3] * i1);
    }
}

// ---------------- fused LN2 + gate (fp32 logits) -------------------------------
__global__ void gate_ln_kernel(const float* __restrict__ x1, const float* __restrict__ g,
                               const float* __restrict__ bparm, const float* __restrict__ gw,
                               const float* __restrict__ gb, int* __restrict__ cnt,
                               int* __restrict__ ptok, int* __restrict__ smap,
                               float* __restrict__ sw) {
    __shared__ float xs[DIM];
    __shared__ float red[256];
    __shared__ float lg[NE];
    int t = blockIdx.x, tid = threadIdx.x;
    const float* xr = x1 + (size_t)t * DIM;
    float s = 0.f;
    for (int i = tid; i < DIM; i += 256) { float v = xr[i]; xs[i] = v; s += v; }
    red[tid] = s; __syncthreads();
    for (int st = 128; st > 0; st >>= 1) { if (tid < st) red[tid] += red[tid + st]; __syncthreads(); }
    float mu = red[0] * (1.f / DIM);
    __syncthreads();
    s = 0.f;
    for (int i = tid; i < DIM; i += 256) { float d = xs[i] - mu; s += d * d; }
    red[tid] = s; __syncthreads();
    for (int st = 128; st > 0; st >>= 1) { if (tid < st) red[tid] += red[tid + st]; __syncthreads(); }
    float inv = rsqrtf(red[0] * (1.f / DIM) + 1e-5f);
    __syncthreads();

    int w = tid >> 5, lane = tid & 31;
    float acc = 0.f;
    const float* gr = gw + (size_t)w * DIM;
    for (int k = lane; k < DIM; k += 32) {
        float hv = (xs[k] - mu) * inv * g[k] + bparm[k];
        acc += hv * gr[k];
    }
#pragma unroll
    for (int off = 16; off > 0; off >>= 1) acc += __shfl_down_sync(0xffffffffu, acc, off);
    if (lane == 0) lg[w] = acc + gb[w];
    __syncthreads();
    if (tid == 0) {
        int b0 = 0; float v0 = lg[0];
        for (int e = 1; e < NE; e++) if (lg[e] > v0) { v0 = lg[e]; b0 = e; }
        int b1 = -1; float v1 = -1e30f;
        for (int e = 0; e < NE; e++) {
            if (e == b0) continue;
            if (lg[e] > v1) { v1 = lg[e]; b1 = e; }
        }
        float e1 = __expf(v1 - v0);
        float s0 = 1.f / (1.f + e1);
        float s1 = 1.f - s0;
        int p0 = atomicAdd(&cnt[b0], 1);
        int p1 = atomicAdd(&cnt[b1], 1);
        ptok[b0 * TT + p0] = t;
        ptok[b1 * TT + p1] = t;
        smap[t * 2 + 0] = b0 * TT + p0; sw[t * 2 + 0] = s0;
        smap[t * 2 + 1] = b1 * TT + p1; sw[t * 2 + 1] = s1;
    }
}

// ---------------- combine -------------------------------------------------------
__global__ void combine_kernel(const float* __restrict__ x1, const float* __restrict__ y,
                               const int* __restrict__ smap, const float* __restrict__ sw,
                               float* __restrict__ out) {
    int t = blockIdx.x, tid = threadIdx.x;
    int s0 = smap[t * 2 + 0], s1 = smap[t * 2 + 1];
    float w0 = sw[t * 2 + 0], w1 = sw[t * 2 + 1];
    const float* y0 = y + (size_t)s0 * DIM;
    const float* y1 = y + (size_t)s1 * DIM;
    const float* xr = x1 + (size_t)t * DIM;
    float* orow = out + (size_t)t * DIM;
    for (int c = tid; c < DIM; c += 256)
        orow[c] = xr[c] + w0 * y0[c] + w1 * y1[c];
}

// ---------------- host launcher -------------------------------------------------
extern "C" void kernel_launch(void* const* d_in, const int* in_sizes, int n_in,
                              void* d_out, int out_size) {
    const float* x      = (const float*)d_in[0];
    const float* ln1_g  = (const float*)d_in[1];
    const float* ln1_b  = (const float*)d_in[2];
    const float* qkv_w  = (const float*)d_in[3];
    const float* proj_w = (const float*)d_in[4];
    const float* proj_b = (const float*)d_in[5];
    const float* ln2_g  = (const float*)d_in[6];
    const float* ln2_b  = (const float*)d_in[7];
    const float* gate_w = (const float*)d_in[8];
    const float* gate_b = (const float*)d_in[9];
    const float* w1     = (const float*)d_in[10];
    const float* b1     = (const float*)d_in[11];
    const float* w2     = (const float*)d_in[12];
    const float* b2     = (const float*)d_in[13];
    float* out = (float*)d_out;

    __half *h, *qkvb, *attn, *h1, *wh;
    float *x1, *y, *sw;
    int *cnt, *ptok, *smap;
    cudaGetSymbolAddress((void**)&h, g_h);
    cudaGetSymbolAddress((void**)&qkvb, g_qkv);
    cudaGetSymbolAddress((void**)&attn, g_attn);
    cudaGetSymbolAddress((void**)&x1, g_x1);
    cudaGetSymbolAddress((void**)&h1, g_h1);
    cudaGetSymbolAddress((void**)&y, g_y);
    cudaGetSymbolAddress((void**)&wh, g_wh);
    cudaGetSymbolAddress((void**)&cnt, g_cnt);
    cudaGetSymbolAddress((void**)&ptok, g_ptok);
    cudaGetSymbolAddress((void**)&smap, g_smap);
    cudaGetSymbolAddress((void**)&sw, g_sw);

    __half* qkv_wh = wh + W_QKV_OFF;
    __half* proj_wh = wh + W_PROJ_OFF;
    __half* w1h = wh + W_W1_OFF;
    __half* w2h = wh + W_W2_OFF;

    const int GEMM_SMEM = NSTAGE * 128 * HKPAD * 2 * 2;   // 61440
    cudaFuncSetAttribute(gemm_hc<false, false, 2>, cudaFuncAttributeMaxDynamicSharedMemorySize, GEMM_SMEM);
    cudaFuncSetAttribute(gemm_hc<false, false, 0>, cudaFuncAttributeMaxDynamicSharedMemorySize, GEMM_SMEM);
    cudaFuncSetAttribute(gemm_hc<true, true, 2>,   cudaFuncAttributeMaxDynamicSharedMemorySize, GEMM_SMEM);

    // 0. zero counters + fp16 weight conversion
    zero_cnt_kernel<<<1, 32>>>(cnt);
    tohalf_kernel<<<1024, 256>>>((const float4*)qkv_w,  (__half2*)qkv_wh,  W_QKV_N / 4);
    tohalf_kernel<<<512, 256>>>((const float4*)proj_w, (__half2*)proj_wh, W_PROJ_N / 4);
    tohalf_kernel<<<4096, 256>>>((const float4*)w1,     (__half2*)w1h,     W_W1_N / 4);
    tohalf_kernel<<<4096, 256>>>((const float4*)w2,     (__half2*)w2h,     W_W2_N / 4);

    // 1. LN1 -> h (fp16)
    ln_kernel<<<TT, 256>>>(x, ln1_g, ln1_b, h);

    // 2. qkv = h @ qkv_w^T  (fp16 out)
    gemm_hc<false, false, 2><<<dim3(18, 32, 1), 256, GEMM_SMEM>>>(
        h, qkv_wh, nullptr, nullptr, qkvb, TT, 3 * DIM, DIM, nullptr, nullptr, 0, 0, 0);

    // 3. attention (fp16, register softmax)
    attn_h<<<dim3(NN / 128, BB * HEADS), 256>>>(qkvb, attn);

    // 4. x1 = x + attn @ proj_w^T + proj_b  (fp32 out)
    gemm_hc<false, false, 0><<<dim3(6, 32, 1), 256, GEMM_SMEM>>>(
        attn, proj_wh, proj_b, x, x1, TT, DIM, DIM, nullptr, nullptr, 0, 0, 0);

    // 5. LN2 -> h (fp16, GEMM input only)
    ln_kernel<<<TT, 256>>>(x1, ln2_g, ln2_b, h);

    // 6. fused LN2+gate from fp32 x1
    gate_ln_kernel<<<TT, 256>>>(x1, ln2_g, ln2_b, gate_w, gate_b, cnt, ptok, smap, sw);

    // 7. MoE up-proj + GELU (gathered, fp16 out)
    gemm_hc<true, true, 2><<<dim3(HID / 128, TT / 128, NE), 256, GEMM_SMEM>>>(
        h, w1h, b1, nullptr, h1, TT, HID, DIM, ptok, cnt,
        0, (size_t)HID * DIM, (size_t)TT * HID);

    // 8. MoE down-proj (fp32 out)
    gemm_hc<false, false, 0><<<dim3(6, 32, NE), 256, GEMM_SMEM>>>(
        h1, w2h, b2, nullptr, y, TT, DIM, HID, nullptr, cnt,
        (size_t)TT * HID, (size_t)DIM * HID, (size_t)TT * DIM);

    // 9. combine + final residual
    combine_kernel<<<TT, 256>>>(x1, y, smap, sw, out);
}

// round 9
// speedup vs baseline: 5.7487x; 1.1860x over previous
#include <cuda_runtime.h>
#include <cuda_fp16.h>
#include <math.h>
#include <stdint.h>

#define BB 4
#define NN 1024
#define TT 4096
#define DIM 768
#define HEADS 12
#define HD 64
#define HID 3072
#define NE 8

#define NSTAGE 3
#define HKPAD 40   // gemm smem pitch in halves (80B rows; ldmatrix conflict-free)

#define APITCH 72  // attention pitch in halves (144B rows; ldmatrix conflict-free)

// half weight scratch offsets (in halves)
#define W_QKV_OFF 0
#define W_QKV_N   (3 * DIM * DIM)
#define W_PROJ_OFF (W_QKV_OFF + W_QKV_N)
#define W_PROJ_N  (DIM * DIM)
#define W_W1_OFF  (W_PROJ_OFF + W_PROJ_N)
#define W_W1_N    (NE * HID * DIM)
#define W_W2_OFF  (W_W1_OFF + W_W1_N)
#define W_W2_N    (NE * DIM * HID)

// ---------------- scratch (static device globals; no allocs) ----------------
__device__ __half g_h[(size_t)TT * DIM];
__device__ __half g_qkv[(size_t)TT * 3 * DIM];
__device__ __half g_attn[(size_t)TT * DIM];
__device__ float  g_x1[(size_t)TT * DIM];
__device__ __half g_h1[(size_t)NE * TT * HID];
__device__ float  g_y[(size_t)NE * TT * DIM];
__device__ __half g_wh[(size_t)W_W2_OFF + W_W2_N];
__device__ int    g_cnt[NE];
__device__ int    g_ptok[NE * TT];
__device__ int    g_smap[TT * 2];
__device__ float  g_sw[TT * 2];

__global__ void zero_cnt_kernel(int* c) {
    if (threadIdx.x < NE) c[threadIdx.x] = 0;
}

// ---------------- helpers ------------------------------------------------------
__device__ __forceinline__ uint32_t h2u(__half2 v) {
    union { __half2 h; uint32_t u; } cvt;
    cvt.h = v;
    return cvt.u;
}
__device__ __forceinline__ uint32_t pack2(float a, float b) {
    return h2u(__floats2half2_rn(a, b));
}

__device__ __forceinline__ void mma_f16(float* c, const uint32_t* a, const uint32_t* b) {
    asm volatile(
        "mma.sync.aligned.m16n8k16.row.col.f32.f16.f16.f32 "
        "{%0,%1,%2,%3}, {%4,%5,%6,%7}, {%8,%9}, {%0,%1,%2,%3};"
        : "+f"(c[0]), "+f"(c[1]), "+f"(c[2]), "+f"(c[3])
        : "r"(a[0]), "r"(a[1]), "r"(a[2]), "r"(a[3]), "r"(b[0]), "r"(b[1]));
}

__device__ __forceinline__ void ldsm4(uint32_t* r, uint32_t addr) {
    asm volatile("ldmatrix.sync.aligned.m8n8.x4.shared.b16 {%0,%1,%2,%3}, [%4];"
                 : "=r"(r[0]), "=r"(r[1]), "=r"(r[2]), "=r"(r[3]) : "r"(addr));
}
__device__ __forceinline__ void ldsm4t(uint32_t* r, uint32_t addr) {
    asm volatile("ldmatrix.sync.aligned.m8n8.x4.trans.shared.b16 {%0,%1,%2,%3}, [%4];"
                 : "=r"(r[0]), "=r"(r[1]), "=r"(r[2]), "=r"(r[3]) : "r"(addr));
}

__device__ __forceinline__ void cp16(uint32_t dst, const void* src, int sz) {
    asm volatile("cp.async.cg.shared.global [%0], [%1], 16, %2;"
                 :: "r"(dst), "l"(src), "r"(sz));
}

// ---------------- f32 -> f16 weight conversion ---------------------------------
__global__ void tohalf_kernel(const float4* __restrict__ src, __half2* __restrict__ dst, int n4) {
    int i = blockIdx.x * blockDim.x + threadIdx.x;
    int stride = gridDim.x * blockDim.x;
    for (; i < n4; i += stride) {
        float4 v = src[i];
        dst[2 * i + 0] = __floats2half2_rn(v.x, v.y);
        dst[2 * i + 1] = __floats2half2_rn(v.z, v.w);
    }
}

// ---------------- layernorm (fp16 output) --------------------------------------
__global__ void ln_kernel(const float* __restrict__ x, const float* __restrict__ g,
                          const float* __restrict__ b, __half* __restrict__ o) {
    __shared__ float xs[DIM];
    __shared__ float red[256];
    int t = blockIdx.x, tid = threadIdx.x;
    const float* xr = x + (size_t)t * DIM;
    float s = 0.f;
    for (int i = tid; i < DIM; i += 256) { float v = xr[i]; xs[i] = v; s += v; }
    red[tid] = s; __syncthreads();
    for (int st = 128; st > 0; st >>= 1) { if (tid < st) red[tid] += red[tid + st]; __syncthreads(); }
    float mu = red[0] * (1.f / DIM);
    __syncthreads();
    s = 0.f;
    for (int i = tid; i < DIM; i += 256) { float d = xs[i] - mu; s += d * d; }
    red[tid] = s; __syncthreads();
    for (int st = 128; st > 0; st >>= 1) { if (tid < st) red[tid] += red[tid + st]; __syncthreads(); }
    float inv = rsqrtf(red[0] * (1.f / DIM) + 1e-5f);
    __half* orow = o + (size_t)t * DIM;
    for (int i = tid; i < DIM; i += 256)
        orow[i] = __float2half_rn((xs[i] - mu) * inv * g[i] + b[i]);
}

// ---------------- fp16 tensor-core GEMM (ldmatrix): C = A @ B^T ----------------
// OUTMODE: 0 = float, 2 = half
template <bool GATHER, bool GELU, int OUTMODE>
__global__ void __launch_bounds__(256)
gemm_hc(const __half* __restrict__ A, const __half* __restrict__ Bw,
        const float* __restrict__ bias, const float* __restrict__ resid,
        void* __restrict__ Cout, int M, int N, int K,
        const int* __restrict__ rows, const int* __restrict__ cnts,
        size_t sA, size_t sB, size_t sC) {
    extern __shared__ __half smh[];
    __half* SA = smh;
    __half* SB = smh + (size_t)NSTAGE * 128 * HKPAD;

    int z = blockIdx.z;
    A += (size_t)z * sA; Bw += (size_t)z * sB;
    if (bias) bias += (size_t)z * N;
    if (rows) rows += (size_t)z * TT;
    int Mz = cnts ? cnts[z] : M;
    if (Mz > M) Mz = M;
    int m0 = blockIdx.y * 128;
    if (m0 >= Mz) return;
    int n0 = blockIdx.x * 128;

    int tid = threadIdx.x;
    int r0 = tid >> 2, kq = tid & 3;

    const __half *ga0, *ga1;
    int za0 = 16, za1 = 16;
    if (GATHER) {
        int i0 = m0 + r0, i1 = i0 + 64;
        int g0 = 0, g1 = 0;
        if (i0 < Mz) g0 = rows[i0]; else za0 = 0;
        if (i1 < Mz) g1 = rows[i1]; else za1 = 0;
        ga0 = A + (size_t)g0 * K + kq * 8;
        ga1 = A + (size_t)g1 * K + kq * 8;
    } else {
        ga0 = A + (size_t)(m0 + r0) * K + kq * 8;
        ga1 = ga0 + (size_t)64 * K;
    }
    const __half* gb0 = Bw + (size_t)(n0 + r0) * K + kq * 8;
    const __half* gb1 = gb0 + (size_t)64 * K;

    uint32_t sa_smem = (uint32_t)__cvta_generic_to_shared(SA);
    uint32_t sb_smem = (uint32_t)__cvta_generic_to_shared(SB);
    uint32_t sa_base = sa_smem + (r0 * HKPAD + kq * 8) * 2;
    uint32_t sb_base = sb_smem + (r0 * HKPAD + kq * 8) * 2;
    const uint32_t BUFB = 128 * HKPAD * 2;
    const uint32_t HALF = 64 * HKPAD * 2;

    int NIT = K >> 5;

    auto load_tile = [&](int it) {
        uint32_t off = (uint32_t)(it % NSTAGE) * BUFB;
        cp16(sa_base + off,        ga0 + it * 32, za0);
        cp16(sa_base + off + HALF, ga1 + it * 32, za1);
        cp16(sb_base + off,        gb0 + it * 32, 16);
        cp16(sb_base + off + HALF, gb1 + it * 32, 16);
        asm volatile("cp.async.commit_group;" ::: "memory");
    };

    int warp = tid >> 5, lane = tid & 31;
    int gid = lane >> 2, tg = lane & 3;
    int wm = (warp >> 1) * 32, wn = (warp & 1) * 64;

    // ldmatrix lane-address offsets
    int a_r = lane & 15;                 // A row within 16-tile
    int a_k = (lane & 16) ? 8 : 0;       // A k-half offset
    int b_r = (lane & 7) + ((lane & 16) ? 8 : 0);  // B row within 16-pair
    int b_k = (lane & 8) ? 8 : 0;        // B k-half offset

    float acc[2][8][4];
#pragma unroll
    for (int i = 0; i < 2; i++)
#pragma unroll
        for (int j = 0; j < 8; j++)
#pragma unroll
            for (int k = 0; k < 4; k++) acc[i][j][k] = 0.f;

    load_tile(0);
    if (NIT > 1) load_tile(1);

    for (int it = 0; it < NIT; ++it) {
        if (it + 1 < NIT) asm volatile("cp.async.wait_group 1;" ::: "memory");
        else              asm volatile("cp.async.wait_group 0;" ::: "memory");
        __syncthreads();
        if (it + 2 < NIT) load_tile(it + 2);

        uint32_t st = (uint32_t)(it % NSTAGE) * BUFB;
        uint32_t sa_st = sa_smem + st;
        uint32_t sb_st = sb_smem + st;

#pragma unroll
        for (int ks = 0; ks < 2; ks++) {
            uint32_t af[2][4], bf[8][2];
#pragma unroll
            for (int mi = 0; mi < 2; mi++)
                ldsm4(af[mi], sa_st + ((wm + mi * 16 + a_r) * HKPAD + ks * 16 + a_k) * 2);
#pragma unroll
            for (int np = 0; np < 4; np++) {
                uint32_t bq[4];
                ldsm4(bq, sb_st + ((wn + np * 16 + b_r) * HKPAD + ks * 16 + b_k) * 2);
                bf[2 * np][0] = bq[0]; bf[2 * np][1] = bq[1];
                bf[2 * np + 1][0] = bq[2]; bf[2 * np + 1][1] = bq[3];
            }
#pragma unroll
            for (int mi = 0; mi < 2; mi++)
#pragma unroll
                for (int ni = 0; ni < 8; ni++)
                    mma_f16(acc[mi][ni], af[mi], bf[ni]);
        }
    }

#pragma unroll
    for (int mi = 0; mi < 2; mi++) {
#pragma unroll
        for (int hh = 0; hh < 2; hh++) {
            int rr = m0 + wm + mi * 16 + gid + hh * 8;
            if (rr >= Mz) continue;
            const float* rrow = resid ? resid + (size_t)rr * N : nullptr;
#pragma unroll
            for (int ni = 0; ni < 8; ni++) {
                int col = n0 + wn + ni * 8 + tg * 2;
                float v0 = acc[mi][ni][hh * 2 + 0];
                float v1 = acc[mi][ni][hh * 2 + 1];
                if (bias) { v0 += bias[col]; v1 += bias[col + 1]; }
                if (GELU) {
                    v0 = 0.5f * v0 * (1.f + erff(v0 * 0.70710678118654752f));
                    v1 = 0.5f * v1 * (1.f + erff(v1 * 0.70710678118654752f));
                }
                if (rrow) { v0 += rrow[col]; v1 += rrow[col + 1]; }
                if (OUTMODE == 2) {
                    __half2* crow = (__half2*)((__half*)Cout + (size_t)z * sC + (size_t)rr * N + col);
                    *crow = __floats2half2_rn(v0, v1);
                } else {
                    float* crow = (float*)Cout + (size_t)z * sC + (size_t)rr * N + col;
                    crow[0] = v0; crow[1] = v1;
                }
            }
        }
    }
}

// ---------------- fp16 flash attention (ldmatrix, register softmax) ------------
// 128 q-rows/block, 8 warps, warp w owns rows [16w,16w+16). 64-key tiles.
__global__ void __launch_bounds__(256)
attn_h(const __half* __restrict__ qkv, __half* __restrict__ out) {
    __shared__ __half SQ[128 * APITCH];
    __shared__ __half SK[64 * APITCH];
    __shared__ __half SV[64 * APITCH];   // row-major [key][dim]; trans-ldmatrix for PV

    int bh = blockIdx.y;
    int b = bh / HEADS, h = bh % HEADS;
    int q0 = blockIdx.x * 128;
    int tid = threadIdx.x;
    int warp = tid >> 5, lane = tid & 31;
    int gid = lane >> 2, tg = lane & 3;
    int wm = warp * 16;

    uint32_t sq_smem = (uint32_t)__cvta_generic_to_shared(SQ);
    uint32_t sk_smem = (uint32_t)__cvta_generic_to_shared(SK);
    uint32_t sv_smem = (uint32_t)__cvta_generic_to_shared(SV);

    // ldmatrix lane offsets
    int a_r = lane & 15;
    int a_k = (lane & 16) ? 8 : 0;
    int b_r = (lane & 7) + ((lane & 16) ? 8 : 0);
    int b_k = (lane & 8) ? 8 : 0;
    int v_r = (lane & 7) + ((lane & 8) ? 8 : 0);   // trans: key-row offset
    int v_c = (lane & 16) ? 8 : 0;                 // trans: dim-col offset

    // ---- stage Q (x 0.125, exact in fp16) ----
    {
        int row = tid >> 1, cb = (tid & 1) * 32;
        const __half* qp = qkv + (size_t)(b * NN + q0 + row) * (3 * DIM) + h * HD + cb;
        __half* dst = SQ + row * APITCH + cb;
        const __half2 sc = __floats2half2_rn(0.125f, 0.125f);
#pragma unroll
        for (int j = 0; j < 4; j++) {
            __half2 v0 = *(const __half2*)(qp + j * 8 + 0);
            __half2 v1 = *(const __half2*)(qp + j * 8 + 2);
            __half2 v2 = *(const __half2*)(qp + j * 8 + 4);
            __half2 v3 = *(const __half2*)(qp + j * 8 + 6);
            *(__half2*)(dst + j * 8 + 0) = __hmul2(v0, sc);
            *(__half2*)(dst + j * 8 + 2) = __hmul2(v1, sc);
            *(__half2*)(dst + j * 8 + 4) = __hmul2(v2, sc);
            *(__half2*)(dst + j * 8 + 6) = __hmul2(v3, sc);
        }
    }
    __syncthreads();

    // ---- Q fragments via ldmatrix ----
    uint32_t qf[4][4];
#pragma unroll
    for (int s = 0; s < 4; s++)
        ldsm4(qf[s], sq_smem + ((wm + a_r) * APITCH + s * 16 + a_k) * 2);

    float of[8][4];
#pragma unroll
    for (int i = 0; i < 8; i++)
#pragma unroll
        for (int j = 0; j < 4; j++) of[i][j] = 0.f;
    float m0r = -1e30f, m1r = -1e30f, l0r = 0.f, l1r = 0.f;

    for (int kt = 0; kt < NN / 64; kt++) {
        __syncthreads();
        // ---- load K and V row-major (uint4) ----
        {
            int row = tid >> 2, cb = (tid & 3) * 16;
            const __half* kp = qkv + (size_t)(b * NN + kt * 64 + row) * (3 * DIM) + DIM + h * HD + cb;
            const __half* vp = kp + DIM;
            *(uint4*)(SK + row * APITCH + cb)     = *(const uint4*)(kp);
            *(uint4*)(SK + row * APITCH + cb + 8) = *(const uint4*)(kp + 8);
            *(uint4*)(SV + row * APITCH + cb)     = *(const uint4*)(vp);
            *(uint4*)(SV + row * APITCH + cb + 8) = *(const uint4*)(vp + 8);
        }
        __syncthreads();

        // ---- S = Qs @ K^T ----
        float sf[8][4];
#pragma unroll
        for (int i = 0; i < 8; i++)
#pragma unroll
            for (int j = 0; j < 4; j++) sf[i][j] = 0.f;
#pragma unroll
        for (int s = 0; s < 4; s++) {
            uint32_t bf[8][2];
#pragma unroll
            for (int np = 0; np < 4; np++) {
                uint32_t bq[4];
                ldsm4(bq, sk_smem + ((np * 16 + b_r) * APITCH + s * 16 + b_k) * 2);
                bf[2 * np][0] = bq[0]; bf[2 * np][1] = bq[1];
                bf[2 * np + 1][0] = bq[2]; bf[2 * np + 1][1] = bq[3];
            }
#pragma unroll
            for (int ni = 0; ni < 8; ni++)
                mma_f16(sf[ni], qf[s], bf[ni]);
        }

        // ---- register-resident online softmax ----
        float tm0 = -1e30f, tm1 = -1e30f;
#pragma unroll
        for (int ni = 0; ni < 8; ni++) {
            tm0 = fmaxf(tm0, fmaxf(sf[ni][0], sf[ni][1]));
            tm1 = fmaxf(tm1, fmaxf(sf[ni][2], sf[ni][3]));
        }
        tm0 = fmaxf(tm0, __shfl_xor_sync(0xffffffffu, tm0, 1));
        tm0 = fmaxf(tm0, __shfl_xor_sync(0xffffffffu, tm0, 2));
        tm1 = fmaxf(tm1, __shfl_xor_sync(0xffffffffu, tm1, 1));
        tm1 = fmaxf(tm1, __shfl_xor_sync(0xffffffffu, tm1, 2));
        float mn0 = fmaxf(m0r, tm0), mn1 = fmaxf(m1r, tm1);
        float c0 = __expf(m0r - mn0), c1 = __expf(m1r - mn1);
        m0r = mn0; m1r = mn1;
        float rs0 = 0.f, rs1 = 0.f;
#pragma unroll
        for (int ni = 0; ni < 8; ni++) {
            sf[ni][0] = __expf(sf[ni][0] - mn0);
            sf[ni][1] = __expf(sf[ni][1] - mn0);
            sf[ni][2] = __expf(sf[ni][2] - mn1);
            sf[ni][3] = __expf(sf[ni][3] - mn1);
            rs0 += sf[ni][0] + sf[ni][1];
            rs1 += sf[ni][2] + sf[ni][3];
        }
        rs0 += __shfl_xor_sync(0xffffffffu, rs0, 1);
        rs0 += __shfl_xor_sync(0xffffffffu, rs0, 2);
        rs1 += __shfl_xor_sync(0xffffffffu, rs1, 1);
        rs1 += __shfl_xor_sync(0xffffffffu, rs1, 2);
        l0r = l0r * c0 + rs0;
        l1r = l1r * c1 + rs1;
#pragma unroll
        for (int ni = 0; ni < 8; ni++) {
            of[ni][0] *= c0; of[ni][1] *= c0;
            of[ni][2] *= c1; of[ni][3] *= c1;
        }

        // ---- O += P @ V : P frags from S accumulators, V frags via trans-ldmatrix
#pragma unroll
        for (int s = 0; s < 4; s++) {
            uint32_t pf[4];
            pf[0] = pack2(sf[2 * s][0], sf[2 * s][1]);
            pf[1] = pack2(sf[2 * s][2], sf[2 * s][3]);
            pf[2] = pack2(sf[2 * s + 1][0], sf[2 * s + 1][1]);
            pf[3] = pack2(sf[2 * s + 1][2], sf[2 * s + 1][3]);
            uint32_t bf[8][2];
#pragma unroll
            for (int np = 0; np < 4; np++) {
                uint32_t bq[4];
                ldsm4t(bq, sv_smem + ((s * 16 + v_r) * APITCH + np * 16 + v_c) * 2);
                bf[2 * np][0] = bq[0]; bf[2 * np][1] = bq[1];
                bf[2 * np + 1][0] = bq[2]; bf[2 * np + 1][1] = bq[3];
            }
#pragma unroll
            for (int ni = 0; ni < 8; ni++)
                mma_f16(of[ni], pf, bf[ni]);
        }
    }

    // ---- finalize ----
    float i0 = 1.f / l0r, i1 = 1.f / l1r;
    __half* o0 = out + (size_t)(b * NN + q0 + wm + gid) * DIM + h * HD;
    __half* o1 = out + (size_t)(b * NN + q0 + wm + gid + 8) * DIM + h * HD;
#pragma unroll
    for (int ni = 0; ni < 8; ni++) {
        int col = ni * 8 + 2 * tg;
        *(__half2*)(o0 + col) = __floats2half2_rn(of[ni][0] * i0, of[ni][1] * i0);
        *(__half2*)(o1 + col) = __floats2half2_rn(of[ni][2] * i1, of[ni][3] * i1);
    }
}

// ---------------- fused LN2 + gate + fp16 h output -----------------------------
__global__ void gate_ln_kernel(const float* __restrict__ x1, const float* __restrict__ g,
                               const float* __restrict__ bparm, const float* __restrict__ gw,
                               const float* __restrict__ gb, int* __restrict__ cnt,
                               int* __restrict__ ptok, int* __restrict__ smap,
                               float* __restrict__ sw, __half* __restrict__ hout) {
    __shared__ float xs[DIM];
    __shared__ float red[256];
    __shared__ float lg[NE];
    int t = blockIdx.x, tid = threadIdx.x;
    const float* xr = x1 + (size_t)t * DIM;
    float s = 0.f;
    for (int i = tid; i < DIM; i += 256) { float v = xr[i]; xs[i] = v; s += v; }
    red[tid] = s; __syncthreads();
    for (int st = 128; st > 0; st >>= 1) { if (tid < st) red[tid] += red[tid + st]; __syncthreads(); }
    float mu = red[0] * (1.f / DIM);
    __syncthreads();
    s = 0.f;
    for (int i = tid; i < DIM; i += 256) { float d = xs[i] - mu; s += d * d; }
    red[tid] = s; __syncthreads();
    for (int st = 128; st > 0; st >>= 1) { if (tid < st) red[tid] += red[tid + st]; __syncthreads(); }
    float inv = rsqrtf(red[0] * (1.f / DIM) + 1e-5f);
    __syncthreads();

    int w = tid >> 5, lane = tid & 31;
    float acc = 0.f;
    const float* gr = gw + (size_t)w * DIM;
    __half* hrow = hout + (size_t)t * DIM;
    for (int k = lane; k < DIM; k += 32) {
        float hv = (xs[k] - mu) * inv * g[k] + bparm[k];
        acc += hv * gr[k];
        if (w == 0) hrow[k] = __float2half_rn(hv);
    }
#pragma unroll
    for (int off = 16; off > 0; off >>= 1) acc += __shfl_down_sync(0xffffffffu, acc, off);
    if (lane == 0) lg[w] = acc + gb[w];
    __syncthreads();
    if (tid == 0) {
        int b0 = 0; float v0 = lg[0];
        for (int e = 1; e < NE; e++) if (lg[e] > v0) { v0 = lg[e]; b0 = e; }
        int b1 = -1; float v1 = -1e30f;
        for (int e = 0; e < NE; e++) {
            if (e == b0) continue;
            if (lg[e] > v1) { v1 = lg[e]; b1 = e; }
        }
        float e1 = __expf(v1 - v0);
        float s0 = 1.f / (1.f + e1);
        float s1 = 1.f - s0;
        int p0 = atomicAdd(&cnt[b0], 1);
        int p1 = atomicAdd(&cnt[b1], 1);
        ptok[b0 * TT + p0] = t;
        ptok[b1 * TT + p1] = t;
        smap[t * 2 + 0] = b0 * TT + p0; sw[t * 2 + 0] = s0;
        smap[t * 2 + 1] = b1 * TT + p1; sw[t * 2 + 1] = s1;
    }
}

// ---------------- combine -------------------------------------------------------
__global__ void combine_kernel(const float* __restrict__ x1, const float* __restrict__ y,
                               const int* __restrict__ smap, const float* __restrict__ sw,
                               float* __restrict__ out) {
    int t = blockIdx.x, tid = threadIdx.x;
    int s0 = smap[t * 2 + 0], s1 = smap[t * 2 + 1];
    float w0 = sw[t * 2 + 0], w1 = sw[t * 2 + 1];
    const float* y0 = y + (size_t)s0 * DIM;
    const float* y1 = y + (size_t)s1 * DIM;
    const float* xr = x1 + (size_t)t * DIM;
    float* orow = out + (size_t)t * DIM;
    for (int c = tid; c < DIM; c += 256)
        orow[c] = xr[c] + w0 * y0[c] + w1 * y1[c];
}

// ---------------- host launcher -------------------------------------------------
extern "C" void kernel_launch(void* const* d_in, const int* in_sizes, int n_in,
                              void* d_out, int out_size) {
    const float* x      = (const float*)d_in[0];
    const float* ln1_g  = (const float*)d_in[1];
    const float* ln1_b  = (const float*)d_in[2];
    const float* qkv_w  = (const float*)d_in[3];
    const float* proj_w = (const float*)d_in[4];
    const float* proj_b = (const float*)d_in[5];
    const float* ln2_g  = (const float*)d_in[6];
    const float* ln2_b  = (const float*)d_in[7];
    const float* gate_w = (const float*)d_in[8];
    const float* gate_b = (const float*)d_in[9];
    const float* w1     = (const float*)d_in[10];
    const float* b1     = (const float*)d_in[11];
    const float* w2     = (const float*)d_in[12];
    const float* b2     = (const float*)d_in[13];
    float* out = (float*)d_out;

    __half *h, *qkvb, *attn, *h1, *wh;
    float *x1, *y, *sw;
    int *cnt, *ptok, *smap;
    cudaGetSymbolAddress((void**)&h, g_h);
    cudaGetSymbolAddress((void**)&qkvb, g_qkv);
    cudaGetSymbolAddress((void**)&attn, g_attn);
    cudaGetSymbolAddress((void**)&x1, g_x1);
    cudaGetSymbolAddress((void**)&h1, g_h1);
    cudaGetSymbolAddress((void**)&y, g_y);
    cudaGetSymbolAddress((void**)&wh, g_wh);
    cudaGetSymbolAddress((void**)&cnt, g_cnt);
    cudaGetSymbolAddress((void**)&ptok, g_ptok);
    cudaGetSymbolAddress((void**)&smap, g_smap);
    cudaGetSymbolAddress((void**)&sw, g_sw);

    __half* qkv_wh = wh + W_QKV_OFF;
    __half* proj_wh = wh + W_PROJ_OFF;
    __half* w1h = wh + W_W1_OFF;
    __half* w2h = wh + W_W2_OFF;

    const int GEMM_SMEM = NSTAGE * 128 * HKPAD * 2 * 2;   // 61440
    cudaFuncSetAttribute(gemm_hc<false, false, 2>, cudaFuncAttributeMaxDynamicSharedMemorySize, GEMM_SMEM);
    cudaFuncSetAttribute(gemm_hc<false, false, 0>, cudaFuncAttributeMaxDynamicSharedMemorySize, GEMM_SMEM);
    cudaFuncSetAttribute(gemm_hc<true, true, 2>,   cudaFuncAttributeMaxDynamicSharedMemorySize, GEMM_SMEM);

    // 0. zero counters + fp16 weight conversion
    zero_cnt_kernel<<<1, 32>>>(cnt);
    tohalf_kernel<<<1024, 256>>>((const float4*)qkv_w,  (__half2*)qkv_wh,  W_QKV_N / 4);
    tohalf_kernel<<<512, 256>>>((const float4*)proj_w, (__half2*)proj_wh, W_PROJ_N / 4);
    tohalf_kernel<<<4096, 256>>>((const float4*)w1,     (__half2*)w1h,     W_W1_N / 4);
    tohalf_kernel<<<4096, 256>>>((const float4*)w2,     (__half2*)w2h,     W_W2_N / 4);

    // 1. LN1 -> h (fp16)
    ln_kernel<<<TT, 256>>>(x, ln1_g, ln1_b, h);

    // 2. qkv = h @ qkv_w^T  (fp16 out)
    gemm_hc<false, false, 2><<<dim3(18, 32, 1), 256, GEMM_SMEM>>>(
        h, qkv_wh, nullptr, nullptr, qkvb, TT, 3 * DIM, DIM, nullptr, nullptr, 0, 0, 0);

    // 3. attention
    attn_h<<<dim3(NN / 128, BB * HEADS), 256>>>(qkvb, attn);

    // 4. x1 = x + attn @ proj_w^T + proj_b  (fp32 out)
    gemm_hc<false, false, 0><<<dim3(6, 32, 1), 256, GEMM_SMEM>>>(
        attn, proj_wh, proj_b, x, x1, TT, DIM, DIM, nullptr, nullptr, 0, 0, 0);

    // 5. fused LN2 + gate (+ fp16 h)
    gate_ln_kernel<<<TT, 256>>>(x1, ln2_g, ln2_b, gate_w, gate_b, cnt, ptok, smap, sw, h);

    // 6. MoE up-proj + GELU (gathered, fp16 out)
    gemm_hc<true, true, 2><<<dim3(HID / 128, TT / 128, NE), 256, GEMM_SMEM>>>(
        h, w1h, b1, nullptr, h1, TT, HID, DIM, ptok, cnt,
        0, (size_t)HID * DIM, (size_t)TT * HID);

    // 7. MoE down-proj (fp32 out)
    gemm_hc<false, false, 0><<<dim3(6, 32, NE), 256, GEMM_SMEM>>>(
        h1, w2h, b2, nullptr, y, TT, DIM, HID, nullptr, cnt,
        (size_t)TT * HID, (size_t)DIM * HID, (size_t)TT * DIM);

    // 8. combine + final residual
    combine_kernel<<<TT, 256>>>(x1, y, smap, sw, out);
}

// round 11
// speedup vs baseline: 5.9274x; 1.0311x over previous
#include <cuda_runtime.h>
#include <cuda_fp16.h>
#include <math.h>
#include <stdint.h>

#define BB 4
#define NN 1024
#define TT 4096
#define DIM 768
#define HEADS 12
#define HD 64
#define HID 3072
#define NE 8

#define NSTAGE 3
#define HKPAD 40   // gemm smem pitch in halves (80B rows; ldmatrix conflict-free)

#define APITCH 72  // attention pitch in halves (144B rows; ldmatrix conflict-free)

// half weight scratch offsets (in halves)
#define W_QKV_OFF 0
#define W_QKV_N   (3 * DIM * DIM)
#define W_PROJ_OFF (W_QKV_OFF + W_QKV_N)
#define W_PROJ_N  (DIM * DIM)
#define W_W1_OFF  (W_PROJ_OFF + W_PROJ_N)
#define W_W1_N    (NE * HID * DIM)
#define W_W2_OFF  (W_W1_OFF + W_W1_N)
#define W_W2_N    (NE * DIM * HID)

// ---------------- scratch (static device globals; no allocs) ----------------
__device__ __half g_h[(size_t)TT * DIM];
__device__ __half g_qkv[(size_t)TT * 3 * DIM];
__device__ __half g_attn[(size_t)TT * DIM];
__device__ float  g_x1[(size_t)TT * DIM];
__device__ __half g_h1[(size_t)NE * TT * HID];
__device__ __half g_wh[(size_t)W_W2_OFF + W_W2_N];
__device__ int    g_cnt[NE];
__device__ int    g_ptok[NE * TT];
__device__ float  g_pw[NE * TT];     // combine weight per (expert, slot)

__global__ void zero_cnt_kernel(int* c) {
    if (threadIdx.x < NE) c[threadIdx.x] = 0;
}

// ---------------- helpers ------------------------------------------------------
__device__ __forceinline__ uint32_t h2u(__half2 v) {
    union { __half2 h; uint32_t u; } cvt;
    cvt.h = v;
    return cvt.u;
}
__device__ __forceinline__ uint32_t pack2(float a, float b) {
    return h2u(__floats2half2_rn(a, b));
}

__device__ __forceinline__ void mma_f16(float* c, const uint32_t* a, const uint32_t* b) {
    asm volatile(
        "mma.sync.aligned.m16n8k16.row.col.f32.f16.f16.f32 "
        "{%0,%1,%2,%3}, {%4,%5,%6,%7}, {%8,%9}, {%0,%1,%2,%3};"
        : "+f"(c[0]), "+f"(c[1]), "+f"(c[2]), "+f"(c[3])
        : "r"(a[0]), "r"(a[1]), "r"(a[2]), "r"(a[3]), "r"(b[0]), "r"(b[1]));
}

__device__ __forceinline__ void ldsm4(uint32_t* r, uint32_t addr) {
    asm volatile("ldmatrix.sync.aligned.m8n8.x4.shared.b16 {%0,%1,%2,%3}, [%4];"
                 : "=r"(r[0]), "=r"(r[1]), "=r"(r[2]), "=r"(r[3]) : "r"(addr));
}
__device__ __forceinline__ void ldsm4t(uint32_t* r, uint32_t addr) {
    asm volatile("ldmatrix.sync.aligned.m8n8.x4.trans.shared.b16 {%0,%1,%2,%3}, [%4];"
                 : "=r"(r[0]), "=r"(r[1]), "=r"(r[2]), "=r"(r[3]) : "r"(addr));
}

__device__ __forceinline__ void cp16(uint32_t dst, const void* src, int sz) {
    asm volatile("cp.async.cg.shared.global [%0], [%1], 16, %2;"
                 :: "r"(dst), "l"(src), "r"(sz));
}

// ---------------- f32 -> f16 weight conversion (16B stores) --------------------
__global__ void tohalf_kernel(const float4* __restrict__ src, uint4* __restrict__ dst, int n8) {
    int i = blockIdx.x * blockDim.x + threadIdx.x;
    int stride = gridDim.x * blockDim.x;
    for (; i < n8; i += stride) {
        float4 a = src[2 * i];
        float4 b = src[2 * i + 1];
        uint4 o;
        o.x = pack2(a.x, a.y); o.y = pack2(a.z, a.w);
        o.z = pack2(b.x, b.y); o.w = pack2(b.z, b.w);
        dst[i] = o;
    }
}

// ---------------- layernorm (fp16 output) --------------------------------------
__global__ void ln_kernel(const float* __restrict__ x, const float* __restrict__ g,
                          const float* __restrict__ b, __half* __restrict__ o) {
    __shared__ float xs[DIM];
    __shared__ float red[256];
    int t = blockIdx.x, tid = threadIdx.x;
    const float* xr = x + (size_t)t * DIM;
    float s = 0.f;
    for (int i = tid; i < DIM; i += 256) { float v = xr[i]; xs[i] = v; s += v; }
    red[tid] = s; __syncthreads();
    for (int st = 128; st > 0; st >>= 1) { if (tid < st) red[tid] += red[tid + st]; __syncthreads(); }
    float mu = red[0] * (1.f / DIM);
    __syncthreads();
    s = 0.f;
    for (int i = tid; i < DIM; i += 256) { float d = xs[i] - mu; s += d * d; }
    red[tid] = s; __syncthreads();
    for (int st = 128; st > 0; st >>= 1) { if (tid < st) red[tid] += red[tid + st]; __syncthreads(); }
    float inv = rsqrtf(red[0] * (1.f / DIM) + 1e-5f);
    __half* orow = o + (size_t)t * DIM;
    for (int i = tid; i < DIM; i += 256)
        orow[i] = __float2half_rn((xs[i] - mu) * inv * g[i] + b[i]);
}

// ---------------- fp16 tensor-core GEMM (ldmatrix): C = A @ B^T ----------------
// OUTMODE: 0 = float, 2 = half, 3 = scatter-atomic float (MoE combine)
template <bool GATHER, bool GELU, int OUTMODE>
__global__ void __launch_bounds__(256)
gemm_hc(const __half* __restrict__ A, const __half* __restrict__ Bw,
        const float* __restrict__ bias, const float* __restrict__ resid,
        void* __restrict__ Cout, int M, int N, int K,
        const int* __restrict__ rows, const int* __restrict__ cnts,
        const float* __restrict__ pw,
        size_t sA, size_t sB, size_t sC) {
    extern __shared__ __half smh[];
    __half* SA = smh;
    __half* SB = smh + (size_t)NSTAGE * 128 * HKPAD;

    int z = blockIdx.z;
    A += (size_t)z * sA; Bw += (size_t)z * sB;
    if (bias) bias += (size_t)z * N;
    if (rows) rows += (size_t)z * TT;
    if (pw)   pw += (size_t)z * TT;
    int Mz = cnts ? cnts[z] : M;
    if (Mz > M) Mz = M;
    int m0 = blockIdx.y * 128;
    if (m0 >= Mz) return;
    int n0 = blockIdx.x * 128;

    int tid = threadIdx.x;
    int r0 = tid >> 2, kq = tid & 3;

    const __half *ga0, *ga1;
    int za0 = 16, za1 = 16;
    if (GATHER) {
        int i0 = m0 + r0, i1 = i0 + 64;
        int g0 = 0, g1 = 0;
        if (i0 < Mz) g0 = rows[i0]; else za0 = 0;
        if (i1 < Mz) g1 = rows[i1]; else za1 = 0;
        ga0 = A + (size_t)g0 * K + kq * 8;
        ga1 = A + (size_t)g1 * K + kq * 8;
    } else {
        ga0 = A + (size_t)(m0 + r0) * K + kq * 8;
        ga1 = ga0 + (size_t)64 * K;
    }
    const __half* gb0 = Bw + (size_t)(n0 + r0) * K + kq * 8;
    const __half* gb1 = gb0 + (size_t)64 * K;

    uint32_t sa_smem = (uint32_t)__cvta_generic_to_shared(SA);
    uint32_t sb_smem = (uint32_t)__cvta_generic_to_shared(SB);
    uint32_t sa_base = sa_smem + (r0 * HKPAD + kq * 8) * 2;
    uint32_t sb_base = sb_smem + (r0 * HKPAD + kq * 8) * 2;
    const uint32_t BUFB = 128 * HKPAD * 2;
    const uint32_t HALF = 64 * HKPAD * 2;

    int NIT = K >> 5;

    auto load_tile = [&](int it) {
        uint32_t off = (uint32_t)(it % NSTAGE) * BUFB;
        cp16(sa_base + off,        ga0 + it * 32, za0);
        cp16(sa_base + off + HALF, ga1 + it * 32, za1);
        cp16(sb_base + off,        gb0 + it * 32, 16);
        cp16(sb_base + off + HALF, gb1 + it * 32, 16);
        asm volatile("cp.async.commit_group;" ::: "memory");
    };

    int warp = tid >> 5, lane = tid & 31;
    int gid = lane >> 2, tg = lane & 3;
    int wm = (warp >> 1) * 32, wn = (warp & 1) * 64;

    int a_r = lane & 15;
    int a_k = (lane & 16) ? 8 : 0;
    int b_r = (lane & 7) + ((lane & 16) ? 8 : 0);
    int b_k = (lane & 8) ? 8 : 0;

    float acc[2][8][4];
#pragma unroll
    for (int i = 0; i < 2; i++)
#pragma unroll
        for (int j = 0; j < 8; j++)
#pragma unroll
            for (int k = 0; k < 4; k++) acc[i][j][k] = 0.f;

    load_tile(0);
    if (NIT > 1) load_tile(1);

    for (int it = 0; it < NIT; ++it) {
        if (it + 1 < NIT) asm volatile("cp.async.wait_group 1;" ::: "memory");
        else              asm volatile("cp.async.wait_group 0;" ::: "memory");
        __syncthreads();
        if (it + 2 < NIT) load_tile(it + 2);

        uint32_t st = (uint32_t)(it % NSTAGE) * BUFB;
        uint32_t sa_st = sa_smem + st;
        uint32_t sb_st = sb_smem + st;

#pragma unroll
        for (int ks = 0; ks < 2; ks++) {
            uint32_t af[2][4], bf[8][2];
#pragma unroll
            for (int mi = 0; mi < 2; mi++)
                ldsm4(af[mi], sa_st + ((wm + mi * 16 + a_r) * HKPAD + ks * 16 + a_k) * 2);
#pragma unroll
            for (int np = 0; np < 4; np++) {
                uint32_t bq[4];
                ldsm4(bq, sb_st + ((wn + np * 16 + b_r) * HKPAD + ks * 16 + b_k) * 2);
                bf[2 * np][0] = bq[0]; bf[2 * np][1] = bq[1];
                bf[2 * np + 1][0] = bq[2]; bf[2 * np + 1][1] = bq[3];
            }
#pragma unroll
            for (int mi = 0; mi < 2; mi++)
#pragma unroll
                for (int ni = 0; ni < 8; ni++)
                    mma_f16(acc[mi][ni], af[mi], bf[ni]);
        }
    }

#pragma unroll
    for (int mi = 0; mi < 2; mi++) {
#pragma unroll
        for (int hh = 0; hh < 2; hh++) {
            int rr = m0 + wm + mi * 16 + gid + hh * 8;
            if (rr >= Mz) continue;
            const float* rrow = resid ? resid + (size_t)rr * N : nullptr;
            int tok = 0; float wgt = 0.f;
            if (OUTMODE == 3) { tok = rows[rr]; wgt = pw[rr]; }
#pragma unroll
            for (int ni = 0; ni < 8; ni++) {
                int col = n0 + wn + ni * 8 + tg * 2;
                float v0 = acc[mi][ni][hh * 2 + 0];
                float v1 = acc[mi][ni][hh * 2 + 1];
                if (bias) { v0 += bias[col]; v1 += bias[col + 1]; }
                if (GELU) {
                    v0 = 0.5f * v0 * (1.f + erff(v0 * 0.70710678118654752f));
                    v1 = 0.5f * v1 * (1.f + erff(v1 * 0.70710678118654752f));
                }
                if (rrow) { v0 += rrow[col]; v1 += rrow[col + 1]; }
                if (OUTMODE == 2) {
                    __half2* crow = (__half2*)((__half*)Cout + (size_t)z * sC + (size_t)rr * N + col);
                    *crow = __floats2half2_rn(v0, v1);
                } else if (OUTMODE == 3) {
                    float* orow = (float*)Cout + (size_t)tok * N + col;
                    atomicAdd(orow, wgt * v0);
                    atomicAdd(orow + 1, wgt * v1);
                } else {
                    float* crow = (float*)Cout + (size_t)z * sC + (size_t)rr * N + col;
                    crow[0] = v0; crow[1] = v1;
                }
            }
        }
    }
}

// ---------------- fp16 flash attention (ldmatrix + cp.async pipeline) ----------
// 128 q-rows/block, 8 warps, warp w owns rows [16w,16w+16). 64-key tiles, 2 stages.
__global__ void __launch_bounds__(256)
attn_h(const __half* __restrict__ qkv, __half* __restrict__ out) {
    extern __shared__ __half sma[];
    __half* SQ = sma;                          // [128][APITCH]
    __half* SK = SQ + 128 * APITCH;            // [2][64][APITCH]
    __half* SV = SK + 2 * 64 * APITCH;         // [2][64][APITCH]

    int bh = blockIdx.y;
    int b = bh / HEADS, h = bh % HEADS;
    int q0 = blockIdx.x * 128;
    int tid = threadIdx.x;
    int warp = tid >> 5, lane = tid & 31;
    int gid = lane >> 2, tg = lane & 3;
    int wm = warp * 16;

    uint32_t sq_smem = (uint32_t)__cvta_generic_to_shared(SQ);
    uint32_t sk_smem = (uint32_t)__cvta_generic_to_shared(SK);
    uint32_t sv_smem = (uint32_t)__cvta_generic_to_shared(SV);
    const uint32_t STAGE = 64 * APITCH * 2;   // bytes per K/V stage

    int a_r = lane & 15;
    int a_k = (lane & 16) ? 8 : 0;
    int b_r = (lane & 7) + ((lane & 16) ? 8 : 0);
    int b_k = (lane & 8) ? 8 : 0;
    int v_r = (lane & 7) + ((lane & 8) ? 8 : 0);
    int v_c = (lane & 16) ? 8 : 0;

    // KV loader: thread -> row tid>>2, 16-half chunk (tid&3)
    int krow = tid >> 2, kq4 = tid & 3;
    const __half* kbase = qkv + (size_t)(b * NN + krow) * (3 * DIM) + DIM + h * HD + kq4 * 16;
    uint32_t kdst = sk_smem + (krow * APITCH + kq4 * 16) * 2;
    uint32_t vdst = sv_smem + (krow * APITCH + kq4 * 16) * 2;

    auto loadKV = [&](int kt) {
        uint32_t off = (uint32_t)(kt & 1) * STAGE;
        const __half* kp = kbase + (size_t)kt * 64 * 3 * DIM;
        const __half* vp = kp + DIM;
        cp16(kdst + off, kp, 16);
        cp16(kdst + off + 16, kp + 8, 16);
        cp16(vdst + off, vp, 16);
        cp16(vdst + off + 16, vp + 8, 16);
        asm volatile("cp.async.commit_group;" ::: "memory");
    };

    // ---- stage Q (x 0.125, exact in fp16) ----
    {
        int row = tid >> 1, cb = (tid & 1) * 32;
        const __half* qp = qkv + (size_t)(b * NN + q0 + row) * (3 * DIM) + h * HD + cb;
        __half* dst = SQ + row * APITCH + cb;
        const __half2 sc = __floats2half2_rn(0.125f, 0.125f);
#pragma unroll
        for (int j = 0; j < 4; j++) {
            __half2 v0 = *(const __half2*)(qp + j * 8 + 0);
            __half2 v1 = *(const __half2*)(qp + j * 8 + 2);
            __half2 v2 = *(const __half2*)(qp + j * 8 + 4);
            __half2 v3 = *(const __half2*)(qp + j * 8 + 6);
            *(__half2*)(dst + j * 8 + 0) = __hmul2(v0, sc);
            *(__half2*)(dst + j * 8 + 2) = __hmul2(v1, sc);
            *(__half2*)(dst + j * 8 + 4) = __hmul2(v2, sc);
            *(__half2*)(dst + j * 8 + 6) = __hmul2(v3, sc);
        }
    }
    loadKV(0);
    __syncthreads();

    // ---- Q fragments via ldmatrix ----
    uint32_t qf[4][4];
#pragma unroll
    for (int s = 0; s < 4; s++)
        ldsm4(qf[s], sq_smem + ((wm + a_r) * APITCH + s * 16 + a_k) * 2);

    float of[8][4];
#pragma unroll
    for (int i = 0; i < 8; i++)
#pragma unroll
        for (int j = 0; j < 4; j++) of[i][j] = 0.f;
    float m0r = -1e30f, m1r = -1e30f, l0r = 0.f, l1r = 0.f;

    const int NT = NN / 64;
    for (int kt = 0; kt < NT; kt++) {
        if (kt + 1 < NT) loadKV(kt + 1);
        if (kt + 1 < NT) asm volatile("cp.async.wait_group 1;" ::: "memory");
        else             asm volatile("cp.async.wait_group 0;" ::: "memory");
        __syncthreads();

        uint32_t sk_st = sk_smem + (uint32_t)(kt & 1) * STAGE;
        uint32_t sv_st = sv_smem + (uint32_t)(kt & 1) * STAGE;

        // ---- S = Qs @ K^T ----
        float sf[8][4];
#pragma unroll
        for (int i = 0; i < 8; i++)
#pragma unroll
            for (int j = 0; j < 4; j++) sf[i][j] = 0.f;
#pragma unroll
        for (int s = 0; s < 4; s++) {
            uint32_t bf[8][2];
#pragma unroll
            for (int np = 0; np < 4; np++) {
                uint32_t bq[4];
                ldsm4(bq, sk_st + ((np * 16 + b_r) * APITCH + s * 16 + b_k) * 2);
                bf[2 * np][0] = bq[0]; bf[2 * np][1] = bq[1];
                bf[2 * np + 1][0] = bq[2]; bf[2 * np + 1][1] = bq[3];
            }
#pragma unroll
            for (int ni = 0; ni < 8; ni++)
                mma_f16(sf[ni], qf[s], bf[ni]);
        }

        // ---- register-resident online softmax ----
        float tm0 = -1e30f, tm1 = -1e30f;
#pragma unroll
        for (int ni = 0; ni < 8; ni++) {
            tm0 = fmaxf(tm0, fmaxf(sf[ni][0], sf[ni][1]));
            tm1 = fmaxf(tm1, fmaxf(sf[ni][2], sf[ni][3]));
        }
        tm0 = fmaxf(tm0, __shfl_xor_sync(0xffffffffu, tm0, 1));
        tm0 = fmaxf(tm0, __shfl_xor_sync(0xffffffffu, tm0, 2));
        tm1 = fmaxf(tm1, __shfl_xor_sync(0xffffffffu, tm1, 1));
        tm1 = fmaxf(tm1, __shfl_xor_sync(0xffffffffu, tm1, 2));
        float mn0 = fmaxf(m0r, tm0), mn1 = fmaxf(m1r, tm1);
        float c0 = __expf(m0r - mn0), c1 = __expf(m1r - mn1);
        m0r = mn0; m1r = mn1;
        float rs0 = 0.f, rs1 = 0.f;
#pragma unroll
        for (int ni = 0; ni < 8; ni++) {
            sf[ni][0] = __expf(sf[ni][0] - mn0);
            sf[ni][1] = __expf(sf[ni][1] - mn0);
            sf[ni][2] = __expf(sf[ni][2] - mn1);
            sf[ni][3] = __expf(sf[ni][3] - mn1);
            rs0 += sf[ni][0] + sf[ni][1];
            rs1 += sf[ni][2] + sf[ni][3];
        }
        rs0 += __shfl_xor_sync(0xffffffffu, rs0, 1);
        rs0 += __shfl_xor_sync(0xffffffffu, rs0, 2);
        rs1 += __shfl_xor_sync(0xffffffffu, rs1, 1);
        rs1 += __shfl_xor_sync(0xffffffffu, rs1, 2);
        l0r = l0r * c0 + rs0;
        l1r = l1r * c1 + rs1;
#pragma unroll
        for (int ni = 0; ni < 8; ni++) {
            of[ni][0] *= c0; of[ni][1] *= c0;
            of[ni][2] *= c1; of[ni][3] *= c1;
        }

        // ---- O += P @ V ----
#pragma unroll
        for (int s = 0; s < 4; s++) {
            uint32_t pf[4];
            pf[0] = pack2(sf[2 * s][0], sf[2 * s][1]);
            pf[1] = pack2(sf[2 * s][2], sf[2 * s][3]);
            pf[2] = pack2(sf[2 * s + 1][0], sf[2 * s + 1][1]);
            pf[3] = pack2(sf[2 * s + 1][2], sf[2 * s + 1][3]);
            uint32_t bf[8][2];
#pragma unroll
            for (int np = 0; np < 4; np++) {
                uint32_t bq[4];
                ldsm4t(bq, sv_st + ((s * 16 + v_r) * APITCH + np * 16 + v_c) * 2);
                bf[2 * np][0] = bq[0]; bf[2 * np][1] = bq[1];
                bf[2 * np + 1][0] = bq[2]; bf[2 * np + 1][1] = bq[3];
            }
#pragma unroll
            for (int ni = 0; ni < 8; ni++)
                mma_f16(of[ni], pf, bf[ni]);
        }
        __syncthreads();   // stage reuse guard
    }

    // ---- finalize ----
    float i0 = 1.f / l0r, i1 = 1.f / l1r;
    __half* o0 = out + (size_t)(b * NN + q0 + wm + gid) * DIM + h * HD;
    __half* o1 = out + (size_t)(b * NN + q0 + wm + gid + 8) * DIM + h * HD;
#pragma unroll
    for (int ni = 0; ni < 8; ni++) {
        int col = ni * 8 + 2 * tg;
        *(__half2*)(o0 + col) = __floats2half2_rn(of[ni][0] * i0, of[ni][1] * i0);
        *(__half2*)(o1 + col) = __floats2half2_rn(of[ni][2] * i1, of[ni][3] * i1);
    }
}

// ------ fused LN2 + gate + fp16 h + out-init (out = x1) ------------------------
__global__ void gate_ln_kernel(const float* __restrict__ x1, const float* __restrict__ g,
                               const float* __restrict__ bparm, const float* __restrict__ gw,
                               const float* __restrict__ gb, int* __restrict__ cnt,
                               int* __restrict__ ptok, float* __restrict__ pw,
                               __half* __restrict__ hout, float* __restrict__ outinit) {
    __shared__ float xs[DIM];
    __shared__ float red[256];
    __shared__ float lg[NE];
    int t = blockIdx.x, tid = threadIdx.x;
    const float* xr = x1 + (size_t)t * DIM;
    float* orow = outinit + (size_t)t * DIM;
    float s = 0.f;
    for (int i = tid; i < DIM; i += 256) {
        float v = xr[i];
        xs[i] = v; orow[i] = v;
        s += v;
    }
    red[tid] = s; __syncthreads();
    for (int st = 128; st > 0; st >>= 1) { if (tid < st) red[tid] += red[tid + st]; __syncthreads(); }
    float mu = red[0] * (1.f / DIM);
    __syncthreads();
    s = 0.f;
    for (int i = tid; i < DIM; i += 256) { float d = xs[i] - mu; s += d * d; }
    red[tid] = s; __syncthreads();
    for (int st = 128; st > 0; st >>= 1) { if (tid < st) red[tid] += red[tid + st]; __syncthreads(); }
    float inv = rsqrtf(red[0] * (1.f / DIM) + 1e-5f);
    __syncthreads();

    int w = tid >> 5, lane = tid & 31;
    float acc = 0.f;
    const float* gr = gw + (size_t)w * DIM;
    __half* hrow = hout + (size_t)t * DIM;
    for (int k = lane; k < DIM; k += 32) {
        float hv = (xs[k] - mu) * inv * g[k] + bparm[k];
        acc += hv * gr[k];
        if (w == 0) hrow[k] = __float2half_rn(hv);
    }
#pragma unroll
    for (int off = 16; off > 0; off >>= 1) acc += __shfl_down_sync(0xffffffffu, acc, off);
    if (lane == 0) lg[w] = acc + gb[w];
    __syncthreads();
    if (tid == 0) {
        int b0 = 0; float v0 = lg[0];
        for (int e = 1; e < NE; e++) if (lg[e] > v0) { v0 = lg[e]; b0 = e; }
        int b1 = -1; float v1 = -1e30f;
        for (int e = 0; e < NE; e++) {
            if (e == b0) continue;
            if (lg[e] > v1) { v1 = lg[e]; b1 = e; }
        }
        float e1 = __expf(v1 - v0);
        float s0 = 1.f / (1.f + e1);
        float s1 = 1.f - s0;
        int p0 = atomicAdd(&cnt[b0], 1);
        int p1 = atomicAdd(&cnt[b1], 1);
        ptok[b0 * TT + p0] = t; pw[b0 * TT + p0] = s0;
        ptok[b1 * TT + p1] = t; pw[b1 * TT + p1] = s1;
    }
}

// ---------------- host launcher -------------------------------------------------
extern "C" void kernel_launch(void* const* d_in, const int* in_sizes, int n_in,
                              void* d_out, int out_size) {
    const float* x      = (const float*)d_in[0];
    const float* ln1_g  = (const float*)d_in[1];
    const float* ln1_b  = (const float*)d_in[2];
    const float* qkv_w  = (const float*)d_in[3];
    const float* proj_w = (const float*)d_in[4];
    const float* proj_b = (const float*)d_in[5];
    const float* ln2_g  = (const float*)d_in[6];
    const float* ln2_b  = (const float*)d_in[7];
    const float* gate_w = (const float*)d_in[8];
    const float* gate_b = (const float*)d_in[9];
    const float* w1     = (const float*)d_in[10];
    const float* b1     = (const float*)d_in[11];
    const float* w2     = (const float*)d_in[12];
    const float* b2     = (const float*)d_in[13];
    float* out = (float*)d_out;

    __half *h, *qkvb, *attn, *h1, *wh;
    float *x1, *pw;
    int *cnt, *ptok;
    cudaGetSymbolAddress((void**)&h, g_h);
    cudaGetSymbolAddress((void**)&qkvb, g_qkv);
    cudaGetSymbolAddress((void**)&attn, g_attn);
    cudaGetSymbolAddress((void**)&x1, g_x1);
    cudaGetSymbolAddress((void**)&h1, g_h1);
    cudaGetSymbolAddress((void**)&wh, g_wh);
    cudaGetSymbolAddress((void**)&cnt, g_cnt);
    cudaGetSymbolAddress((void**)&ptok, g_ptok);
    cudaGetSymbolAddress((void**)&pw, g_pw);

    __half* qkv_wh = wh + W_QKV_OFF;
    __half* proj_wh = wh + W_PROJ_OFF;
    __half* w1h = wh + W_W1_OFF;
    __half* w2h = wh + W_W2_OFF;

    const int GEMM_SMEM = NSTAGE * 128 * HKPAD * 2 * 2;           // 61440
    const int ATTN_SMEM = (128 + 4 * 64) * APITCH * 2;            // 55296
    cudaFuncSetAttribute(gemm_hc<false, false, 2>, cudaFuncAttributeMaxDynamicSharedMemorySize, GEMM_SMEM);
    cudaFuncSetAttribute(gemm_hc<false, false, 0>, cudaFuncAttributeMaxDynamicSharedMemorySize, GEMM_SMEM);
    cudaFuncSetAttribute(gemm_hc<true, true, 2>,   cudaFuncAttributeMaxDynamicSharedMemorySize, GEMM_SMEM);
    cudaFuncSetAttribute(gemm_hc<false, false, 3>, cudaFuncAttributeMaxDynamicSharedMemorySize, GEMM_SMEM);
    cudaFuncSetAttribute(attn_h, cudaFuncAttributeMaxDynamicSharedMemorySize, ATTN_SMEM);

    // 0. zero counters + fp16 weight conversion
    zero_cnt_kernel<<<1, 32>>>(cnt);
    tohalf_kernel<<<1024, 256>>>((const float4*)qkv_w,  (uint4*)qkv_wh,  W_QKV_N / 8);
    tohalf_kernel<<<512, 256>>>((const float4*)proj_w, (uint4*)proj_wh, W_PROJ_N / 8);
    tohalf_kernel<<<4096, 256>>>((const float4*)w1,     (uint4*)w1h,     W_W1_N / 8);
    tohalf_kernel<<<4096, 256>>>((const float4*)w2,     (uint4*)w2h,     W_W2_N / 8);

    // 1. LN1 -> h (fp16)
    ln_kernel<<<TT, 256>>>(x, ln1_g, ln1_b, h);

    // 2. qkv = h @ qkv_w^T  (fp16 out)
    gemm_hc<false, false, 2><<<dim3(18, 32, 1), 256, GEMM_SMEM>>>(
        h, qkv_wh, nullptr, nullptr, qkvb, TT, 3 * DIM, DIM, nullptr, nullptr, nullptr, 0, 0, 0);

    // 3. attention
    attn_h<<<dim3(NN / 128, BB * HEADS), 256, ATTN_SMEM>>>(qkvb, attn);

    // 4. x1 = x + attn @ proj_w^T + proj_b  (fp32 out)
    gemm_hc<false, false, 0><<<dim3(6, 32, 1), 256, GEMM_SMEM>>>(
        attn, proj_wh, proj_b, x, x1, TT, DIM, DIM, nullptr, nullptr, nullptr, 0, 0, 0);

    // 5. fused LN2 + gate (+ fp16 h, + out = x1 init)
    gate_ln_kernel<<<TT, 256>>>(x1, ln2_g, ln2_b, gate_w, gate_b, cnt, ptok, pw, h, out);

    // 6. MoE up-proj + GELU (gathered, fp16 out)
    gemm_hc<true, true, 2><<<dim3(HID / 128, TT / 128, NE), 256, GEMM_SMEM>>>(
        h, w1h, b1, nullptr, h1, TT, HID, DIM, ptok, cnt, nullptr,
        0, (size_t)HID * DIM, (size_t)TT * HID);

    // 7. MoE down-proj, fused combine (scatter-atomic into out)
    gemm_hc<false, false, 3><<<dim3(6, 32, NE), 256, GEMM_SMEM>>>(
        h1, w2h, b2, nullptr, out, TT, DIM, HID, ptok, cnt, pw,
        (size_t)TT * HID, (size_t)DIM * HID, 0);
}

// round 12
// speedup vs baseline: 6.0168x; 1.0151x over previous
#include <cuda_runtime.h>
#include <cuda_fp16.h>
#include <math.h>
#include <stdint.h>

#define BB 4
#define NN 1024
#define TT 4096
#define DIM 768
#define HEADS 12
#define HD 64
#define HID 3072
#define NE 8

#define NSTAGE 3
#define HKPAD 40   // gemm smem pitch in halves (80B rows; ldmatrix conflict-free)

#define APITCH 72  // attention pitch in halves (144B rows; ldmatrix conflict-free)

// half weight scratch offsets (in halves)
#define W_QKV_OFF 0
#define W_QKV_N   (3 * DIM * DIM)
#define W_PROJ_OFF (W_QKV_OFF + W_QKV_N)
#define W_PROJ_N  (DIM * DIM)
#define W_W1_OFF  (W_PROJ_OFF + W_PROJ_N)
#define W_W1_N    (NE * HID * DIM)
#define W_W2_OFF  (W_W1_OFF + W_W1_N)
#define W_W2_N    (NE * DIM * HID)
#define W_TOTAL   (W_W2_OFF + W_W2_N)

// ---------------- scratch (static device globals; no allocs) ----------------
__device__ __half g_h[(size_t)TT * DIM];
__device__ __half g_qkv[(size_t)TT * 3 * DIM];
__device__ __half g_attn[(size_t)TT * DIM];
__device__ float  g_x1[(size_t)TT * DIM];
__device__ __half g_h1[(size_t)NE * TT * HID];
__device__ __half g_wh[(size_t)W_TOTAL];
__device__ int    g_cnt[NE];
__device__ int    g_ptok[NE * TT];
__device__ float  g_pw[NE * TT];     // combine weight per (expert, slot)

__global__ void zero_cnt_kernel(int* c) {
    if (threadIdx.x < NE) c[threadIdx.x] = 0;
}

// ---------------- helpers ------------------------------------------------------
__device__ __forceinline__ uint32_t h2u(__half2 v) {
    union { __half2 h; uint32_t u; } cvt;
    cvt.h = v;
    return cvt.u;
}
__device__ __forceinline__ uint32_t pack2(float a, float b) {
    return h2u(__floats2half2_rn(a, b));
}

__device__ __forceinline__ void mma_f16(float* c, const uint32_t* a, const uint32_t* b) {
    asm volatile(
        "mma.sync.aligned.m16n8k16.row.col.f32.f16.f16.f32 "
        "{%0,%1,%2,%3}, {%4,%5,%6,%7}, {%8,%9}, {%0,%1,%2,%3};"
        : "+f"(c[0]), "+f"(c[1]), "+f"(c[2]), "+f"(c[3])
        : "r"(a[0]), "r"(a[1]), "r"(a[2]), "r"(a[3]), "r"(b[0]), "r"(b[1]));
}

__device__ __forceinline__ void ldsm4(uint32_t* r, uint32_t addr) {
    asm volatile("ldmatrix.sync.aligned.m8n8.x4.shared.b16 {%0,%1,%2,%3}, [%4];"
                 : "=r"(r[0]), "=r"(r[1]), "=r"(r[2]), "=r"(r[3]) : "r"(addr));
}
__device__ __forceinline__ void ldsm4t(uint32_t* r, uint32_t addr) {
    asm volatile("ldmatrix.sync.aligned.m8n8.x4.trans.shared.b16 {%0,%1,%2,%3}, [%4];"
                 : "=r"(r[0]), "=r"(r[1]), "=r"(r[2]), "=r"(r[3]) : "r"(addr));
}

__device__ __forceinline__ void cp16(uint32_t dst, const void* src, int sz) {
    asm volatile("cp.async.cg.shared.global [%0], [%1], 16, %2;"
                 :: "r"(dst), "l"(src), "r"(sz));
}

// ---------------- fused f32 -> f16 conversion of ALL weights -------------------
// one launch; region selected by range (memory-bound, branch negligible)
__global__ void tohalf_all(const float4* __restrict__ qkv_w, const float4* __restrict__ proj_w,
                           const float4* __restrict__ w1, const float4* __restrict__ w2,
                           uint4* __restrict__ dst) {
    const int n8 = W_TOTAL / 8;
    int i = blockIdx.x * blockDim.x + threadIdx.x;
    int stride = gridDim.x * blockDim.x;
    for (; i < n8; i += stride) {
        int e = i * 8;   // half index
        const float4* src;
        int off;
        if (e < W_PROJ_OFF)      { src = qkv_w;  off = e - W_QKV_OFF; }
        else if (e < W_W1_OFF)   { src = proj_w; off = e - W_PROJ_OFF; }
        else if (e < W_W2_OFF)   { src = w1;     off = e - W_W1_OFF; }
        else                     { src = w2;     off = e - W_W2_OFF; }
        float4 a = src[off / 4];
        float4 b = src[off / 4 + 1];
        uint4 o;
        o.x = pack2(a.x, a.y); o.y = pack2(a.z, a.w);
        o.z = pack2(b.x, b.y); o.w = pack2(b.z, b.w);
        dst[i] = o;
    }
}

// ---------------- layernorm (fp16 output) --------------------------------------
__global__ void ln_kernel(const float* __restrict__ x, const float* __restrict__ g,
                          const float* __restrict__ b, __half* __restrict__ o) {
    __shared__ float xs[DIM];
    __shared__ float red[256];
    int t = blockIdx.x, tid = threadIdx.x;
    const float* xr = x + (size_t)t * DIM;
    float s = 0.f;
    for (int i = tid; i < DIM; i += 256) { float v = xr[i]; xs[i] = v; s += v; }
    red[tid] = s; __syncthreads();
    for (int st = 128; st > 0; st >>= 1) { if (tid < st) red[tid] += red[tid + st]; __syncthreads(); }
    float mu = red[0] * (1.f / DIM);
    __syncthreads();
    s = 0.f;
    for (int i = tid; i < DIM; i += 256) { float d = xs[i] - mu; s += d * d; }
    red[tid] = s; __syncthreads();
    for (int st = 128; st > 0; st >>= 1) { if (tid < st) red[tid] += red[tid + st]; __syncthreads(); }
    float inv = rsqrtf(red[0] * (1.f / DIM) + 1e-5f);
    __half* orow = o + (size_t)t * DIM;
    for (int i = tid; i < DIM; i += 256)
        orow[i] = __float2half_rn((xs[i] - mu) * inv * g[i] + b[i]);
}

// ---------------- fp16 tensor-core GEMM (ldmatrix): C = A @ B^T ----------------
// OUTMODE: 0 = float, 2 = half, 3 = scatter-atomic float (MoE combine)
template <bool GATHER, bool GELU, int OUTMODE>
__global__ void __launch_bounds__(256, 2)
gemm_hc(const __half* __restrict__ A, const __half* __restrict__ Bw,
        const float* __restrict__ bias, const float* __restrict__ resid,
        void* __restrict__ Cout, int M, int N, int K,
        const int* __restrict__ rows, const int* __restrict__ cnts,
        const float* __restrict__ pw,
        size_t sA, size_t sB, size_t sC) {
    extern __shared__ __half smh[];
    __half* SA = smh;
    __half* SB = smh + (size_t)NSTAGE * 128 * HKPAD;

    int z = blockIdx.z;
    A += (size_t)z * sA; Bw += (size_t)z * sB;
    if (bias) bias += (size_t)z * N;
    if (rows) rows += (size_t)z * TT;
    if (pw)   pw += (size_t)z * TT;
    int Mz = cnts ? cnts[z] : M;
    if (Mz > M) Mz = M;
    int m0 = blockIdx.y * 128;
    if (m0 >= Mz) return;
    int n0 = blockIdx.x * 128;

    int tid = threadIdx.x;
    int r0 = tid >> 2, kq = tid & 3;

    const __half *ga0, *ga1;
    int za0 = 16, za1 = 16;
    if (GATHER) {
        int i0 = m0 + r0, i1 = i0 + 64;
        int g0 = 0, g1 = 0;
        if (i0 < Mz) g0 = rows[i0]; else za0 = 0;
        if (i1 < Mz) g1 = rows[i1]; else za1 = 0;
        ga0 = A + (size_t)g0 * K + kq * 8;
        ga1 = A + (size_t)g1 * K + kq * 8;
    } else {
        ga0 = A + (size_t)(m0 + r0) * K + kq * 8;
        ga1 = ga0 + (size_t)64 * K;
    }
    const __half* gb0 = Bw + (size_t)(n0 + r0) * K + kq * 8;
    const __half* gb1 = gb0 + (size_t)64 * K;

    uint32_t sa_smem = (uint32_t)__cvta_generic_to_shared(SA);
    uint32_t sb_smem = (uint32_t)__cvta_generic_to_shared(SB);
    uint32_t sa_base = sa_smem + (r0 * HKPAD + kq * 8) * 2;
    uint32_t sb_base = sb_smem + (r0 * HKPAD + kq * 8) * 2;
    const uint32_t BUFB = 128 * HKPAD * 2;
    const uint32_t HALF = 64 * HKPAD * 2;

    int NIT = K >> 5;

    auto load_tile = [&](int it) {
        uint32_t off = (uint32_t)(it % NSTAGE) * BUFB;
        cp16(sa_base + off,        ga0 + it * 32, za0);
        cp16(sa_base + off + HALF, ga1 + it * 32, za1);
        cp16(sb_base + off,        gb0 + it * 32, 16);
        cp16(sb_base + off + HALF, gb1 + it * 32, 16);
        asm volatile("cp.async.commit_group;" ::: "memory");
    };

    int warp = tid >> 5, lane = tid & 31;
    int gid = lane >> 2, tg = lane & 3;
    int wm = (warp >> 1) * 32, wn = (warp & 1) * 64;

    int a_r = lane & 15;
    int a_k = (lane & 16) ? 8 : 0;
    int b_r = (lane & 7) + ((lane & 16) ? 8 : 0);
    int b_k = (lane & 8) ? 8 : 0;

    float acc[2][8][4];
#pragma unroll
    for (int i = 0; i < 2; i++)
#pragma unroll
        for (int j = 0; j < 8; j++)
#pragma unroll
            for (int k = 0; k < 4; k++) acc[i][j][k] = 0.f;

    load_tile(0);
    if (NIT > 1) load_tile(1);

    for (int it = 0; it < NIT; ++it) {
        if (it + 1 < NIT) asm volatile("cp.async.wait_group 1;" ::: "memory");
        else              asm volatile("cp.async.wait_group 0;" ::: "memory");
        __syncthreads();
        if (it + 2 < NIT) load_tile(it + 2);

        uint32_t st = (uint32_t)(it % NSTAGE) * BUFB;
        uint32_t sa_st = sa_smem + st;
        uint32_t sb_st = sb_smem + st;

#pragma unroll
        for (int ks = 0; ks < 2; ks++) {
            uint32_t af[2][4], bf[8][2];
#pragma unroll
            for (int mi = 0; mi < 2; mi++)
                ldsm4(af[mi], sa_st + ((wm + mi * 16 + a_r) * HKPAD + ks * 16 + a_k) * 2);
#pragma unroll
            for (int np = 0; np < 4; np++) {
                uint32_t bq[4];
                ldsm4(bq, sb_st + ((wn + np * 16 + b_r) * HKPAD + ks * 16 + b_k) * 2);
                bf[2 * np][0] = bq[0]; bf[2 * np][1] = bq[1];
                bf[2 * np + 1][0] = bq[2]; bf[2 * np + 1][1] = bq[3];
            }
#pragma unroll
            for (int mi = 0; mi < 2; mi++)
#pragma unroll
                for (int ni = 0; ni < 8; ni++)
                    mma_f16(acc[mi][ni], af[mi], bf[ni]);
        }
    }

#pragma unroll
    for (int mi = 0; mi < 2; mi++) {
#pragma unroll
        for (int hh = 0; hh < 2; hh++) {
            int rr = m0 + wm + mi * 16 + gid + hh * 8;
            if (rr >= Mz) continue;
            const float* rrow = resid ? resid + (size_t)rr * N : nullptr;
            int tok = 0; float wgt = 0.f;
            if (OUTMODE == 3) { tok = rows[rr]; wgt = pw[rr]; }
#pragma unroll
            for (int ni = 0; ni < 8; ni++) {
                int col = n0 + wn + ni * 8 + tg * 2;
                float v0 = acc[mi][ni][hh * 2 + 0];
                float v1 = acc[mi][ni][hh * 2 + 1];
                if (bias) { v0 += bias[col]; v1 += bias[col + 1]; }
                if (GELU) {
                    v0 = 0.5f * v0 * (1.f + erff(v0 * 0.70710678118654752f));
                    v1 = 0.5f * v1 * (1.f + erff(v1 * 0.70710678118654752f));
                }
                if (rrow) { v0 += rrow[col]; v1 += rrow[col + 1]; }
                if (OUTMODE == 2) {
                    __half2* crow = (__half2*)((__half*)Cout + (size_t)z * sC + (size_t)rr * N + col);
                    *crow = __floats2half2_rn(v0, v1);
                } else if (OUTMODE == 3) {
                    float* orow = (float*)Cout + (size_t)tok * N + col;
                    atomicAdd(orow, wgt * v0);
                    atomicAdd(orow + 1, wgt * v1);
                } else {
                    float* crow = (float*)Cout + (size_t)z * sC + (size_t)rr * N + col;
                    crow[0] = v0; crow[1] = v1;
                }
            }
        }
    }
}

// ---------------- fp16 flash attention (ldmatrix + cp.async pipeline) ----------
__global__ void __launch_bounds__(256, 2)
attn_h(const __half* __restrict__ qkv, __half* __restrict__ out) {
    extern __shared__ __half sma[];
    __half* SQ = sma;                          // [128][APITCH]
    __half* SK = SQ + 128 * APITCH;            // [2][64][APITCH]
    __half* SV = SK + 2 * 64 * APITCH;         // [2][64][APITCH]

    int bh = blockIdx.y;
    int b = bh / HEADS, h = bh % HEADS;
    int q0 = blockIdx.x * 128;
    int tid = threadIdx.x;
    int warp = tid >> 5, lane = tid & 31;
    int gid = lane >> 2, tg = lane & 3;
    int wm = warp * 16;

    uint32_t sq_smem = (uint32_t)__cvta_generic_to_shared(SQ);
    uint32_t sk_smem = (uint32_t)__cvta_generic_to_shared(SK);
    uint32_t sv_smem = (uint32_t)__cvta_generic_to_shared(SV);
    const uint32_t STAGE = 64 * APITCH * 2;

    int a_r = lane & 15;
    int a_k = (lane & 16) ? 8 : 0;
    int b_r = (lane & 7) + ((lane & 16) ? 8 : 0);
    int b_k = (lane & 8) ? 8 : 0;
    int v_r = (lane & 7) + ((lane & 8) ? 8 : 0);
    int v_c = (lane & 16) ? 8 : 0;

    int krow = tid >> 2, kq4 = tid & 3;
    const __half* kbase = qkv + (size_t)(b * NN + krow) * (3 * DIM) + DIM + h * HD + kq4 * 16;
    uint32_t kdst = sk_smem + (krow * APITCH + kq4 * 16) * 2;
    uint32_t vdst = sv_smem + (krow * APITCH + kq4 * 16) * 2;

    auto loadKV = [&](int kt) {
        uint32_t off = (uint32_t)(kt & 1) * STAGE;
        const __half* kp = kbase + (size_t)kt * 64 * 3 * DIM;
        const __half* vp = kp + DIM;
        cp16(kdst + off, kp, 16);
        cp16(kdst + off + 16, kp + 8, 16);
        cp16(vdst + off, vp, 16);
        cp16(vdst + off + 16, vp + 8, 16);
        asm volatile("cp.async.commit_group;" ::: "memory");
    };

    // stage Q (x 0.125, exact in fp16)
    {
        int row = tid >> 1, cb = (tid & 1) * 32;
        const __half* qp = qkv + (size_t)(b * NN + q0 + row) * (3 * DIM) + h * HD + cb;
        __half* dst = SQ + row * APITCH + cb;
        const __half2 sc = __floats2half2_rn(0.125f, 0.125f);
#pragma unroll
        for (int j = 0; j < 4; j++) {
            __half2 v0 = *(const __half2*)(qp + j * 8 + 0);
            __half2 v1 = *(const __half2*)(qp + j * 8 + 2);
            __half2 v2 = *(const __half2*)(qp + j * 8 + 4);
            __half2 v3 = *(const __half2*)(qp + j * 8 + 6);
            *(__half2*)(dst + j * 8 + 0) = __hmul2(v0, sc);
            *(__half2*)(dst + j * 8 + 2) = __hmul2(v1, sc);
            *(__half2*)(dst + j * 8 + 4) = __hmul2(v2, sc);
            *(__half2*)(dst + j * 8 + 6) = __hmul2(v3, sc);
        }
    }
    loadKV(0);
    __syncthreads();

    uint32_t qf[4][4];
#pragma unroll
    for (int s = 0; s < 4; s++)
        ldsm4(qf[s], sq_smem + ((wm + a_r) * APITCH + s * 16 + a_k) * 2);

    float of[8][4];
#pragma unroll
    for (int i = 0; i < 8; i++)
#pragma unroll
        for (int j = 0; j < 4; j++) of[i][j] = 0.f;
    float m0r = -1e30f, m1r = -1e30f, l0r = 0.f, l1r = 0.f;

    const int NT = NN / 64;
    for (int kt = 0; kt < NT; kt++) {
        if (kt + 1 < NT) loadKV(kt + 1);
        if (kt + 1 < NT) asm volatile("cp.async.wait_group 1;" ::: "memory");
        else             asm volatile("cp.async.wait_group 0;" ::: "memory");
        __syncthreads();

        uint32_t sk_st = sk_smem + (uint32_t)(kt & 1) * STAGE;
        uint32_t sv_st = sv_smem + (uint32_t)(kt & 1) * STAGE;

        float sf[8][4];
#pragma unroll
        for (int i = 0; i < 8; i++)
#pragma unroll
            for (int j = 0; j < 4; j++) sf[i][j] = 0.f;
#pragma unroll
        for (int s = 0; s < 4; s++) {
            uint32_t bf[8][2];
#pragma unroll
            for (int np = 0; np < 4; np++) {
                uint32_t bq[4];
                ldsm4(bq, sk_st + ((np * 16 + b_r) * APITCH + s * 16 + b_k) * 2);
                bf[2 * np][0] = bq[0]; bf[2 * np][1] = bq[1];
                bf[2 * np + 1][0] = bq[2]; bf[2 * np + 1][1] = bq[3];
            }
#pragma unroll
            for (int ni = 0; ni < 8; ni++)
                mma_f16(sf[ni], qf[s], bf[ni]);
        }

        float tm0 = -1e30f, tm1 = -1e30f;
#pragma unroll
        for (int ni = 0; ni < 8; ni++) {
            tm0 = fmaxf(tm0, fmaxf(sf[ni][0], sf[ni][1]));
            tm1 = fmaxf(tm1, fmaxf(sf[ni][2], sf[ni][3]));
        }
        tm0 = fmaxf(tm0, __shfl_xor_sync(0xffffffffu, tm0, 1));
        tm0 = fmaxf(tm0, __shfl_xor_sync(0xffffffffu, tm0, 2));
        tm1 = fmaxf(tm1, __shfl_xor_sync(0xffffffffu, tm1, 1));
        tm1 = fmaxf(tm1, __shfl_xor_sync(0xffffffffu, tm1, 2));
        float mn0 = fmaxf(m0r, tm0), mn1 = fmaxf(m1r, tm1);
        float c0 = __expf(m0r - mn0), c1 = __expf(m1r - mn1);
        m0r = mn0; m1r = mn1;
        float rs0 = 0.f, rs1 = 0.f;
#pragma unroll
        for (int ni = 0; ni < 8; ni++) {
            sf[ni][0] = __expf(sf[ni][0] - mn0);
            sf[ni][1] = __expf(sf[ni][1] - mn0);
            sf[ni][2] = __expf(sf[ni][2] - mn1);
            sf[ni][3] = __expf(sf[ni][3] - mn1);
            rs0 += sf[ni][0] + sf[ni][1];
            rs1 += sf[ni][2] + sf[ni][3];
        }
        rs0 += __shfl_xor_sync(0xffffffffu, rs0, 1);
        rs0 += __shfl_xor_sync(0xffffffffu, rs0, 2);
        rs1 += __shfl_xor_sync(0xffffffffu, rs1, 1);
        rs1 += __shfl_xor_sync(0xffffffffu, rs1, 2);
        l0r = l0r * c0 + rs0;
        l1r = l1r * c1 + rs1;
#pragma unroll
        for (int ni = 0; ni < 8; ni++) {
            of[ni][0] *= c0; of[ni][1] *= c0;
            of[ni][2] *= c1; of[ni][3] *= c1;
        }

#pragma unroll
        for (int s = 0; s < 4; s++) {
            uint32_t pf[4];
            pf[0] = pack2(sf[2 * s][0], sf[2 * s][1]);
            pf[1] = pack2(sf[2 * s][2], sf[2 * s][3]);
            pf[2] = pack2(sf[2 * s + 1][0], sf[2 * s + 1][1]);
            pf[3] = pack2(sf[2 * s + 1][2], sf[2 * s + 1][3]);
            uint32_t bf[8][2];
#pragma unroll
            for (int np = 0; np < 4; np++) {
                uint32_t bq[4];
                ldsm4t(bq, sv_st + ((s * 16 + v_r) * APITCH + np * 16 + v_c) * 2);
                bf[2 * np][0] = bq[0]; bf[2 * np][1] = bq[1];
                bf[2 * np + 1][0] = bq[2]; bf[2 * np + 1][1] = bq[3];
            }
#pragma unroll
            for (int ni = 0; ni < 8; ni++)
                mma_f16(of[ni], pf, bf[ni]);
        }
        __syncthreads();
    }

    float i0 = 1.f / l0r, i1 = 1.f / l1r;
    __half* o0 = out + (size_t)(b * NN + q0 + wm + gid) * DIM + h * HD;
    __half* o1 = out + (size_t)(b * NN + q0 + wm + gid + 8) * DIM + h * HD;
#pragma unroll
    for (int ni = 0; ni < 8; ni++) {
        int col = ni * 8 + 2 * tg;
        *(__half2*)(o0 + col) = __floats2half2_rn(of[ni][0] * i0, of[ni][1] * i0);
        *(__half2*)(o1 + col) = __floats2half2_rn(of[ni][2] * i1, of[ni][3] * i1);
    }
}

// ------ fused LN2 + gate + fp16 h + out-init (out = x1) ------------------------
__global__ void gate_ln_kernel(const float* __restrict__ x1, const float* __restrict__ g,
                               const float* __restrict__ bparm, const float* __restrict__ gw,
                               const float* __restrict__ gb, int* __restrict__ cnt,
                               int* __restrict__ ptok, float* __restrict__ pw,
                               __half* __restrict__ hout, float* __restrict__ outinit) {
    __shared__ float xs[DIM];
    __shared__ float red[256];
    __shared__ float lg[NE];
    int t = blockIdx.x, tid = threadIdx.x;
    const float* xr = x1 + (size_t)t * DIM;
    float* orow = outinit + (size_t)t * DIM;
    float s = 0.f;
    for (int i = tid; i < DIM; i += 256) {
        float v = xr[i];
        xs[i] = v; orow[i] = v;
        s += v;
    }
    red[tid] = s; __syncthreads();
    for (int st = 128; st > 0; st >>= 1) { if (tid < st) red[tid] += red[tid + st]; __syncthreads(); }
    float mu = red[0] * (1.f / DIM);
    __syncthreads();
    s = 0.f;
    for (int i = tid; i < DIM; i += 256) { float d = xs[i] - mu; s += d * d; }
    red[tid] = s; __syncthreads();
    for (int st = 128; st > 0; st >>= 1) { if (tid < st) red[tid] += red[tid + st]; __syncthreads(); }
    float inv = rsqrtf(red[0] * (1.f / DIM) + 1e-5f);
    __syncthreads();

    int w = tid >> 5, lane = tid & 31;
    float acc = 0.f;
    const float* gr = gw + (size_t)w * DIM;
    __half* hrow = hout + (size_t)t * DIM;
    for (int k = lane; k < DIM; k += 32) {
        float hv = (xs[k] - mu) * inv * g[k] + bparm[k];
        acc += hv * gr[k];
        if (w == 0) hrow[k] = __float2half_rn(hv);
    }
#pragma unroll
    for (int off = 16; off > 0; off >>= 1) acc += __shfl_down_sync(0xffffffffu, acc, off);
    if (lane == 0) lg[w] = acc + gb[w];
    __syncthreads();
    if (tid == 0) {
        int b0 = 0; float v0 = lg[0];
        for (int e = 1; e < NE; e++) if (lg[e] > v0) { v0 = lg[e]; b0 = e; }
        int b1 = -1; float v1 = -1e30f;
        for (int e = 0; e < NE; e++) {
            if (e == b0) continue;
            if (lg[e] > v1) { v1 = lg[e]; b1 = e; }
        }
        float e1 = __expf(v1 - v0);
        float s0 = 1.f / (1.f + e1);
        float s1 = 1.f - s0;
        int p0 = atomicAdd(&cnt[b0], 1);
        int p1 = atomicAdd(&cnt[b1], 1);
        ptok[b0 * TT + p0] = t; pw[b0 * TT + p0] = s0;
        ptok[b1 * TT + p1] = t; pw[b1 * TT + p1] = s1;
    }
}

// ---------------- host launcher -------------------------------------------------
extern "C" void kernel_launch(void* const* d_in, const int* in_sizes, int n_in,
                              void* d_out, int out_size) {
    const float* x      = (const float*)d_in[0];
    const float* ln1_g  = (const float*)d_in[1];
    const float* ln1_b  = (const float*)d_in[2];
    const float* qkv_w  = (const float*)d_in[3];
    const float* proj_w = (const float*)d_in[4];
    const float* proj_b = (const float*)d_in[5];
    const float* ln2_g  = (const float*)d_in[6];
    const float* ln2_b  = (const float*)d_in[7];
    const float* gate_w = (const float*)d_in[8];
    const float* gate_b = (const float*)d_in[9];
    const float* w1     = (const float*)d_in[10];
    const float* b1     = (const float*)d_in[11];
    const float* w2     = (const float*)d_in[12];
    const float* b2     = (const float*)d_in[13];
    float* out = (float*)d_out;

    __half *h, *qkvb, *attn, *h1, *wh;
    float *x1, *pw;
    int *cnt, *ptok;
    cudaGetSymbolAddress((void**)&h, g_h);
    cudaGetSymbolAddress((void**)&qkvb, g_qkv);
    cudaGetSymbolAddress((void**)&attn, g_attn);
    cudaGetSymbolAddress((void**)&x1, g_x1);
    cudaGetSymbolAddress((void**)&h1, g_h1);
    cudaGetSymbolAddress((void**)&wh, g_wh);
    cudaGetSymbolAddress((void**)&cnt, g_cnt);
    cudaGetSymbolAddress((void**)&ptok, g_ptok);
    cudaGetSymbolAddress((void**)&pw, g_pw);

    __half* qkv_wh = wh + W_QKV_OFF;
    __half* proj_wh = wh + W_PROJ_OFF;
    __half* w1h = wh + W_W1_OFF;
    __half* w2h = wh + W_W2_OFF;

    const int GEMM_SMEM = NSTAGE * 128 * HKPAD * 2 * 2;           // 61440
    const int ATTN_SMEM = (128 + 4 * 64) * APITCH * 2;            // 55296
    cudaFuncSetAttribute(gemm_hc<false, false, 2>, cudaFuncAttributeMaxDynamicSharedMemorySize, GEMM_SMEM);
    cudaFuncSetAttribute(gemm_hc<false, false, 0>, cudaFuncAttributeMaxDynamicSharedMemorySize, GEMM_SMEM);
    cudaFuncSetAttribute(gemm_hc<true, true, 2>,   cudaFuncAttributeMaxDynamicSharedMemorySize, GEMM_SMEM);
    cudaFuncSetAttribute(gemm_hc<false, false, 3>, cudaFuncAttributeMaxDynamicSharedMemorySize, GEMM_SMEM);
    cudaFuncSetAttribute(attn_h, cudaFuncAttributeMaxDynamicSharedMemorySize, ATTN_SMEM);

    // 0. zero counters + single fused fp16 weight conversion
    zero_cnt_kernel<<<1, 32>>>(cnt);
    tohalf_all<<<4096, 256>>>((const float4*)qkv_w, (const float4*)proj_w,
                              (const float4*)w1, (const float4*)w2, (uint4*)wh);

    // 1. LN1 -> h (fp16)
    ln_kernel<<<TT, 256>>>(x, ln1_g, ln1_b, h);

    // 2. qkv = h @ qkv_w^T  (fp16 out)
    gemm_hc<false, false, 2><<<dim3(18, 32, 1), 256, GEMM_SMEM>>>(
        h, qkv_wh, nullptr, nullptr, qkvb, TT, 3 * DIM, DIM, nullptr, nullptr, nullptr, 0, 0, 0);

    // 3. attention
    attn_h<<<dim3(NN / 128, BB * HEADS), 256, ATTN_SMEM>>>(qkvb, attn);

    // 4. x1 = x + attn @ proj_w^T + proj_b  (fp32 out)  [6th launch -> ncu capture]
    gemm_hc<false, false, 0><<<dim3(6, 32, 1), 256, GEMM_SMEM>>>(
        attn, proj_wh, proj_b, x, x1, TT, DIM, DIM, nullptr, nullptr, nullptr, 0, 0, 0);

    // 5. fused LN2 + gate (+ fp16 h, + out = x1 init)
    gate_ln_kernel<<<TT, 256>>>(x1, ln2_g, ln2_b, gate_w, gate_b, cnt, ptok, pw, h, out);

    // 6. MoE up-proj + GELU (gathered, fp16 out)
    gemm_hc<true, true, 2><<<dim3(HID / 128, TT / 128, NE), 256, GEMM_SMEM>>>(
        h, w1h, b1, nullptr, h1, TT, HID, DIM, ptok, cnt, nullptr,
        0, (size_t)HID * DIM, (size_t)TT * HID);

    // 7. MoE down-proj, fused combine (scatter-atomic into out)
    gemm_hc<false, false, 3><<<dim3(6, 32, NE), 256, GEMM_SMEM>>>(
        h1, w2h, b2, nullptr, out, TT, DIM, HID, ptok, cnt, pw,
        (size_t)TT * HID, (size_t)DIM * HID, 0);
}